// round 10
// baseline (speedup 1.0000x reference)
#include <cuda_runtime.h>
#include <cuda_bf16.h>
#include <math.h>
#include <stdint.h>

#define NB 16
#define TT 12
#define NN 2048
#define HD 64
#define HR 12

// ---------------- scratch ----------------
__device__ __nv_bfloat16 g_Shi[(size_t)NN * NN];
__device__ __nv_bfloat16 g_Slo[(size_t)NN * NN];
__device__ __nv_bfloat16 g_Bhi[(size_t)NN * NN];
__device__ __nv_bfloat16 g_Blo[(size_t)NN * NN];
__device__ __nv_bfloat16 g_B0hi[(size_t)1024 * NN];
__device__ __nv_bfloat16 g_B0lo[(size_t)1024 * NN];
__device__ __nv_bfloat16 g_B1hi[(size_t)1024 * NN];
__device__ __nv_bfloat16 g_B1lo[(size_t)1024 * NN];
__device__ __nv_bfloat16 g_Wg0t_hi[(size_t)NN * 128 * 144];
__device__ __nv_bfloat16 g_Wg0t_lo[(size_t)NN * 128 * 144];
__device__ __nv_bfloat16 g_Wu0t_hi[(size_t)NN * 64 * 144];
__device__ __nv_bfloat16 g_Wu0t_lo[(size_t)NN * 64 * 144];
__device__ __nv_bfloat16 g_Wg1t_hi[(size_t)NN * 128 * 256];
__device__ __nv_bfloat16 g_Wg1t_lo[(size_t)NN * 128 * 256];
__device__ __nv_bfloat16 g_Wu1t_hi[(size_t)NN * 64 * 256];
__device__ __nv_bfloat16 g_Wu1t_lo[(size_t)NN * 64 * 256];
__device__ float g_Tsrc[768000];
__device__ float g_bg0[NN * 128];
__device__ float g_bu0[NN * 64];
__device__ float g_bg1[NN * 128];
__device__ float g_bu1[NN * 64];
__device__ float g_state0a[NN * NB * HD];
__device__ float g_state0b[NN * NB * HD];
__device__ float g_state1 [NN * NB * HD];
__device__ float g_SY [(size_t)NN * 2048];
__device__ float g_SXall[(size_t)NN * 192];
__device__ float g_SZS0[NN * NB * HD];
__device__ float g_SZS1[NN * NB * HD];
__device__ float g_ZS0[NN * NB * HD];
__device__ float g_ZS1[NN * NB * HD];
__device__ float g_r0 [NN * NB * HD];
__device__ float g_r1 [NN * NB * HD];

__device__ __forceinline__ float* s0RD(int t) { return (t & 1) ? g_state0b : g_state0a; }
__device__ __forceinline__ float* s0WR(int t) { return (t & 1) ? g_state0a : g_state0b; }

// ================= helpers =================
__device__ __forceinline__ uint32_t smem_u32(const void* p) {
    return (uint32_t)__cvta_generic_to_shared(p);
}
__device__ __forceinline__ void ldsm4(uint32_t* r, uint32_t a) {
    asm volatile("ldmatrix.sync.aligned.m8n8.x4.shared.b16 {%0,%1,%2,%3}, [%4];"
                 : "=r"(r[0]), "=r"(r[1]), "=r"(r[2]), "=r"(r[3]) : "r"(a));
}
__device__ __forceinline__ void ldsm2(uint32_t* r, uint32_t a) {
    asm volatile("ldmatrix.sync.aligned.m8n8.x2.shared.b16 {%0,%1}, [%2];"
                 : "=r"(r[0]), "=r"(r[1]) : "r"(a));
}
__device__ __forceinline__ void mma16816(float* c, const uint32_t* a, uint32_t b0, uint32_t b1) {
    asm volatile("mma.sync.aligned.m16n8k16.row.col.f32.bf16.bf16.f32 "
                 "{%0,%1,%2,%3}, {%4,%5,%6,%7}, {%8,%9}, {%0,%1,%2,%3};"
                 : "+f"(c[0]), "+f"(c[1]), "+f"(c[2]), "+f"(c[3])
                 : "r"(a[0]), "r"(a[1]), "r"(a[2]), "r"(a[3]), "r"(b0), "r"(b1));
}
__device__ __forceinline__ uint32_t swz16(int chunk, int row) {
    return (uint32_t)(((chunk & ~7) | ((chunk ^ row) & 7)) << 4);
}

// ---------------- S = softmax(relu(E E^T)) -> bf16 hi/lo ----------------
__global__ __launch_bounds__(256) void build_S(const float* __restrict__ E) {
    __shared__ float row[2048];
    __shared__ float red[8];
    int n = blockIdx.x, tid = threadIdx.x;
    float en[10];
#pragma unroll
    for (int d = 0; d < 10; d++) en[d] = E[n * 10 + d];
    float lmax = 0.f;
    for (int m = tid; m < 2048; m += 256) {
        float dot = 0.f;
#pragma unroll
        for (int d = 0; d < 10; d++) dot = fmaf(en[d], E[m * 10 + d], dot);
        dot = fmaxf(dot, 0.f);
        row[m] = dot;
        lmax = fmaxf(lmax, dot);
    }
#pragma unroll
    for (int o = 16; o; o >>= 1) lmax = fmaxf(lmax, __shfl_xor_sync(0xffffffffu, lmax, o));
    if ((tid & 31) == 0) red[tid >> 5] = lmax;
    __syncthreads();
    float mx = fmaxf(fmaxf(fmaxf(red[0], red[1]), fmaxf(red[2], red[3])),
                     fmaxf(fmaxf(red[4], red[5]), fmaxf(red[6], red[7])));
    __syncthreads();
    float lsum = 0.f;
    for (int m = tid; m < 2048; m += 256) {
        float e = expf(row[m] - mx);
        row[m] = e;
        lsum += e;
    }
#pragma unroll
    for (int o = 16; o; o >>= 1) lsum += __shfl_xor_sync(0xffffffffu, lsum, o);
    if ((tid & 31) == 0) red[tid >> 5] = lsum;
    __syncthreads();
    float inv = 1.f / (red[0] + red[1] + red[2] + red[3] + red[4] + red[5] + red[6] + red[7]);
    for (int m = tid; m < 2048; m += 256) {
        float v = row[m] * inv;
        __nv_bfloat16 h = __float2bfloat16(v);
        g_Shi[(size_t)n * 2048 + m] = h;
        g_Slo[(size_t)n * 2048 + m] = __float2bfloat16(v - __bfloat162float(h));
    }
}

// ---------------- weight source transpose ----------------
__global__ void transpose_src(const float* __restrict__ Wg0, const float* __restrict__ Wu0,
                              const float* __restrict__ Wg1, const float* __restrict__ Wu1) {
    int idx = blockIdx.x * 256 + threadIdx.x;
    if (idx >= 768000) return;
    const float* W; int off, OUT, K2, K2P;
    if (idx < 184320)      { W = Wg0; off = 0;      OUT = 128; K2 = 130; K2P = 144; }
    else if (idx < 276480) { W = Wu0; off = 184320; OUT = 64;  K2 = 130; K2P = 144; }
    else if (idx < 604160) { W = Wg1; off = 276480; OUT = 128; K2 = 256; K2P = 256; }
    else                   { W = Wu1; off = 604160; OUT = 64;  K2 = 256; K2P = 256; }
    int rem = idx - off;
    int d = rem / (OUT * K2P);
    int r2 = rem % (OUT * K2P);
    int o = r2 / K2P, kp = r2 % K2P;
    g_Tsrc[idx] = (kp < K2) ? W[(size_t)d * K2 * OUT + (size_t)kp * OUT + o] : 0.f;
}

// ---------------- bf16 hi/lo weight expansion ----------------
__global__ __launch_bounds__(256) void expand_w(const float* __restrict__ E) {
    __shared__ float Es[32][10];
    __shared__ float Ws[10][256];
    int bid = blockIdx.x, tid = threadIdx.x;
    int o, nc, OUT, K2P; size_t toff; __nv_bfloat16 *Dhi, *Dlo;
    if (bid < 8192)       { int r = bid;         o = r >> 6; nc = r & 63; OUT = 128; K2P = 144; toff = 0;      Dhi = g_Wg0t_hi; Dlo = g_Wg0t_lo; }
    else if (bid < 12288) { int r = bid - 8192;  o = r >> 6; nc = r & 63; OUT = 64;  K2P = 144; toff = 184320; Dhi = g_Wu0t_hi; Dlo = g_Wu0t_lo; }
    else if (bid < 20480) { int r = bid - 12288; o = r >> 6; nc = r & 63; OUT = 128; K2P = 256; toff = 276480; Dhi = g_Wg1t_hi; Dlo = g_Wg1t_lo; }
    else                  { int r = bid - 20480; o = r >> 6; nc = r & 63; OUT = 64;  K2P = 256; toff = 604160; Dhi = g_Wu1t_hi; Dlo = g_Wu1t_lo; }
    for (int s = tid; s < 320; s += 256)
        Es[s / 10][s % 10] = E[(nc * 32 + s / 10) * 10 + s % 10];
    for (int d = 0; d < 10; d++)
        if (tid < K2P) Ws[d][tid] = g_Tsrc[toff + ((size_t)d * OUT + o) * K2P + tid];
    __syncthreads();
    if (tid >= K2P) return;
#pragma unroll 1
    for (int n = 0; n < 32; n++) {
        float a = 0.f;
#pragma unroll
        for (int d = 0; d < 10; d++) a = fmaf(Es[n][d], Ws[d][tid], a);
        __nv_bfloat16 h = __float2bfloat16(a);
        size_t base = ((size_t)(nc * 32 + n) * OUT + o) * K2P + tid;
        Dhi[base] = h;
        Dlo[base] = __float2bfloat16(a - __bfloat162float(h));
    }
}

// ---------------- bias expansion ----------------
__global__ void expand_bias(const float* __restrict__ E,
                            const float* __restrict__ bg0, const float* __restrict__ bu0,
                            const float* __restrict__ bg1, const float* __restrict__ bu1) {
    int n = blockIdx.x, tid = threadIdx.x;  // 384 threads
    const float* B; float* D; int M, j;
    if (tid < 128)      { B = bg0; D = g_bg0; M = 128; j = tid; }
    else if (tid < 192) { B = bu0; D = g_bu0; M = 64;  j = tid - 128; }
    else if (tid < 320) { B = bg1; D = g_bg1; M = 128; j = tid - 192; }
    else                { B = bu1; D = g_bu1; M = 64;  j = tid - 320; }
    float a = 0.f;
#pragma unroll
    for (int d = 0; d < 10; d++) a = fmaf(E[n * 10 + d], B[d * M + j], a);
    D[n * M + j] = a;
}

__global__ void zero_all() {
    int idx = blockIdx.x * 256 + threadIdx.x;
    if (idx < NN * 2048) g_SY[idx] = 0.f;
    if (idx < NN * NB * HD) {
        g_state0a[idx] = 0.f; g_state0b[idx] = 0.f; g_state1[idx] = 0.f;
    }
}

// ---------------- packers ----------------
__global__ void pack_x(const float* __restrict__ src) {
    int idx = blockIdx.x * 256 + threadIdx.x;
    if (idx >= 256 * 2048) return;
    int m = idx & 2047, j = idx >> 11;
    float v = 0.f;
    if (j < 192) v = src[(((j & 15) * TT) + (j >> 4)) * NN + m];
    __nv_bfloat16 h = __float2bfloat16(v);
    g_Bhi[(size_t)j * 2048 + m] = h;
    g_Blo[(size_t)j * 2048 + m] = __float2bfloat16(v - __bfloat162float(h));
}

__global__ __launch_bounds__(256) void pack_big(int t) {
    __shared__ float tile[32][33];
    const float* __restrict__ s0 = s0WR(t);
    int m0 = blockIdx.x * 32, j0 = blockIdx.y * 32;
    int tx = threadIdx.x, ty = threadIdx.y;
#pragma unroll
    for (int i = 0; i < 4; i++) {
        int m = m0 + ty + i * 8;
        int j = j0 + tx;
        float v = (j < 1024) ? s0[m * 1024 + j] : g_state1[m * 1024 + (j - 1024)];
        tile[ty + i * 8][tx] = v;
    }
    __syncthreads();
#pragma unroll
    for (int i = 0; i < 4; i++) {
        int j = j0 + ty + i * 8;
        int m = m0 + tx;
        float v = tile[tx][ty + i * 8];
        __nv_bfloat16 h = __float2bfloat16(v);
        g_Bhi[(size_t)j * 2048 + m] = h;
        g_Blo[(size_t)j * 2048 + m] = __float2bfloat16(v - __bfloat162float(h));
    }
}

__global__ __launch_bounds__(256) void pack_zs(int sA, int sB) {
    __shared__ float tile[32][33];
    int set = (blockIdx.z == 0) ? sA : sB;
    const float* __restrict__ Z = set ? g_ZS1 : g_ZS0;
    __nv_bfloat16* __restrict__ Dhi = set ? g_B1hi : g_B0hi;
    __nv_bfloat16* __restrict__ Dlo = set ? g_B1lo : g_B0lo;
    int m0 = blockIdx.x * 32, j0 = blockIdx.y * 32;
    int tx = threadIdx.x, ty = threadIdx.y;
#pragma unroll
    for (int i = 0; i < 4; i++) {
        int m = m0 + ty + i * 8;
        int j = j0 + tx;
        tile[ty + i * 8][tx] = Z[m * 1024 + j];
    }
    __syncthreads();
#pragma unroll
    for (int i = 0; i < 4; i++) {
        int j = j0 + ty + i * 8;
        int m = m0 + tx;
        float v = tile[tx][ty + i * 8];
        __nv_bfloat16 h = __float2bfloat16(v);
        Dhi[(size_t)j * 2048 + m] = h;
        Dlo[(size_t)j * 2048 + m] = __float2bfloat16(v - __bfloat162float(h));
    }
}

// ---------------- big GEMM core: 128x64 C tile, 2 CTAs/SM ----------------
#define CHUNK_B   128
#define A_TILE_B  16384            // 128 rows x 128B
#define B_TILE_B  8192             // 64 rows x 128B
#define STAGE_BYTES (2 * A_TILE_B + 2 * B_TILE_B)   // 48 KB
#define NCH 32

struct GemmCore {
    uint32_t sbase;
    int lane, wr, wc, row0, col0;
    const __nv_bfloat16 *Bhi, *Blo;

    __device__ __forceinline__ void load_chunk(int c, int tid) {
        int s = c & 1;
        uint32_t st = sbase + s * STAGE_BYTES;
#pragma unroll
        for (int op = 0; op < 2; op++) {  // A: Shi, Slo (128 rows)
            const __nv_bfloat16* gp0 = op ? g_Slo : g_Shi;
            const char* g = (const char*)gp0 + (size_t)row0 * 4096 + (size_t)c * CHUNK_B;
            uint32_t sm0 = st + op * A_TILE_B;
#pragma unroll
            for (int it = 0; it < 4; it++) {
                int seg = it * 256 + tid;
                int r = seg >> 3, c16 = seg & 7;
                uint32_t off = (uint32_t)(r * 128 + c16 * 16);
                uint32_t sw = off ^ ((off >> 3) & 0x70);
                asm volatile("cp.async.cg.shared.global [%0], [%1], 16;"
                             :: "r"(sm0 + sw), "l"(g + (size_t)r * 4096 + c16 * 16));
            }
        }
#pragma unroll
        for (int op = 0; op < 2; op++) {  // B: Bhi, Blo (64 rows)
            const __nv_bfloat16* gp0 = op ? Blo : Bhi;
            const char* g = (const char*)gp0 + (size_t)col0 * 4096 + (size_t)c * CHUNK_B;
            uint32_t sm0 = st + 2 * A_TILE_B + op * B_TILE_B;
#pragma unroll
            for (int it = 0; it < 2; it++) {
                int seg = it * 256 + tid;
                int r = seg >> 3, c16 = seg & 7;
                uint32_t off = (uint32_t)(r * 128 + c16 * 16);
                uint32_t sw = off ^ ((off >> 3) & 0x70);
                asm volatile("cp.async.cg.shared.global [%0], [%1], 16;"
                             :: "r"(sm0 + sw), "l"(g + (size_t)r * 4096 + c16 * 16));
            }
        }
        asm volatile("cp.async.commit_group;" ::: "memory");
    }

    __device__ __forceinline__ void run(float* __restrict__ Cg, int J, int tid) {
        float acc[2][4][4];
#pragma unroll
        for (int i = 0; i < 2; i++)
#pragma unroll
            for (int j = 0; j < 4; j++)
#pragma unroll
                for (int k = 0; k < 4; k++) acc[i][j][k] = 0.f;

        int l15 = lane & 15, khalf = lane >> 4;
        int rA0 = wr * 32 + l15;
        int rB0 = wc * 32 + l15;
        uint32_t xA = (uint32_t)((rA0 & 7) * 16);
        uint32_t xB = (uint32_t)((rB0 & 7) * 16);

        load_chunk(0, tid);
        load_chunk(1, tid);

        for (int c = 0; c < NCH; c++) {
            int s = c & 1;
            if (c + 1 < NCH) asm volatile("cp.async.wait_group 1;" ::: "memory");
            else             asm volatile("cp.async.wait_group 0;" ::: "memory");
            __syncthreads();

            uint32_t tAhi = sbase + s * STAGE_BYTES;
            uint32_t tAlo = tAhi + A_TILE_B;
            uint32_t tBhi = tAhi + 2 * A_TILE_B;
            uint32_t tBlo = tBhi + B_TILE_B;

#pragma unroll
            for (int kk = 0; kk < 4; kk++) {
                uint32_t kb = (uint32_t)(kk * 32 + khalf * 16);
                uint32_t ah0[4], ah1[4], al0[4], al1[4];
                ldsm4(ah0, tAhi + (uint32_t)(rA0 * 128)        + (kb ^ xA));
                ldsm4(ah1, tAhi + (uint32_t)((rA0 + 16) * 128) + (kb ^ xA));
                ldsm4(al0, tAlo + (uint32_t)(rA0 * 128)        + (kb ^ xA));
                ldsm4(al1, tAlo + (uint32_t)((rA0 + 16) * 128) + (kb ^ xA));
#pragma unroll
                for (int g = 0; g < 2; g++) {
                    int rB = rB0 + g * 16;
                    uint32_t bh[4], bl[4];
                    ldsm4(bh, tBhi + (uint32_t)(rB * 128) + (kb ^ xB));
                    ldsm4(bl, tBlo + (uint32_t)(rB * 128) + (kb ^ xB));
                    mma16816(acc[0][g * 2 + 0], ah0, bh[0], bh[2]);
                    mma16816(acc[0][g * 2 + 0], ah0, bl[0], bl[2]);
                    mma16816(acc[0][g * 2 + 0], al0, bh[0], bh[2]);
                    mma16816(acc[0][g * 2 + 1], ah0, bh[1], bh[3]);
                    mma16816(acc[0][g * 2 + 1], ah0, bl[1], bl[3]);
                    mma16816(acc[0][g * 2 + 1], al0, bh[1], bh[3]);
                    mma16816(acc[1][g * 2 + 0], ah1, bh[0], bh[2]);
                    mma16816(acc[1][g * 2 + 0], ah1, bl[0], bl[2]);
                    mma16816(acc[1][g * 2 + 0], al1, bh[0], bh[2]);
                    mma16816(acc[1][g * 2 + 1], ah1, bh[1], bh[3]);
                    mma16816(acc[1][g * 2 + 1], ah1, bl[1], bl[3]);
                    mma16816(acc[1][g * 2 + 1], al1, bh[1], bh[3]);
                }
            }
            __syncthreads();
            if (c + 2 < NCH) load_chunk(c + 2, tid);
        }

        int qr = lane >> 2, qc = lane & 3;
#pragma unroll
        for (int mt = 0; mt < 2; mt++) {
#pragma unroll
            for (int nt = 0; nt < 4; nt++) {
                int col = col0 + wc * 32 + nt * 8 + qc * 2;
                if (col < J) {
                    int row = row0 + wr * 32 + mt * 16 + qr;
                    *(float2*)&Cg[(size_t)row * J + col] =
                        make_float2(acc[mt][nt][0], acc[mt][nt][1]);
                    *(float2*)&Cg[(size_t)(row + 8) * J + col] =
                        make_float2(acc[mt][nt][2], acc[mt][nt][3]);
                }
            }
        }
    }
};

template <int WHICH>
__global__ void __launch_bounds__(256, 2) mma_gemm(int J) {
    extern __shared__ __align__(1024) char smem[];
    GemmCore gc;
    int tid = threadIdx.x;
    gc.sbase = smem_u32(smem);
    gc.lane = tid & 31;
    int wid = tid >> 5;
    gc.wr = wid & 3; gc.wc = wid >> 2;
    gc.row0 = blockIdx.y * 128;
    gc.col0 = blockIdx.x * 64;
    gc.Bhi = g_Bhi; gc.Blo = g_Blo;
    gc.run((WHICH == 0) ? g_SY : g_SXall, J, tid);
}

__global__ void __launch_bounds__(256, 2) mma_gemm_sm(int sA, int sB) {
    extern __shared__ __align__(1024) char smem[];
    int set = (blockIdx.z == 0) ? sA : sB;
    GemmCore gc;
    int tid = threadIdx.x;
    gc.sbase = smem_u32(smem);
    gc.lane = tid & 31;
    int wid = tid >> 5;
    gc.wr = wid & 3; gc.wc = wid >> 2;
    gc.row0 = blockIdx.y * 128;
    gc.col0 = blockIdx.x * 64;
    gc.Bhi = set ? g_B1hi : g_B0hi;
    gc.Blo = set ? g_B1lo : g_B0lo;
    gc.run(set ? g_SZS1 : g_SZS0, 1024, tid);
}

// ---------------- tensor-core gate/update heads: 32 outputs / block, 128 thr ----------------
// MODE: 0 gate-layer0, 1 gate-layer1, 2 update-layer0, 3 update-layer1
template <int K2P, int MODE>
__device__ __forceinline__ void head_body(const float* __restrict__ src, int tt,
                                          char* smem, int bx) {
    constexpr int STRB = (K2P == 256) ? 512 : 384;
    constexpr int KST  = K2P / 16;
    constexpr bool GATE = (MODE == 0 || MODE == 1);
    constexpr int OUTTOT = GATE ? 128 : 64;
    int node, q;
    if (GATE) { node = bx >> 2; q = bx & 3; } else { node = bx >> 1; q = bx & 1; }
    int tid = threadIdx.x, lane = tid & 31, w = tid >> 5;   // 4 warps

    uint32_t sWhi = smem_u32(smem);
    uint32_t sWlo = sWhi + 32u * STRB;
    uint32_t sXhi = sWhi + 64u * STRB;
    uint32_t sXlo = sXhi + 16u * STRB;

    const __nv_bfloat16 *gWhi, *gWlo;
    const float* bias;
    {
        size_t off = ((size_t)node * OUTTOT + q * 32) * K2P;
        if (MODE == 0)      { gWhi = g_Wg0t_hi + off; gWlo = g_Wg0t_lo + off; bias = g_bg0 + node * 128 + q * 32; }
        else if (MODE == 1) { gWhi = g_Wg1t_hi + off; gWlo = g_Wg1t_lo + off; bias = g_bg1 + node * 128 + q * 32; }
        else if (MODE == 2) { gWhi = g_Wu0t_hi + off; gWlo = g_Wu0t_lo + off; bias = g_bu0 + node * 64 + q * 32; }
        else                { gWhi = g_Wu1t_hi + off; gWlo = g_Wu1t_lo + off; bias = g_bu1 + node * 64 + q * 32; }
    }

    constexpr int NCHK = (K2P * 2) / 16;
    constexpr int WTOT = 32 * NCHK;
#pragma unroll
    for (int s = tid; s < WTOT; s += 128) {
        int r = s / NCHK, c = s % NCHK;
        uint32_t dst = (uint32_t)(r * STRB) + swz16(c, r);
        const char* srchi = (const char*)(gWhi + (size_t)r * K2P) + c * 16;
        const char* srclo = (const char*)(gWlo + (size_t)r * K2P) + c * 16;
        asm volatile("cp.async.cg.shared.global [%0], [%1], 16;" :: "r"(sWhi + dst), "l"(srchi));
        asm volatile("cp.async.cg.shared.global [%0], [%1], 16;" :: "r"(sWlo + dst), "l"(srclo));
    }
    asm volatile("cp.async.commit_group;" ::: "memory");

    const float* srd = (MODE == 0 || MODE == 2) ? s0RD(tt) : (const float*)0;
    const float* swr = (MODE == 1 || MODE == 3) ? s0WR(tt) : (const float*)0;

    // batched X gather: load phase, then convert/store
    if (K2P == 256) {
        float4 xv[8];
#pragma unroll
        for (int it = 0; it < 8; it++) {
            int v = it * 128 + tid;
            int b = v >> 6, i4 = (v & 63) << 2;
            int seg = i4 >> 6, off = i4 & 63;
            const float* p;
            if (MODE == 1) {
                if      (seg == 0) p = swr      + node * 1024 + b * 64 + off;
                else if (seg == 1) p = g_state1 + node * 1024 + b * 64 + off;
                else if (seg == 2) p = g_SY     + (size_t)node * 2048 + b * 64 + off;
                else               p = g_SY     + (size_t)node * 2048 + 1024 + b * 64 + off;
            } else {
                if      (seg == 0) p = swr      + node * 1024 + b * 64 + off;
                else if (seg == 1) p = g_ZS1    + node * 1024 + b * 64 + off;
                else if (seg == 2) p = g_SY     + (size_t)node * 2048 + b * 64 + off;
                else               p = g_SZS1   + node * 1024 + b * 64 + off;
            }
            xv[it] = *(const float4*)p;
        }
#pragma unroll
        for (int it = 0; it < 8; it++) {
            int v = it * 128 + tid;
            int b = v >> 6, i4 = (v & 63) << 2;
            float4 x = xv[it];
            __nv_bfloat16 h0 = __float2bfloat16(x.x), h1 = __float2bfloat16(x.y);
            __nv_bfloat16 h2 = __float2bfloat16(x.z), h3 = __float2bfloat16(x.w);
            uint32_t hi0 = ((uint32_t)*(unsigned short*)&h0) | ((uint32_t)*(unsigned short*)&h1 << 16);
            uint32_t hi1 = ((uint32_t)*(unsigned short*)&h2) | ((uint32_t)*(unsigned short*)&h3 << 16);
            __nv_bfloat16 l0 = __float2bfloat16(x.x - __bfloat162float(h0));
            __nv_bfloat16 l1 = __float2bfloat16(x.y - __bfloat162float(h1));
            __nv_bfloat16 l2 = __float2bfloat16(x.z - __bfloat162float(h2));
            __nv_bfloat16 l3 = __float2bfloat16(x.w - __bfloat162float(h3));
            uint32_t lo0 = ((uint32_t)*(unsigned short*)&l0) | ((uint32_t)*(unsigned short*)&l1 << 16);
            uint32_t lo1 = ((uint32_t)*(unsigned short*)&l2) | ((uint32_t)*(unsigned short*)&l3 << 16);
            uint32_t boff = (uint32_t)(b * STRB) + swz16(i4 >> 3, b) + (uint32_t)((i4 & 7) * 2);
            asm volatile("st.shared.v2.b32 [%0], {%1,%2};" :: "r"(sXhi + boff), "r"(hi0), "r"(hi1));
            asm volatile("st.shared.v2.b32 [%0], {%1,%2};" :: "r"(sXlo + boff), "r"(lo0), "r"(lo1));
        }
    } else {
        float vals[18];
#pragma unroll
        for (int it = 0; it < 18; it++) {
            int idx = it * 128 + tid;
            int b = idx / 144, i = idx % 144;
            float v = 0.f;
            if (MODE == 0) {
                if (i == 0)       v = src[(b * TT + tt) * NN + node];
                else if (i < 65)  v = srd[node * 1024 + b * 64 + (i - 1)];
                else if (i == 65) v = g_SXall[(size_t)node * 192 + tt * 16 + b];
                else if (i < 130) v = g_SY[(size_t)node * 2048 + b * 64 + (i - 66)];
            } else {
                if (i == 0)       v = src[(b * TT + tt) * NN + node];
                else if (i < 65)  v = g_ZS0[node * 1024 + b * 64 + (i - 1)];
                else if (i == 65) v = g_SXall[(size_t)node * 192 + tt * 16 + b];
                else if (i < 130) v = g_SZS0[node * 1024 + b * 64 + (i - 66)];
            }
            vals[it] = v;
        }
#pragma unroll
        for (int it = 0; it < 18; it++) {
            int idx = it * 128 + tid;
            int b = idx / 144, i = idx % 144;
            float v = vals[it];
            __nv_bfloat16 h = __float2bfloat16(v);
            __nv_bfloat16 l = __float2bfloat16(v - __bfloat162float(h));
            uint32_t boff = (uint32_t)(b * STRB) + swz16(i >> 3, b) + (uint32_t)((i & 7) * 2);
            asm volatile("st.shared.b16 [%0], %1;" :: "r"(sXhi + boff), "h"(*(unsigned short*)&h));
            asm volatile("st.shared.b16 [%0], %1;" :: "r"(sXlo + boff), "h"(*(unsigned short*)&l));
        }
    }
    asm volatile("cp.async.wait_group 0;" ::: "memory");
    __syncthreads();

    float acc[4] = {0.f, 0.f, 0.f, 0.f};
    int l15 = lane & 15;
    int rowA = l15;
    int oL = w * 8;                       // warp's 8 outputs within the 32
    int rB = oL + (l15 & 7);
#pragma unroll
    for (int ks = 0; ks < KST; ks++) {
        int cA = ks * 2 + (lane >> 4);
        uint32_t offA = (uint32_t)(rowA * STRB) + swz16(cA, rowA);
        uint32_t ahi[4], alo[4];
        ldsm4(ahi, sXhi + offA);
        ldsm4(alo, sXlo + offA);
        int cB = ks * 2 + ((l15 >> 3) & 1);
        uint32_t offB = (uint32_t)(rB * STRB) + swz16(cB, rB);
        uint32_t bhi[2], blo[2];
        ldsm2(bhi, sWhi + offB);
        ldsm2(blo, sWlo + offB);
        mma16816(acc, ahi, bhi[0], bhi[1]);
        mma16816(acc, alo, bhi[0], bhi[1]);
        mma16816(acc, ahi, blo[0], blo[1]);
    }

    int qr = lane >> 2;
    int o = oL + (lane & 3) * 2;          // local 0..31 (pair)
    int og = q * 32 + o;                   // global within OUTTOT
    float b0 = bias[o], b1 = bias[o + 1];

    if (GATE) {
        float* ZS = (MODE == 0) ? g_ZS0 : g_ZS1;
        float* R  = (MODE == 0) ? g_r0  : g_r1;
        const float* st = (MODE == 0) ? srd : g_state1;
        float s0 = 1.f / (1.f + expf(-(acc[0] + b0)));
        float s1 = 1.f / (1.f + expf(-(acc[1] + b1)));
        float s2 = 1.f / (1.f + expf(-(acc[2] + b0)));
        float s3 = 1.f / (1.f + expf(-(acc[3] + b1)));
        if (q < 2) {
            int base0 = node * 1024 + qr * 64 + og;
            int base1 = base0 + 512;
            ZS[base0]     = s0 * st[base0];
            ZS[base0 + 1] = s1 * st[base0 + 1];
            ZS[base1]     = s2 * st[base1];
            ZS[base1 + 1] = s3 * st[base1 + 1];
        } else {
            int base0 = node * 1024 + qr * 64 + (og - 64);
            int base1 = base0 + 512;
            R[base0] = s0; R[base0 + 1] = s1;
            R[base1] = s2; R[base1 + 1] = s3;
        }
    } else {
        const float* R   = (MODE == 2) ? g_r0 : g_r1;
        const float* stR = (MODE == 2) ? srd : g_state1;
        float* stW       = (MODE == 2) ? s0WR(tt) : g_state1;
        int base0 = node * 1024 + qr * 64 + og;
        int base1 = base0 + 512;
        float h0 = tanhf(acc[0] + b0);
        float h1 = tanhf(acc[1] + b1);
        float h2 = tanhf(acc[2] + b0);
        float h3 = tanhf(acc[3] + b1);
        float r0v = R[base0],     r1v = R[base0 + 1];
        float r2v = R[base1],     r3v = R[base1 + 1];
        stW[base0]     = r0v * stR[base0]     + (1.f - r0v) * h0;
        stW[base0 + 1] = r1v * stR[base0 + 1] + (1.f - r1v) * h1;
        stW[base1]     = r2v * stR[base1]     + (1.f - r2v) * h2;
        stW[base1 + 1] = r3v * stR[base1 + 1] + (1.f - r3v) * h3;
    }
}

__global__ __launch_bounds__(128) void fused_gate(const float* __restrict__ src, int t1, int t0) {
    extern __shared__ __align__(128) char smem[];
    int role;
    if (gridDim.y == 2) role = (blockIdx.y == 0) ? 1 : 0;
    else                role = (t1 >= 0) ? 1 : 0;
    if (role) head_body<256, 1>(src, t1, smem, blockIdx.x);
    else      head_body<144, 0>(src, t0, smem, blockIdx.x);
}

__global__ __launch_bounds__(128) void fused_update(const float* __restrict__ src, int t1, int t0) {
    extern __shared__ __align__(128) char smem[];
    int role;
    if (gridDim.y == 2) role = (blockIdx.y == 0) ? 1 : 0;
    else                role = (t1 >= 0) ? 1 : 0;
    if (role) head_body<256, 3>(src, t1, smem, blockIdx.x);
    else      head_body<144, 2>(src, t0, smem, blockIdx.x);
}

// ---------------- output head ----------------
__global__ void out_kernel(const float* __restrict__ cw, const float* __restrict__ cb,
                           float* __restrict__ out) {
    int idx = blockIdx.x * 256 + threadIdx.x;
    if (idx >= NB * HR * NN) return;
    int n = idx & 2047;
    int h = (idx >> 11) % HR;
    int b = idx / (HR * NN);
    float a = cb[h];
#pragma unroll
    for (int c = 0; c < 64; c++)
        a = fmaf(g_state1[n * 1024 + b * 64 + c], cw[h * 64 + c], a);
    out[idx] = a;
}

// ---------------- launcher ----------------
extern "C" void kernel_launch(void* const* d_in, const int* in_sizes, int n_in,
                              void* d_out, int out_size) {
    const float* src = (const float*)d_in[0];
    const float* E   = (const float*)d_in[1];
    const float* Wg0 = (const float*)d_in[2];
    const float* bg0 = (const float*)d_in[3];
    const float* Wu0 = (const float*)d_in[4];
    const float* bu0 = (const float*)d_in[5];
    const float* Wg1 = (const float*)d_in[6];
    const float* bg1 = (const float*)d_in[7];
    const float* Wu1 = (const float*)d_in[8];
    const float* bu1 = (const float*)d_in[9];
    const float* cw  = (const float*)d_in[10];
    const float* cb  = (const float*)d_in[11];
    float* out = (float*)d_out;

    const int GEMM_SMEM = 2 * STAGE_BYTES;   // 96 KB
    const int HEAD_SMEM = 96 * 512;          // 48 KB
    cudaFuncSetAttribute(mma_gemm<0>,  cudaFuncAttributeMaxDynamicSharedMemorySize, GEMM_SMEM);
    cudaFuncSetAttribute(mma_gemm<2>,  cudaFuncAttributeMaxDynamicSharedMemorySize, GEMM_SMEM);
    cudaFuncSetAttribute(mma_gemm_sm,  cudaFuncAttributeMaxDynamicSharedMemorySize, GEMM_SMEM);
    cudaFuncSetAttribute(fused_gate,   cudaFuncAttributeMaxDynamicSharedMemorySize, HEAD_SMEM);
    cudaFuncSetAttribute(fused_update, cudaFuncAttributeMaxDynamicSharedMemorySize, HEAD_SMEM);

    dim3 pk(32, 8);

    // launches 1..4: #4 is a small THROWAWAY fused_gate for ncu profiling.
    build_S<<<NN, 256>>>(E);                                           // 1
    zero_all<<<(NN * 2048 + 255) / 256, 256>>>();                      // 2
    pack_x<<<(256 * 2048 + 255) / 256, 256>>>(src);                    // 3
    fused_gate<<<dim3(2048, 2), 128, HEAD_SMEM>>>(src, 0, 1);          // 4 <- PROFILED (throwaway)

    mma_gemm<2><<<dim3(3, 16), 256, GEMM_SMEM>>>(192);                 // S@X all steps
    transpose_src<<<3000, 256>>>(Wg0, Wu0, Wg1, Wu1);
    expand_w<<<24576, 256>>>(E);
    expand_bias<<<NN, 384>>>(E, bg0, bu0, bg1, bu1);

    // prologue: layer0 @ t=0
    fused_gate  <<<dim3(8192, 1), 128, HEAD_SMEM>>>(src, -1, 0);
    pack_zs     <<<dim3(64, 32, 1), pk>>>(0, 0);
    mma_gemm_sm <<<dim3(16, 16, 1), 256, GEMM_SMEM>>>(0, 0);
    fused_update<<<dim3(4096, 1), 128, HEAD_SMEM>>>(src, -1, 0);
    pack_big    <<<dim3(64, 64), pk>>>(0);
    mma_gemm<0> <<<dim3(32, 16), 256, GEMM_SMEM>>>(2048);

    // steady state: layer1(t) || layer0(t+1)
    for (int t = 0; t + 1 < TT; t++) {
        fused_gate  <<<dim3(8192, 2), 128, HEAD_SMEM>>>(src, t, t + 1);
        pack_zs     <<<dim3(64, 32, 2), pk>>>(1, 0);
        mma_gemm_sm <<<dim3(16, 16, 2), 256, GEMM_SMEM>>>(1, 0);
        fused_update<<<dim3(4096, 2), 128, HEAD_SMEM>>>(src, t, t + 1);
        pack_big    <<<dim3(64, 64), pk>>>(t + 1);
        mma_gemm<0> <<<dim3(32, 16), 256, GEMM_SMEM>>>(2048);
    }

    // epilogue: layer1 @ t=TT-1
    fused_gate  <<<dim3(8192, 1), 128, HEAD_SMEM>>>(src, TT - 1, -1);
    pack_zs     <<<dim3(64, 32, 1), pk>>>(1, 1);
    mma_gemm_sm <<<dim3(16, 16, 1), 256, GEMM_SMEM>>>(1, 1);
    fused_update<<<dim3(4096, 1), 128, HEAD_SMEM>>>(src, TT - 1, -1);

    out_kernel<<<(NB * HR * NN + 255) / 256, 256>>>(cw, cb, out);
}

// round 11
// speedup vs baseline: 1.1036x; 1.1036x over previous
#include <cuda_runtime.h>
#include <cuda_bf16.h>
#include <math.h>
#include <stdint.h>

#define NB 16
#define TT 12
#define NN 2048
#define HD 64
#define HR 12

// ---------------- scratch ----------------
__device__ __nv_bfloat16 g_Shi[(size_t)NN * NN];
__device__ __nv_bfloat16 g_Slo[(size_t)NN * NN];
__device__ __nv_bfloat16 g_Bhi[(size_t)NN * NN];
__device__ __nv_bfloat16 g_Blo[(size_t)NN * NN];
__device__ __nv_bfloat16 g_B0hi[(size_t)1024 * NN];
__device__ __nv_bfloat16 g_B0lo[(size_t)1024 * NN];
__device__ __nv_bfloat16 g_B1hi[(size_t)1024 * NN];
__device__ __nv_bfloat16 g_B1lo[(size_t)1024 * NN];
// staging: per-node transposed weights [n][o][kp], bf16 hi/lo
__device__ __nv_bfloat16 g_Wg0t_hi[(size_t)NN * 128 * 144];
__device__ __nv_bfloat16 g_Wg0t_lo[(size_t)NN * 128 * 144];
__device__ __nv_bfloat16 g_Wu0t_hi[(size_t)NN * 64 * 144];
__device__ __nv_bfloat16 g_Wu0t_lo[(size_t)NN * 64 * 144];
__device__ __nv_bfloat16 g_Wg1t_hi[(size_t)NN * 128 * 256];
__device__ __nv_bfloat16 g_Wg1t_lo[(size_t)NN * 128 * 256];
__device__ __nv_bfloat16 g_Wu1t_hi[(size_t)NN * 64 * 256];
__device__ __nv_bfloat16 g_Wu1t_lo[(size_t)NN * 64 * 256];
// fragment-order weights: [n][og8][ks][lane][c], c = {bhi_j0, bhi_j1, blo_j0, blo_j1}
__device__ uint32_t g_WFg0[(size_t)NN * 16 * 9 * 128];
__device__ uint32_t g_WFu0[(size_t)NN * 8 * 9 * 128];
__device__ uint32_t g_WFg1[(size_t)NN * 16 * 16 * 128];
__device__ uint32_t g_WFu1[(size_t)NN * 8 * 16 * 128];
__device__ float g_Tsrc[768000];
__device__ float g_bg0[NN * 128];
__device__ float g_bu0[NN * 64];
__device__ float g_bg1[NN * 128];
__device__ float g_bu1[NN * 64];
__device__ float g_state0a[NN * NB * HD];
__device__ float g_state0b[NN * NB * HD];
__device__ float g_state1 [NN * NB * HD];
__device__ float g_SY [(size_t)NN * 2048];
__device__ float g_SXall[(size_t)NN * 192];
__device__ float g_SZS0[NN * NB * HD];
__device__ float g_SZS1[NN * NB * HD];
__device__ float g_ZS0[NN * NB * HD];
__device__ float g_ZS1[NN * NB * HD];
__device__ float g_r0 [NN * NB * HD];
__device__ float g_r1 [NN * NB * HD];

__device__ __forceinline__ float* s0RD(int t) { return (t & 1) ? g_state0b : g_state0a; }
__device__ __forceinline__ float* s0WR(int t) { return (t & 1) ? g_state0a : g_state0b; }

// ================= helpers =================
__device__ __forceinline__ uint32_t smem_u32(const void* p) {
    return (uint32_t)__cvta_generic_to_shared(p);
}
__device__ __forceinline__ void ldsm4(uint32_t* r, uint32_t a) {
    asm volatile("ldmatrix.sync.aligned.m8n8.x4.shared.b16 {%0,%1,%2,%3}, [%4];"
                 : "=r"(r[0]), "=r"(r[1]), "=r"(r[2]), "=r"(r[3]) : "r"(a));
}
__device__ __forceinline__ void mma16816(float* c, const uint32_t* a, uint32_t b0, uint32_t b1) {
    asm volatile("mma.sync.aligned.m16n8k16.row.col.f32.bf16.bf16.f32 "
                 "{%0,%1,%2,%3}, {%4,%5,%6,%7}, {%8,%9}, {%0,%1,%2,%3};"
                 : "+f"(c[0]), "+f"(c[1]), "+f"(c[2]), "+f"(c[3])
                 : "r"(a[0]), "r"(a[1]), "r"(a[2]), "r"(a[3]), "r"(b0), "r"(b1));
}
__device__ __forceinline__ uint32_t swz16(int chunk, int row) {
    return (uint32_t)(((chunk & ~7) | ((chunk ^ row) & 7)) << 4);
}

// ---------------- S = softmax(relu(E E^T)) -> bf16 hi/lo ----------------
__global__ __launch_bounds__(256) void build_S(const float* __restrict__ E) {
    __shared__ float row[2048];
    __shared__ float red[8];
    int n = blockIdx.x, tid = threadIdx.x;
    float en[10];
#pragma unroll
    for (int d = 0; d < 10; d++) en[d] = E[n * 10 + d];
    float lmax = 0.f;
    for (int m = tid; m < 2048; m += 256) {
        float dot = 0.f;
#pragma unroll
        for (int d = 0; d < 10; d++) dot = fmaf(en[d], E[m * 10 + d], dot);
        dot = fmaxf(dot, 0.f);
        row[m] = dot;
        lmax = fmaxf(lmax, dot);
    }
#pragma unroll
    for (int o = 16; o; o >>= 1) lmax = fmaxf(lmax, __shfl_xor_sync(0xffffffffu, lmax, o));
    if ((tid & 31) == 0) red[tid >> 5] = lmax;
    __syncthreads();
    float mx = fmaxf(fmaxf(fmaxf(red[0], red[1]), fmaxf(red[2], red[3])),
                     fmaxf(fmaxf(red[4], red[5]), fmaxf(red[6], red[7])));
    __syncthreads();
    float lsum = 0.f;
    for (int m = tid; m < 2048; m += 256) {
        float e = expf(row[m] - mx);
        row[m] = e;
        lsum += e;
    }
#pragma unroll
    for (int o = 16; o; o >>= 1) lsum += __shfl_xor_sync(0xffffffffu, lsum, o);
    if ((tid & 31) == 0) red[tid >> 5] = lsum;
    __syncthreads();
    float inv = 1.f / (red[0] + red[1] + red[2] + red[3] + red[4] + red[5] + red[6] + red[7]);
    for (int m = tid; m < 2048; m += 256) {
        float v = row[m] * inv;
        __nv_bfloat16 h = __float2bfloat16(v);
        g_Shi[(size_t)n * 2048 + m] = h;
        g_Slo[(size_t)n * 2048 + m] = __float2bfloat16(v - __bfloat162float(h));
    }
}

// ---------------- weight source transpose ----------------
__global__ void transpose_src(const float* __restrict__ Wg0, const float* __restrict__ Wu0,
                              const float* __restrict__ Wg1, const float* __restrict__ Wu1) {
    int idx = blockIdx.x * 256 + threadIdx.x;
    if (idx >= 768000) return;
    const float* W; int off, OUT, K2, K2P;
    if (idx < 184320)      { W = Wg0; off = 0;      OUT = 128; K2 = 130; K2P = 144; }
    else if (idx < 276480) { W = Wu0; off = 184320; OUT = 64;  K2 = 130; K2P = 144; }
    else if (idx < 604160) { W = Wg1; off = 276480; OUT = 128; K2 = 256; K2P = 256; }
    else                   { W = Wu1; off = 604160; OUT = 64;  K2 = 256; K2P = 256; }
    int rem = idx - off;
    int d = rem / (OUT * K2P);
    int r2 = rem % (OUT * K2P);
    int o = r2 / K2P, kp = r2 % K2P;
    g_Tsrc[idx] = (kp < K2) ? W[(size_t)d * K2 * OUT + (size_t)kp * OUT + o] : 0.f;
}

// ---------------- bf16 hi/lo weight expansion (staging layout) ----------------
__global__ __launch_bounds__(256) void expand_w(const float* __restrict__ E) {
    __shared__ float Es[32][10];
    __shared__ float Ws[10][256];
    int bid = blockIdx.x, tid = threadIdx.x;
    int o, nc, OUT, K2P; size_t toff; __nv_bfloat16 *Dhi, *Dlo;
    if (bid < 8192)       { int r = bid;         o = r >> 6; nc = r & 63; OUT = 128; K2P = 144; toff = 0;      Dhi = g_Wg0t_hi; Dlo = g_Wg0t_lo; }
    else if (bid < 12288) { int r = bid - 8192;  o = r >> 6; nc = r & 63; OUT = 64;  K2P = 144; toff = 184320; Dhi = g_Wu0t_hi; Dlo = g_Wu0t_lo; }
    else if (bid < 20480) { int r = bid - 12288; o = r >> 6; nc = r & 63; OUT = 128; K2P = 256; toff = 276480; Dhi = g_Wg1t_hi; Dlo = g_Wg1t_lo; }
    else                  { int r = bid - 20480; o = r >> 6; nc = r & 63; OUT = 64;  K2P = 256; toff = 604160; Dhi = g_Wu1t_hi; Dlo = g_Wu1t_lo; }
    for (int s = tid; s < 320; s += 256)
        Es[s / 10][s % 10] = E[(nc * 32 + s / 10) * 10 + s % 10];
    for (int d = 0; d < 10; d++)
        if (tid < K2P) Ws[d][tid] = g_Tsrc[toff + ((size_t)d * OUT + o) * K2P + tid];
    __syncthreads();
    if (tid >= K2P) return;
#pragma unroll 1
    for (int n = 0; n < 32; n++) {
        float a = 0.f;
#pragma unroll
        for (int d = 0; d < 10; d++) a = fmaf(Es[n][d], Ws[d][tid], a);
        __nv_bfloat16 h = __float2bfloat16(a);
        size_t base = ((size_t)(nc * 32 + n) * OUT + o) * K2P + tid;
        Dhi[base] = h;
        Dlo[base] = __float2bfloat16(a - __bfloat162float(h));
    }
}

// ---------------- fragmentize: staging [n][o][kp] -> fragment order ----------------
// dst u32 index within (n,og8): u = ks*128 + lane*4 + c
//   c: 0 = bhi(j=0), 1 = bhi(j=1), 2 = blo(j=0), 3 = blo(j=1)
//   lane l holds: o_loc = l>>2, k = ks*16 + j*8 + (l&3)*2 (+ 0/1 in u32 low/high half)
__global__ __launch_bounds__(128) void fragmentize() {
    __shared__ __nv_bfloat16 shh[8 * 256];
    __shared__ __nv_bfloat16 sll[8 * 256];
    int bid = blockIdx.x, tid = threadIdx.x;
    int OUT, K2P, KST, G; const __nv_bfloat16 *Shi, *Slo; uint32_t* D;
    int n, g8;
    if (bid < 32768)       { int r = bid;          n = r >> 4; g8 = r & 15; OUT = 128; K2P = 144; KST = 9;  G = 16; Shi = g_Wg0t_hi; Slo = g_Wg0t_lo; D = g_WFg0; }
    else if (bid < 49152)  { int r = bid - 32768;  n = r >> 3; g8 = r & 7;  OUT = 64;  K2P = 144; KST = 9;  G = 8;  Shi = g_Wu0t_hi; Slo = g_Wu0t_lo; D = g_WFu0; }
    else if (bid < 81920)  { int r = bid - 49152;  n = r >> 4; g8 = r & 15; OUT = 128; K2P = 256; KST = 16; G = 16; Shi = g_Wg1t_hi; Slo = g_Wg1t_lo; D = g_WFg1; }
    else                   { int r = bid - 81920;  n = r >> 3; g8 = r & 7;  OUT = 64;  K2P = 256; KST = 16; G = 8;  Shi = g_Wu1t_hi; Slo = g_Wu1t_lo; D = g_WFu1; }

    for (int idx = tid; idx < 8 * K2P; idx += 128) {
        int o = idx / K2P, kp = idx % K2P;
        size_t s = ((size_t)n * OUT + g8 * 8 + o) * K2P + kp;
        shh[o * 256 + kp] = Shi[s];
        sll[o * 256 + kp] = Slo[s];
    }
    __syncthreads();

    uint32_t* dst = D + ((size_t)n * G + g8) * (size_t)(KST * 128);
    int tot = KST * 128;
    for (int u = tid; u < tot; u += 128) {
        int ks = u >> 7, r = u & 127;
        int lane = r >> 2, c = r & 3;
        int hlo = c >> 1, j = c & 1;
        int o_loc = lane >> 2;
        int k = ks * 16 + j * 8 + (lane & 3) * 2;
        const __nv_bfloat16* arr = hlo ? sll : shh;
        unsigned short e0 = *(const unsigned short*)&arr[o_loc * 256 + k];
        unsigned short e1 = *(const unsigned short*)&arr[o_loc * 256 + k + 1];
        dst[u] = (uint32_t)e0 | ((uint32_t)e1 << 16);
    }
}

// ---------------- bias expansion ----------------
__global__ void expand_bias(const float* __restrict__ E,
                            const float* __restrict__ bg0, const float* __restrict__ bu0,
                            const float* __restrict__ bg1, const float* __restrict__ bu1) {
    int n = blockIdx.x, tid = threadIdx.x;  // 384 threads
    const float* B; float* D; int M, j;
    if (tid < 128)      { B = bg0; D = g_bg0; M = 128; j = tid; }
    else if (tid < 192) { B = bu0; D = g_bu0; M = 64;  j = tid - 128; }
    else if (tid < 320) { B = bg1; D = g_bg1; M = 128; j = tid - 192; }
    else                { B = bu1; D = g_bu1; M = 64;  j = tid - 320; }
    float a = 0.f;
#pragma unroll
    for (int d = 0; d < 10; d++) a = fmaf(E[n * 10 + d], B[d * M + j], a);
    D[n * M + j] = a;
}

__global__ void zero_all() {
    int idx = blockIdx.x * 256 + threadIdx.x;
    if (idx < NN * 2048) g_SY[idx] = 0.f;
    if (idx < NN * NB * HD) {
        g_state0a[idx] = 0.f; g_state0b[idx] = 0.f; g_state1[idx] = 0.f;
    }
}

// ---------------- packers ----------------
__global__ void pack_x(const float* __restrict__ src) {
    int idx = blockIdx.x * 256 + threadIdx.x;
    if (idx >= 256 * 2048) return;
    int m = idx & 2047, j = idx >> 11;
    float v = 0.f;
    if (j < 192) v = src[(((j & 15) * TT) + (j >> 4)) * NN + m];
    __nv_bfloat16 h = __float2bfloat16(v);
    g_Bhi[(size_t)j * 2048 + m] = h;
    g_Blo[(size_t)j * 2048 + m] = __float2bfloat16(v - __bfloat162float(h));
}

__global__ __launch_bounds__(256) void pack_big(int t) {
    __shared__ float tile[32][33];
    const float* __restrict__ s0 = s0WR(t);
    int m0 = blockIdx.x * 32, j0 = blockIdx.y * 32;
    int tx = threadIdx.x, ty = threadIdx.y;
#pragma unroll
    for (int i = 0; i < 4; i++) {
        int m = m0 + ty + i * 8;
        int j = j0 + tx;
        float v = (j < 1024) ? s0[m * 1024 + j] : g_state1[m * 1024 + (j - 1024)];
        tile[ty + i * 8][tx] = v;
    }
    __syncthreads();
#pragma unroll
    for (int i = 0; i < 4; i++) {
        int j = j0 + ty + i * 8;
        int m = m0 + tx;
        float v = tile[tx][ty + i * 8];
        __nv_bfloat16 h = __float2bfloat16(v);
        g_Bhi[(size_t)j * 2048 + m] = h;
        g_Blo[(size_t)j * 2048 + m] = __float2bfloat16(v - __bfloat162float(h));
    }
}

__global__ __launch_bounds__(256) void pack_zs(int sA, int sB) {
    __shared__ float tile[32][33];
    int set = (blockIdx.z == 0) ? sA : sB;
    const float* __restrict__ Z = set ? g_ZS1 : g_ZS0;
    __nv_bfloat16* __restrict__ Dhi = set ? g_B1hi : g_B0hi;
    __nv_bfloat16* __restrict__ Dlo = set ? g_B1lo : g_B0lo;
    int m0 = blockIdx.x * 32, j0 = blockIdx.y * 32;
    int tx = threadIdx.x, ty = threadIdx.y;
#pragma unroll
    for (int i = 0; i < 4; i++) {
        int m = m0 + ty + i * 8;
        int j = j0 + tx;
        tile[ty + i * 8][tx] = Z[m * 1024 + j];
    }
    __syncthreads();
#pragma unroll
    for (int i = 0; i < 4; i++) {
        int j = j0 + ty + i * 8;
        int m = m0 + tx;
        float v = tile[tx][ty + i * 8];
        __nv_bfloat16 h = __float2bfloat16(v);
        Dhi[(size_t)j * 2048 + m] = h;
        Dlo[(size_t)j * 2048 + m] = __float2bfloat16(v - __bfloat162float(h));
    }
}

// ---------------- big GEMM core (R9 proven config) ----------------
#define CHUNK_B   128
#define TILE_BYTES  (128 * 128)
#define STAGE_BYTES (4 * TILE_BYTES)
#define NCH 32

struct GemmCore {
    uint32_t sbase;
    int lane, wr, wc, row0, col0;
    const __nv_bfloat16 *Bhi, *Blo;

    __device__ __forceinline__ void load_chunk(int c, int tid) {
        int s = c & 1;
#pragma unroll
        for (int op = 0; op < 4; op++) {
            const __nv_bfloat16* gp0;
            int r0;
            if      (op == 0) { gp0 = g_Shi; r0 = row0; }
            else if (op == 1) { gp0 = g_Slo; r0 = row0; }
            else if (op == 2) { gp0 = Bhi;   r0 = col0; }
            else              { gp0 = Blo;   r0 = col0; }
            const char* g = (const char*)gp0 + (size_t)r0 * 4096 + (size_t)c * CHUNK_B;
            uint32_t sm0 = sbase + s * STAGE_BYTES + op * TILE_BYTES;
#pragma unroll
            for (int it = 0; it < 4; it++) {
                int seg = it * 256 + tid;
                int r = seg >> 3, c16 = seg & 7;
                uint32_t off = (uint32_t)(r * 128 + c16 * 16);
                uint32_t sw = off ^ ((off >> 3) & 0x70);
                asm volatile("cp.async.cg.shared.global [%0], [%1], 16;"
                             :: "r"(sm0 + sw), "l"(g + (size_t)r * 4096 + c16 * 16));
            }
        }
        asm volatile("cp.async.commit_group;" ::: "memory");
    }

    __device__ __forceinline__ void run(float* __restrict__ Cg, int J, int tid) {
        float acc[2][8][4];
#pragma unroll
        for (int i = 0; i < 2; i++)
#pragma unroll
            for (int j = 0; j < 8; j++)
#pragma unroll
                for (int k = 0; k < 4; k++) acc[i][j][k] = 0.f;

        int l15 = lane & 15, khalf = lane >> 4;
        int rA0 = wr * 32 + l15;
        int rB0 = wc * 64 + l15;
        uint32_t xA = (uint32_t)((rA0 & 7) * 16);
        uint32_t xB = (uint32_t)((rB0 & 7) * 16);

        uint32_t ah[2][2][4], al[2][2][4];
        uint32_t bh[2][4], bl[2][4];
        uint32_t tAhi = 0, tAlo = 0, tBhi = 0, tBlo = 0;

        auto ldA = [&](int buf, int kk) {
            uint32_t kb = (uint32_t)(kk * 32 + khalf * 16);
            ldsm4(ah[buf][0], tAhi + (uint32_t)(rA0 * 128)        + (kb ^ xA));
            ldsm4(ah[buf][1], tAhi + (uint32_t)((rA0 + 16) * 128) + (kb ^ xA));
            ldsm4(al[buf][0], tAlo + (uint32_t)(rA0 * 128)        + (kb ^ xA));
            ldsm4(al[buf][1], tAlo + (uint32_t)((rA0 + 16) * 128) + (kb ^ xA));
        };
        auto ldB = [&](int buf, int kk, int g) {
            uint32_t kb = (uint32_t)(kk * 32 + khalf * 16);
            int rB = rB0 + g * 16;
            ldsm4(bh[buf], tBhi + (uint32_t)(rB * 128) + (kb ^ xB));
            ldsm4(bl[buf], tBlo + (uint32_t)(rB * 128) + (kb ^ xB));
        };

        load_chunk(0, tid);
        load_chunk(1, tid);

        for (int c = 0; c < NCH; c++) {
            int s = c & 1;
            if (c + 1 < NCH) asm volatile("cp.async.wait_group 1;" ::: "memory");
            else             asm volatile("cp.async.wait_group 0;" ::: "memory");
            __syncthreads();

            tAhi = sbase + s * STAGE_BYTES;
            tAlo = tAhi + TILE_BYTES;
            tBhi = tAhi + 2 * TILE_BYTES;
            tBlo = tAhi + 3 * TILE_BYTES;

            ldA(0, 0);
            ldB(0, 0, 0);
#pragma unroll
            for (int kk = 0; kk < 4; kk++) {
                int ab = kk & 1;
#pragma unroll
                for (int g = 0; g < 4; g++) {
                    int gb = g & 1;
                    if (g < 3) {
                        ldB(gb ^ 1, kk, g + 1);
                    } else if (kk < 3) {
                        ldA(ab ^ 1, kk + 1);
                        ldB(0, kk + 1, 0);
                    }
                    mma16816(acc[0][g * 2 + 0], ah[ab][0], bh[gb][0], bh[gb][2]);
                    mma16816(acc[0][g * 2 + 0], ah[ab][0], bl[gb][0], bl[gb][2]);
                    mma16816(acc[0][g * 2 + 0], al[ab][0], bh[gb][0], bh[gb][2]);
                    mma16816(acc[0][g * 2 + 1], ah[ab][0], bh[gb][1], bh[gb][3]);
                    mma16816(acc[0][g * 2 + 1], ah[ab][0], bl[gb][1], bl[gb][3]);
                    mma16816(acc[0][g * 2 + 1], al[ab][0], bh[gb][1], bh[gb][3]);
                    mma16816(acc[1][g * 2 + 0], ah[ab][1], bh[gb][0], bh[gb][2]);
                    mma16816(acc[1][g * 2 + 0], ah[ab][1], bl[gb][0], bl[gb][2]);
                    mma16816(acc[1][g * 2 + 0], al[ab][1], bh[gb][0], bh[gb][2]);
                    mma16816(acc[1][g * 2 + 1], ah[ab][1], bh[gb][1], bh[gb][3]);
                    mma16816(acc[1][g * 2 + 1], ah[ab][1], bl[gb][1], bl[gb][3]);
                    mma16816(acc[1][g * 2 + 1], al[ab][1], bh[gb][1], bh[gb][3]);
                }
            }
            __syncthreads();
            if (c + 2 < NCH) load_chunk(c + 2, tid);
        }

        int qr = lane >> 2, qc = lane & 3;
#pragma unroll
        for (int mt = 0; mt < 2; mt++) {
#pragma unroll
            for (int nt = 0; nt < 8; nt++) {
                int col = col0 + wc * 64 + nt * 8 + qc * 2;
                if (col < J) {
                    int row = row0 + wr * 32 + mt * 16 + qr;
                    *(float2*)&Cg[(size_t)row * J + col] =
                        make_float2(acc[mt][nt][0], acc[mt][nt][1]);
                    *(float2*)&Cg[(size_t)(row + 8) * J + col] =
                        make_float2(acc[mt][nt][2], acc[mt][nt][3]);
                }
            }
        }
    }
};

template <int WHICH>
__global__ void __launch_bounds__(256, 1) mma_gemm(int J) {
    extern __shared__ __align__(1024) char smem[];
    GemmCore gc;
    int tid = threadIdx.x;
    gc.sbase = smem_u32(smem);
    gc.lane = tid & 31;
    int wid = tid >> 5;
    gc.wr = wid & 3; gc.wc = wid >> 2;
    gc.row0 = blockIdx.y * 128;
    gc.col0 = blockIdx.x * 128;
    gc.Bhi = g_Bhi; gc.Blo = g_Blo;
    gc.run((WHICH == 0) ? g_SY : g_SXall, J, tid);
}

__global__ void __launch_bounds__(256, 1) mma_gemm_sm(int sA, int sB) {
    extern __shared__ __align__(1024) char smem[];
    int set = (blockIdx.z == 0) ? sA : sB;
    GemmCore gc;
    int tid = threadIdx.x;
    gc.sbase = smem_u32(smem);
    gc.lane = tid & 31;
    int wid = tid >> 5;
    gc.wr = wid & 3; gc.wc = wid >> 2;
    gc.row0 = blockIdx.y * 128;
    gc.col0 = blockIdx.x * 128;
    gc.Bhi = set ? g_B1hi : g_B0hi;
    gc.Blo = set ? g_B1lo : g_B0lo;
    gc.run(set ? g_SZS1 : g_SZS0, 1024, tid);
}

// ---------------- tensor-core gate/update heads (fragment-LDG weights) ----------------
// MODE: 0 gate-layer0, 1 gate-layer1, 2 update-layer0, 3 update-layer1
template <int K2P, int MODE>
__device__ __forceinline__ void head_body(const float* __restrict__ src, int tt,
                                          char* smem, int bx) {
    constexpr int STRB = (K2P == 256) ? 512 : 384;
    constexpr int KST  = K2P / 16;
    constexpr bool GATE = (MODE == 0 || MODE == 1);
    int node, half;
    if (GATE) { node = bx >> 1; half = bx & 1; } else { node = bx; half = 0; }
    int tid = threadIdx.x, lane = tid & 31, w = tid >> 5;

    uint32_t sXhi = smem_u32(smem);
    uint32_t sXlo = sXhi + 16u * STRB;

    const uint32_t* WF;
    const float* bias;
    int og8 = (GATE ? half * 8 : 0) + w;
    if (MODE == 0)      { WF = g_WFg0 + ((size_t)node * 16 + og8) * (size_t)(KST * 128); bias = g_bg0 + node * 128 + half * 64; }
    else if (MODE == 1) { WF = g_WFg1 + ((size_t)node * 16 + og8) * (size_t)(KST * 128); bias = g_bg1 + node * 128 + half * 64; }
    else if (MODE == 2) { WF = g_WFu0 + ((size_t)node * 8  + og8) * (size_t)(KST * 128); bias = g_bu0 + node * 64; }
    else                { WF = g_WFu1 + ((size_t)node * 8  + og8) * (size_t)(KST * 128); bias = g_bu1 + node * 64; }
    const uint4* wp = (const uint4*)WF;  // [ks][lane] 16B each

    const float* srd = (MODE == 0 || MODE == 2) ? s0RD(tt) : (const float*)0;
    const float* swr = (MODE == 1 || MODE == 3) ? s0WR(tt) : (const float*)0;

    // ---- batched X gather ----
    if (K2P == 256) {
        float4 xv[4];
#pragma unroll
        for (int it = 0; it < 4; it++) {
            int v = it * 256 + tid;
            int b = v >> 6, i4 = (v & 63) << 2;
            int seg = i4 >> 6, off = i4 & 63;
            const float* p;
            if (MODE == 1) {
                if      (seg == 0) p = swr      + node * 1024 + b * 64 + off;
                else if (seg == 1) p = g_state1 + node * 1024 + b * 64 + off;
                else if (seg == 2) p = g_SY     + (size_t)node * 2048 + b * 64 + off;
                else               p = g_SY     + (size_t)node * 2048 + 1024 + b * 64 + off;
            } else {
                if      (seg == 0) p = swr      + node * 1024 + b * 64 + off;
                else if (seg == 1) p = g_ZS1    + node * 1024 + b * 64 + off;
                else if (seg == 2) p = g_SY     + (size_t)node * 2048 + b * 64 + off;
                else               p = g_SZS1   + node * 1024 + b * 64 + off;
            }
            xv[it] = *(const float4*)p;
        }
#pragma unroll
        for (int it = 0; it < 4; it++) {
            int v = it * 256 + tid;
            int b = v >> 6, i4 = (v & 63) << 2;
            float4 x = xv[it];
            __nv_bfloat16 h0 = __float2bfloat16(x.x), h1 = __float2bfloat16(x.y);
            __nv_bfloat16 h2 = __float2bfloat16(x.z), h3 = __float2bfloat16(x.w);
            uint32_t hi0 = ((uint32_t)*(unsigned short*)&h0) | ((uint32_t)*(unsigned short*)&h1 << 16);
            uint32_t hi1 = ((uint32_t)*(unsigned short*)&h2) | ((uint32_t)*(unsigned short*)&h3 << 16);
            __nv_bfloat16 l0 = __float2bfloat16(x.x - __bfloat162float(h0));
            __nv_bfloat16 l1 = __float2bfloat16(x.y - __bfloat162float(h1));
            __nv_bfloat16 l2 = __float2bfloat16(x.z - __bfloat162float(h2));
            __nv_bfloat16 l3 = __float2bfloat16(x.w - __bfloat162float(h3));
            uint32_t lo0 = ((uint32_t)*(unsigned short*)&l0) | ((uint32_t)*(unsigned short*)&l1 << 16);
            uint32_t lo1 = ((uint32_t)*(unsigned short*)&l2) | ((uint32_t)*(unsigned short*)&l3 << 16);
            uint32_t boff = (uint32_t)(b * STRB) + swz16(i4 >> 3, b) + (uint32_t)((i4 & 7) * 2);
            asm volatile("st.shared.v2.b32 [%0], {%1,%2};" :: "r"(sXhi + boff), "r"(hi0), "r"(hi1));
            asm volatile("st.shared.v2.b32 [%0], {%1,%2};" :: "r"(sXlo + boff), "r"(lo0), "r"(lo1));
        }
    } else {
        float vals[9];
#pragma unroll
        for (int it = 0; it < 9; it++) {
            int idx = it * 256 + tid;
            int b = idx / 144, i = idx % 144;
            float v = 0.f;
            if (MODE == 0) {
                if (i == 0)       v = src[(b * TT + tt) * NN + node];
                else if (i < 65)  v = srd[node * 1024 + b * 64 + (i - 1)];
                else if (i == 65) v = g_SXall[(size_t)node * 192 + tt * 16 + b];
                else if (i < 130) v = g_SY[(size_t)node * 2048 + b * 64 + (i - 66)];
            } else {
                if (i == 0)       v = src[(b * TT + tt) * NN + node];
                else if (i < 65)  v = g_ZS0[node * 1024 + b * 64 + (i - 1)];
                else if (i == 65) v = g_SXall[(size_t)node * 192 + tt * 16 + b];
                else if (i < 130) v = g_SZS0[node * 1024 + b * 64 + (i - 66)];
            }
            vals[it] = v;
        }
#pragma unroll
        for (int it = 0; it < 9; it++) {
            int idx = it * 256 + tid;
            int b = idx / 144, i = idx % 144;
            float v = vals[it];
            __nv_bfloat16 h = __float2bfloat16(v);
            __nv_bfloat16 l = __float2bfloat16(v - __bfloat162float(h));
            uint32_t boff = (uint32_t)(b * STRB) + swz16(i >> 3, b) + (uint32_t)((i & 7) * 2);
            asm volatile("st.shared.b16 [%0], %1;" :: "r"(sXhi + boff), "h"(*(unsigned short*)&h));
            asm volatile("st.shared.b16 [%0], %1;" :: "r"(sXlo + boff), "h"(*(unsigned short*)&l));
        }
    }
    __syncthreads();

    // ---- compute: warp w -> 8 outputs; weights streamed via LDG.128 ----
    float acc[4] = {0.f, 0.f, 0.f, 0.f};
    int l15 = lane & 15;
    int rowA = l15;
    int oL = w * 8;
#pragma unroll
    for (int ks = 0; ks < KST; ks++) {
        uint4 wv = wp[ks * 32 + lane];          // {bhi_j0, bhi_j1, blo_j0, blo_j1}
        int cA = ks * 2 + (lane >> 4);
        uint32_t offA = (uint32_t)(rowA * STRB) + swz16(cA, rowA);
        uint32_t ahi[4], alo[4];
        ldsm4(ahi, sXhi + offA);
        ldsm4(alo, sXlo + offA);
        mma16816(acc, ahi, wv.x, wv.y);
        mma16816(acc, alo, wv.x, wv.y);
        mma16816(acc, ahi, wv.z, wv.w);
    }

    int qr = lane >> 2;
    int o = oL + (lane & 3) * 2;
    float b0 = bias[o], b1 = bias[o + 1];
    int base0 = node * 1024 + qr * 64 + o;
    int base1 = base0 + 512;

    if (GATE) {
        float* ZS = (MODE == 0) ? g_ZS0 : g_ZS1;
        float* R  = (MODE == 0) ? g_r0  : g_r1;
        const float* st = (MODE == 0) ? srd : g_state1;
        float s0 = 1.f / (1.f + expf(-(acc[0] + b0)));
        float s1 = 1.f / (1.f + expf(-(acc[1] + b1)));
        float s2 = 1.f / (1.f + expf(-(acc[2] + b0)));
        float s3 = 1.f / (1.f + expf(-(acc[3] + b1)));
        if (half == 0) {
            ZS[base0]     = s0 * st[base0];
            ZS[base0 + 1] = s1 * st[base0 + 1];
            ZS[base1]     = s2 * st[base1];
            ZS[base1 + 1] = s3 * st[base1 + 1];
        } else {
            R[base0] = s0; R[base0 + 1] = s1;
            R[base1] = s2; R[base1 + 1] = s3;
        }
    } else {
        const float* R   = (MODE == 2) ? g_r0 : g_r1;
        const float* stR = (MODE == 2) ? srd : g_state1;
        float* stW       = (MODE == 2) ? s0WR(tt) : g_state1;
        float h0 = tanhf(acc[0] + b0);
        float h1 = tanhf(acc[1] + b1);
        float h2 = tanhf(acc[2] + b0);
        float h3 = tanhf(acc[3] + b1);
        float r0v = R[base0],     r1v = R[base0 + 1];
        float r2v = R[base1],     r3v = R[base1 + 1];
        stW[base0]     = r0v * stR[base0]     + (1.f - r0v) * h0;
        stW[base0 + 1] = r1v * stR[base0 + 1] + (1.f - r1v) * h1;
        stW[base1]     = r2v * stR[base1]     + (1.f - r2v) * h2;
        stW[base1 + 1] = r3v * stR[base1 + 1] + (1.f - r3v) * h3;
    }
}

__global__ __launch_bounds__(256) void fused_gate(const float* __restrict__ src, int t1, int t0) {
    extern __shared__ __align__(128) char smem[];
    int role;
    if (gridDim.y == 2) role = (blockIdx.y == 0) ? 1 : 0;
    else                role = (t1 >= 0) ? 1 : 0;
    if (role) head_body<256, 1>(src, t1, smem, blockIdx.x);
    else      head_body<144, 0>(src, t0, smem, blockIdx.x);
}

__global__ __launch_bounds__(256) void fused_update(const float* __restrict__ src, int t1, int t0) {
    extern __shared__ __align__(128) char smem[];
    int role;
    if (gridDim.y == 2) role = (blockIdx.y == 0) ? 1 : 0;
    else                role = (t1 >= 0) ? 1 : 0;
    if (role) head_body<256, 3>(src, t1, smem, blockIdx.x);
    else      head_body<144, 2>(src, t0, smem, blockIdx.x);
}

// ---------------- output head ----------------
__global__ void out_kernel(const float* __restrict__ cw, const float* __restrict__ cb,
                           float* __restrict__ out) {
    int idx = blockIdx.x * 256 + threadIdx.x;
    if (idx >= NB * HR * NN) return;
    int n = idx & 2047;
    int h = (idx >> 11) % HR;
    int b = idx / (HR * NN);
    float a = cb[h];
#pragma unroll
    for (int c = 0; c < 64; c++)
        a = fmaf(g_state1[n * 1024 + b * 64 + c], cw[h * 64 + c], a);
    out[idx] = a;
}

// ---------------- launcher ----------------
extern "C" void kernel_launch(void* const* d_in, const int* in_sizes, int n_in,
                              void* d_out, int out_size) {
    const float* src = (const float*)d_in[0];
    const float* E   = (const float*)d_in[1];
    const float* Wg0 = (const float*)d_in[2];
    const float* bg0 = (const float*)d_in[3];
    const float* Wu0 = (const float*)d_in[4];
    const float* bu0 = (const float*)d_in[5];
    const float* Wg1 = (const float*)d_in[6];
    const float* bg1 = (const float*)d_in[7];
    const float* Wu1 = (const float*)d_in[8];
    const float* bu1 = (const float*)d_in[9];
    const float* cw  = (const float*)d_in[10];
    const float* cb  = (const float*)d_in[11];
    float* out = (float*)d_out;

    const int GEMM_SMEM = 2 * STAGE_BYTES;   // 128 KB
    const int HEAD_SMEM = 32 * 512;          // 16 KB (X only)
    cudaFuncSetAttribute(mma_gemm<0>,  cudaFuncAttributeMaxDynamicSharedMemorySize, GEMM_SMEM);
    cudaFuncSetAttribute(mma_gemm<2>,  cudaFuncAttributeMaxDynamicSharedMemorySize, GEMM_SMEM);
    cudaFuncSetAttribute(mma_gemm_sm,  cudaFuncAttributeMaxDynamicSharedMemorySize, GEMM_SMEM);
    cudaFuncSetAttribute(fused_gate,   cudaFuncAttributeMaxDynamicSharedMemorySize, HEAD_SMEM);
    cudaFuncSetAttribute(fused_update, cudaFuncAttributeMaxDynamicSharedMemorySize, HEAD_SMEM);

    dim3 pk(32, 8);

    // launches 1..4: #4 is a small THROWAWAY fused_gate for ncu profiling.
    build_S<<<NN, 256>>>(E);                                           // 1
    zero_all<<<(NN * 2048 + 255) / 256, 256>>>();                      // 2
    pack_x<<<(256 * 2048 + 255) / 256, 256>>>(src);                    // 3
    fused_gate<<<dim3(1024, 2), 256, HEAD_SMEM>>>(src, 0, 1);          // 4 <- PROFILED (throwaway)

    mma_gemm<2><<<dim3(2, 16), 256, GEMM_SMEM>>>(192);                 // S@X all steps
    transpose_src<<<3000, 256>>>(Wg0, Wu0, Wg1, Wu1);
    expand_w<<<24576, 256>>>(E);
    fragmentize<<<98304, 128>>>();
    expand_bias<<<NN, 384>>>(E, bg0, bu0, bg1, bu1);

    // prologue: layer0 @ t=0
    fused_gate  <<<dim3(4096, 1), 256, HEAD_SMEM>>>(src, -1, 0);
    pack_zs     <<<dim3(64, 32, 1), pk>>>(0, 0);
    mma_gemm_sm <<<dim3(8, 16, 1), 256, GEMM_SMEM>>>(0, 0);
    fused_update<<<dim3(2048, 1), 256, HEAD_SMEM>>>(src, -1, 0);
    pack_big    <<<dim3(64, 64), pk>>>(0);
    mma_gemm<0> <<<dim3(16, 16), 256, GEMM_SMEM>>>(2048);

    // steady state: layer1(t) || layer0(t+1)
    for (int t = 0; t + 1 < TT; t++) {
        fused_gate  <<<dim3(4096, 2), 256, HEAD_SMEM>>>(src, t, t + 1);
        pack_zs     <<<dim3(64, 32, 2), pk>>>(1, 0);
        mma_gemm_sm <<<dim3(8, 16, 2), 256, GEMM_SMEM>>>(1, 0);
        fused_update<<<dim3(2048, 2), 256, HEAD_SMEM>>>(src, t, t + 1);
        pack_big    <<<dim3(64, 64), pk>>>(t + 1);
        mma_gemm<0> <<<dim3(16, 16), 256, GEMM_SMEM>>>(2048);
    }

    // epilogue: layer1 @ t=TT-1
    fused_gate  <<<dim3(4096, 1), 256, HEAD_SMEM>>>(src, TT - 1, -1);
    pack_zs     <<<dim3(64, 32, 1), pk>>>(1, 1);
    mma_gemm_sm <<<dim3(16, 16, 1), 256, GEMM_SMEM>>>(1, 1);
    fused_update<<<dim3(2048, 1), 256, HEAD_SMEM>>>(src, TT - 1, -1);

    out_kernel<<<(NB * HR * NN + 255) / 256, 256>>>(cw, cb, out);
}

// round 12
// speedup vs baseline: 1.1107x; 1.0064x over previous
#include <cuda_runtime.h>
#include <cuda_bf16.h>
#include <math.h>
#include <stdint.h>

#define NB 16
#define TT 12
#define NN 2048
#define HD 64
#define HR 12

// ---------------- scratch ----------------
__device__ __nv_bfloat16 g_Shi[(size_t)NN * NN];
__device__ __nv_bfloat16 g_Slo[(size_t)NN * NN];
// MN-major packs: [m][j]
__device__ __nv_bfloat16 g_Ybhi[(size_t)NN * 2048];    // big: [m][0:1024)=state0', [1024:2048)=state1
__device__ __nv_bfloat16 g_Yblo[(size_t)NN * 2048];
__device__ __nv_bfloat16 g_Z0hi[(size_t)NN * 1024];    // z*state layer0
__device__ __nv_bfloat16 g_Z0lo[(size_t)NN * 1024];
__device__ __nv_bfloat16 g_Z1hi[(size_t)NN * 1024];    // z*state layer1
__device__ __nv_bfloat16 g_Z1lo[(size_t)NN * 1024];
__device__ __nv_bfloat16 g_Bxhi[(size_t)NN * 256];     // X pack [m][t*16+b]
__device__ __nv_bfloat16 g_Bxlo[(size_t)NN * 256];
// staging: per-node transposed weights [n][o][kp], bf16 hi/lo
__device__ __nv_bfloat16 g_Wg0t_hi[(size_t)NN * 128 * 144];
__device__ __nv_bfloat16 g_Wg0t_lo[(size_t)NN * 128 * 144];
__device__ __nv_bfloat16 g_Wu0t_hi[(size_t)NN * 64 * 144];
__device__ __nv_bfloat16 g_Wu0t_lo[(size_t)NN * 64 * 144];
__device__ __nv_bfloat16 g_Wg1t_hi[(size_t)NN * 128 * 256];
__device__ __nv_bfloat16 g_Wg1t_lo[(size_t)NN * 128 * 256];
__device__ __nv_bfloat16 g_Wu1t_hi[(size_t)NN * 64 * 256];
__device__ __nv_bfloat16 g_Wu1t_lo[(size_t)NN * 64 * 256];
// fragment-order weights
__device__ uint32_t g_WFg0[(size_t)NN * 16 * 9 * 128];
__device__ uint32_t g_WFu0[(size_t)NN * 8 * 9 * 128];
__device__ uint32_t g_WFg1[(size_t)NN * 16 * 16 * 128];
__device__ uint32_t g_WFu1[(size_t)NN * 8 * 16 * 128];
__device__ float g_Tsrc[768000];
__device__ float g_bg0[NN * 128];
__device__ float g_bu0[NN * 64];
__device__ float g_bg1[NN * 128];
__device__ float g_bu1[NN * 64];
__device__ float g_state0a[NN * NB * HD];
__device__ float g_state0b[NN * NB * HD];
__device__ float g_state1 [NN * NB * HD];
__device__ float g_SY [(size_t)NN * 2048];
__device__ float g_SXall[(size_t)NN * 192];
__device__ float g_SZS0[NN * NB * HD];
__device__ float g_SZS1[NN * NB * HD];
__device__ float g_ZS0[NN * NB * HD];
__device__ float g_ZS1[NN * NB * HD];
__device__ float g_r0 [NN * NB * HD];
__device__ float g_r1 [NN * NB * HD];

__device__ __forceinline__ float* s0RD(int t) { return (t & 1) ? g_state0b : g_state0a; }
__device__ __forceinline__ float* s0WR(int t) { return (t & 1) ? g_state0a : g_state0b; }

// ================= helpers =================
__device__ __forceinline__ uint32_t smem_u32(const void* p) {
    return (uint32_t)__cvta_generic_to_shared(p);
}
__device__ __forceinline__ void ldsm4(uint32_t* r, uint32_t a) {
    asm volatile("ldmatrix.sync.aligned.m8n8.x4.shared.b16 {%0,%1,%2,%3}, [%4];"
                 : "=r"(r[0]), "=r"(r[1]), "=r"(r[2]), "=r"(r[3]) : "r"(a));
}
__device__ __forceinline__ void ldsm4t(uint32_t* r, uint32_t a) {
    asm volatile("ldmatrix.sync.aligned.m8n8.x4.trans.shared.b16 {%0,%1,%2,%3}, [%4];"
                 : "=r"(r[0]), "=r"(r[1]), "=r"(r[2]), "=r"(r[3]) : "r"(a));
}
__device__ __forceinline__ void mma16816(float* c, const uint32_t* a, uint32_t b0, uint32_t b1) {
    asm volatile("mma.sync.aligned.m16n8k16.row.col.f32.bf16.bf16.f32 "
                 "{%0,%1,%2,%3}, {%4,%5,%6,%7}, {%8,%9}, {%0,%1,%2,%3};"
                 : "+f"(c[0]), "+f"(c[1]), "+f"(c[2]), "+f"(c[3])
                 : "r"(a[0]), "r"(a[1]), "r"(a[2]), "r"(a[3]), "r"(b0), "r"(b1));
}
__device__ __forceinline__ uint32_t swz16(int chunk, int row) {
    return (uint32_t)(((chunk & ~7) | ((chunk ^ row) & 7)) << 4);
}
__device__ __forceinline__ uint32_t bsplit_hi(float a, float b) {
    __nv_bfloat16 h0 = __float2bfloat16(a), h1 = __float2bfloat16(b);
    return (uint32_t)*(unsigned short*)&h0 | ((uint32_t)*(unsigned short*)&h1 << 16);
}
__device__ __forceinline__ uint32_t bsplit_lo(float a, float b) {
    __nv_bfloat16 h0 = __float2bfloat16(a), h1 = __float2bfloat16(b);
    __nv_bfloat16 l0 = __float2bfloat16(a - __bfloat162float(h0));
    __nv_bfloat16 l1 = __float2bfloat16(b - __bfloat162float(h1));
    return (uint32_t)*(unsigned short*)&l0 | ((uint32_t)*(unsigned short*)&l1 << 16);
}

// ---------------- S = softmax(relu(E E^T)) -> bf16 hi/lo ----------------
__global__ __launch_bounds__(256) void build_S(const float* __restrict__ E) {
    __shared__ float row[2048];
    __shared__ float red[8];
    int n = blockIdx.x, tid = threadIdx.x;
    float en[10];
#pragma unroll
    for (int d = 0; d < 10; d++) en[d] = E[n * 10 + d];
    float lmax = 0.f;
    for (int m = tid; m < 2048; m += 256) {
        float dot = 0.f;
#pragma unroll
        for (int d = 0; d < 10; d++) dot = fmaf(en[d], E[m * 10 + d], dot);
        dot = fmaxf(dot, 0.f);
        row[m] = dot;
        lmax = fmaxf(lmax, dot);
    }
#pragma unroll
    for (int o = 16; o; o >>= 1) lmax = fmaxf(lmax, __shfl_xor_sync(0xffffffffu, lmax, o));
    if ((tid & 31) == 0) red[tid >> 5] = lmax;
    __syncthreads();
    float mx = fmaxf(fmaxf(fmaxf(red[0], red[1]), fmaxf(red[2], red[3])),
                     fmaxf(fmaxf(red[4], red[5]), fmaxf(red[6], red[7])));
    __syncthreads();
    float lsum = 0.f;
    for (int m = tid; m < 2048; m += 256) {
        float e = expf(row[m] - mx);
        row[m] = e;
        lsum += e;
    }
#pragma unroll
    for (int o = 16; o; o >>= 1) lsum += __shfl_xor_sync(0xffffffffu, lsum, o);
    if ((tid & 31) == 0) red[tid >> 5] = lsum;
    __syncthreads();
    float inv = 1.f / (red[0] + red[1] + red[2] + red[3] + red[4] + red[5] + red[6] + red[7]);
    for (int m = tid; m < 2048; m += 256) {
        float v = row[m] * inv;
        __nv_bfloat16 h = __float2bfloat16(v);
        g_Shi[(size_t)n * 2048 + m] = h;
        g_Slo[(size_t)n * 2048 + m] = __float2bfloat16(v - __bfloat162float(h));
    }
}

// ---------------- weight source transpose ----------------
__global__ void transpose_src(const float* __restrict__ Wg0, const float* __restrict__ Wu0,
                              const float* __restrict__ Wg1, const float* __restrict__ Wu1) {
    int idx = blockIdx.x * 256 + threadIdx.x;
    if (idx >= 768000) return;
    const float* W; int off, OUT, K2, K2P;
    if (idx < 184320)      { W = Wg0; off = 0;      OUT = 128; K2 = 130; K2P = 144; }
    else if (idx < 276480) { W = Wu0; off = 184320; OUT = 64;  K2 = 130; K2P = 144; }
    else if (idx < 604160) { W = Wg1; off = 276480; OUT = 128; K2 = 256; K2P = 256; }
    else                   { W = Wu1; off = 604160; OUT = 64;  K2 = 256; K2P = 256; }
    int rem = idx - off;
    int d = rem / (OUT * K2P);
    int r2 = rem % (OUT * K2P);
    int o = r2 / K2P, kp = r2 % K2P;
    g_Tsrc[idx] = (kp < K2) ? W[(size_t)d * K2 * OUT + (size_t)kp * OUT + o] : 0.f;
}

// ---------------- bf16 hi/lo weight expansion (staging layout) ----------------
__global__ __launch_bounds__(256) void expand_w(const float* __restrict__ E) {
    __shared__ float Es[32][10];
    __shared__ float Ws[10][256];
    int bid = blockIdx.x, tid = threadIdx.x;
    int o, nc, OUT, K2P; size_t toff; __nv_bfloat16 *Dhi, *Dlo;
    if (bid < 8192)       { int r = bid;         o = r >> 6; nc = r & 63; OUT = 128; K2P = 144; toff = 0;      Dhi = g_Wg0t_hi; Dlo = g_Wg0t_lo; }
    else if (bid < 12288) { int r = bid - 8192;  o = r >> 6; nc = r & 63; OUT = 64;  K2P = 144; toff = 184320; Dhi = g_Wu0t_hi; Dlo = g_Wu0t_lo; }
    else if (bid < 20480) { int r = bid - 12288; o = r >> 6; nc = r & 63; OUT = 128; K2P = 256; toff = 276480; Dhi = g_Wg1t_hi; Dlo = g_Wg1t_lo; }
    else                  { int r = bid - 20480; o = r >> 6; nc = r & 63; OUT = 64;  K2P = 256; toff = 604160; Dhi = g_Wu1t_hi; Dlo = g_Wu1t_lo; }
    for (int s = tid; s < 320; s += 256)
        Es[s / 10][s % 10] = E[(nc * 32 + s / 10) * 10 + s % 10];
    for (int d = 0; d < 10; d++)
        if (tid < K2P) Ws[d][tid] = g_Tsrc[toff + ((size_t)d * OUT + o) * K2P + tid];
    __syncthreads();
    if (tid >= K2P) return;
#pragma unroll 1
    for (int n = 0; n < 32; n++) {
        float a = 0.f;
#pragma unroll
        for (int d = 0; d < 10; d++) a = fmaf(Es[n][d], Ws[d][tid], a);
        __nv_bfloat16 h = __float2bfloat16(a);
        size_t base = ((size_t)(nc * 32 + n) * OUT + o) * K2P + tid;
        Dhi[base] = h;
        Dlo[base] = __float2bfloat16(a - __bfloat162float(h));
    }
}

// ---------------- fragmentize ----------------
__global__ __launch_bounds__(128) void fragmentize() {
    __shared__ __nv_bfloat16 shh[8 * 256];
    __shared__ __nv_bfloat16 sll[8 * 256];
    int bid = blockIdx.x, tid = threadIdx.x;
    int OUT, K2P, KST, G; const __nv_bfloat16 *Shi, *Slo; uint32_t* D;
    int n, g8;
    if (bid < 32768)       { int r = bid;          n = r >> 4; g8 = r & 15; OUT = 128; K2P = 144; KST = 9;  G = 16; Shi = g_Wg0t_hi; Slo = g_Wg0t_lo; D = g_WFg0; }
    else if (bid < 49152)  { int r = bid - 32768;  n = r >> 3; g8 = r & 7;  OUT = 64;  K2P = 144; KST = 9;  G = 8;  Shi = g_Wu0t_hi; Slo = g_Wu0t_lo; D = g_WFu0; }
    else if (bid < 81920)  { int r = bid - 49152;  n = r >> 4; g8 = r & 15; OUT = 128; K2P = 256; KST = 16; G = 16; Shi = g_Wg1t_hi; Slo = g_Wg1t_lo; D = g_WFg1; }
    else                   { int r = bid - 81920;  n = r >> 3; g8 = r & 7;  OUT = 64;  K2P = 256; KST = 16; G = 8;  Shi = g_Wu1t_hi; Slo = g_Wu1t_lo; D = g_WFu1; }

    for (int idx = tid; idx < 8 * K2P; idx += 128) {
        int o = idx / K2P, kp = idx % K2P;
        size_t s = ((size_t)n * OUT + g8 * 8 + o) * K2P + kp;
        shh[o * 256 + kp] = Shi[s];
        sll[o * 256 + kp] = Slo[s];
    }
    __syncthreads();

    uint32_t* dst = D + ((size_t)n * G + g8) * (size_t)(KST * 128);
    int tot = KST * 128;
    for (int u = tid; u < tot; u += 128) {
        int ks = u >> 7, r = u & 127;
        int lane = r >> 2, c = r & 3;
        int hlo = c >> 1, j = c & 1;
        int o_loc = lane >> 2;
        int k = ks * 16 + j * 8 + (lane & 3) * 2;
        const __nv_bfloat16* arr = hlo ? sll : shh;
        unsigned short e0 = *(const unsigned short*)&arr[o_loc * 256 + k];
        unsigned short e1 = *(const unsigned short*)&arr[o_loc * 256 + k + 1];
        dst[u] = (uint32_t)e0 | ((uint32_t)e1 << 16);
    }
}

// ---------------- bias expansion ----------------
__global__ void expand_bias(const float* __restrict__ E,
                            const float* __restrict__ bg0, const float* __restrict__ bu0,
                            const float* __restrict__ bg1, const float* __restrict__ bu1) {
    int n = blockIdx.x, tid = threadIdx.x;  // 384 threads
    const float* B; float* D; int M, j;
    if (tid < 128)      { B = bg0; D = g_bg0; M = 128; j = tid; }
    else if (tid < 192) { B = bu0; D = g_bu0; M = 64;  j = tid - 128; }
    else if (tid < 320) { B = bg1; D = g_bg1; M = 128; j = tid - 192; }
    else                { B = bu1; D = g_bu1; M = 64;  j = tid - 320; }
    float a = 0.f;
#pragma unroll
    for (int d = 0; d < 10; d++) a = fmaf(E[n * 10 + d], B[d * M + j], a);
    D[n * M + j] = a;
}

__global__ void zero_all() {
    int idx = blockIdx.x * 256 + threadIdx.x;
    if (idx < NN * 2048) {
        g_SY[idx] = 0.f;
        g_Ybhi[idx] = __float2bfloat16(0.f);
        g_Yblo[idx] = __float2bfloat16(0.f);
    }
    if (idx < NN * NB * HD) {
        g_state0a[idx] = 0.f; g_state0b[idx] = 0.f; g_state1[idx] = 0.f;
    }
}

// ---------------- pack_x: [m][j], j = t*16+b (<192), zero-pad to 256 ----------------
__global__ void pack_x(const float* __restrict__ src) {
    int idx = blockIdx.x * 256 + threadIdx.x;
    if (idx >= NN * 256) return;
    int m = idx >> 8, j = idx & 255;
    float v = 0.f;
    if (j < 192) v = src[(((j & 15) * TT) + (j >> 4)) * NN + m];
    __nv_bfloat16 h = __float2bfloat16(v);
    g_Bxhi[idx] = h;
    g_Bxlo[idx] = __float2bfloat16(v - __bfloat162float(h));
}

// ---------------- big GEMM core: A K-major (S), B MN-major via ldsm.trans ----------------
#define CHUNK_B   128
#define TILE_BYTES  16384          // A: 128r x 128B; B: 64r x 256B
#define STAGE_BYTES (4 * TILE_BYTES)
#define NCH 32

struct GemmCore {
    uint32_t sbase;
    int lane, wr, wc, row0, col0, jrowb;
    const __nv_bfloat16 *Bhi, *Blo;

    __device__ __forceinline__ void load_chunk(int c, int tid) {
        int s = c & 1;
        uint32_t st = sbase + s * STAGE_BYTES;
#pragma unroll
        for (int op = 0; op < 2; op++) {  // A: Shi/Slo, 128 rows x 128B
            const __nv_bfloat16* gp0 = op ? g_Slo : g_Shi;
            const char* g = (const char*)gp0 + (size_t)row0 * 4096 + (size_t)c * CHUNK_B;
            uint32_t sm0 = st + op * TILE_BYTES;
#pragma unroll
            for (int it = 0; it < 4; it++) {
                int seg = it * 256 + tid;
                int r = seg >> 3, c16 = seg & 7;
                uint32_t off = (uint32_t)(r * 128 + c16 * 16);
                uint32_t sw = off ^ ((off >> 3) & 0x70);
                asm volatile("cp.async.cg.shared.global [%0], [%1], 16;"
                             :: "r"(sm0 + sw), "l"(g + (size_t)r * 4096 + c16 * 16));
            }
        }
#pragma unroll
        for (int op = 0; op < 2; op++) {  // B: [m][j] rows m=c*64.., 64 rows x 256B
            const __nv_bfloat16* gp0 = op ? Blo : Bhi;
            const char* g = (const char*)gp0 + ((size_t)(c * 64) * jrowb + col0) * 2;
            uint32_t sm0 = st + 2 * TILE_BYTES + op * TILE_BYTES;
#pragma unroll
            for (int it = 0; it < 4; it++) {
                int seg = it * 256 + tid;
                int r = seg >> 4, c16 = seg & 15;
                uint32_t sw = (uint32_t)(r * 256) + swz16(c16, r);
                asm volatile("cp.async.cg.shared.global [%0], [%1], 16;"
                             :: "r"(sm0 + sw), "l"(g + (size_t)r * jrowb * 2 + c16 * 16));
            }
        }
        asm volatile("cp.async.commit_group;" ::: "memory");
    }

    __device__ __forceinline__ void run(float* __restrict__ Cg, int J, int tid) {
        float acc[2][8][4];
#pragma unroll
        for (int i = 0; i < 2; i++)
#pragma unroll
            for (int j = 0; j < 8; j++)
#pragma unroll
                for (int k = 0; k < 4; k++) acc[i][j][k] = 0.f;

        int l15 = lane & 15, khalf = lane >> 4;
        int rA0 = wr * 32 + l15;
        uint32_t xA = (uint32_t)((rA0 & 7) * 16);
        int rll  = (lane & 7) + ((lane >> 4) << 3);   // B trans row-within-16
        int c16b = wc * 8 + ((lane >> 3) & 1);        // B trans col chunk base

        uint32_t ah[2][2][4], al[2][2][4];
        uint32_t bh[2][4], bl[2][4];
        uint32_t tAhi = 0, tAlo = 0, tBhi = 0, tBlo = 0;

        auto ldA = [&](int buf, int kk) {
            uint32_t kb = (uint32_t)(kk * 32 + khalf * 16);
            ldsm4(ah[buf][0], tAhi + (uint32_t)(rA0 * 128)        + (kb ^ xA));
            ldsm4(ah[buf][1], tAhi + (uint32_t)((rA0 + 16) * 128) + (kb ^ xA));
            ldsm4(al[buf][0], tAlo + (uint32_t)(rA0 * 128)        + (kb ^ xA));
            ldsm4(al[buf][1], tAlo + (uint32_t)((rA0 + 16) * 128) + (kb ^ xA));
        };
        auto ldB = [&](int buf, int kk, int g) {
            int rB = kk * 16 + rll;
            int c16 = c16b + g * 2;
            uint32_t off = (uint32_t)(rB * 256) + swz16(c16, rB);
            ldsm4t(bh[buf], tBhi + off);
            ldsm4t(bl[buf], tBlo + off);
        };

        load_chunk(0, tid);
        load_chunk(1, tid);

        for (int c = 0; c < NCH; c++) {
            int s = c & 1;
            if (c + 1 < NCH) asm volatile("cp.async.wait_group 1;" ::: "memory");
            else             asm volatile("cp.async.wait_group 0;" ::: "memory");
            __syncthreads();

            tAhi = sbase + s * STAGE_BYTES;
            tAlo = tAhi + TILE_BYTES;
            tBhi = tAhi + 2 * TILE_BYTES;
            tBlo = tAhi + 3 * TILE_BYTES;

            ldA(0, 0);
            ldB(0, 0, 0);
#pragma unroll
            for (int kk = 0; kk < 4; kk++) {
                int ab = kk & 1;
#pragma unroll
                for (int g = 0; g < 4; g++) {
                    int gb = g & 1;
                    if (g < 3) {
                        ldB(gb ^ 1, kk, g + 1);
                    } else if (kk < 3) {
                        ldA(ab ^ 1, kk + 1);
                        ldB(0, kk + 1, 0);
                    }
                    mma16816(acc[0][g * 2 + 0], ah[ab][0], bh[gb][0], bh[gb][2]);
                    mma16816(acc[0][g * 2 + 0], ah[ab][0], bl[gb][0], bl[gb][2]);
                    mma16816(acc[0][g * 2 + 0], al[ab][0], bh[gb][0], bh[gb][2]);
                    mma16816(acc[0][g * 2 + 1], ah[ab][0], bh[gb][1], bh[gb][3]);
                    mma16816(acc[0][g * 2 + 1], ah[ab][0], bl[gb][1], bl[gb][3]);
                    mma16816(acc[0][g * 2 + 1], al[ab][0], bh[gb][1], bh[gb][3]);
                    mma16816(acc[1][g * 2 + 0], ah[ab][1], bh[gb][0], bh[gb][2]);
                    mma16816(acc[1][g * 2 + 0], ah[ab][1], bl[gb][0], bl[gb][2]);
                    mma16816(acc[1][g * 2 + 0], al[ab][1], bh[gb][0], bh[gb][2]);
                    mma16816(acc[1][g * 2 + 1], ah[ab][1], bh[gb][1], bh[gb][3]);
                    mma16816(acc[1][g * 2 + 1], ah[ab][1], bl[gb][1], bl[gb][3]);
                    mma16816(acc[1][g * 2 + 1], al[ab][1], bh[gb][1], bh[gb][3]);
                }
            }
            __syncthreads();
            if (c + 2 < NCH) load_chunk(c + 2, tid);
        }

        int qr = lane >> 2, qc = lane & 3;
#pragma unroll
        for (int mt = 0; mt < 2; mt++) {
#pragma unroll
            for (int nt = 0; nt < 8; nt++) {
                int col = col0 + wc * 64 + nt * 8 + qc * 2;
                if (col < J) {
                    int row = row0 + wr * 32 + mt * 16 + qr;
                    *(float2*)&Cg[(size_t)row * J + col] =
                        make_float2(acc[mt][nt][0], acc[mt][nt][1]);
                    *(float2*)&Cg[(size_t)(row + 8) * J + col] =
                        make_float2(acc[mt][nt][2], acc[mt][nt][3]);
                }
            }
        }
    }
};

template <int WHICH>   // 0: Ybig->g_SY (J=2048); 2: Yx->g_SXall (J=192, jrow 256)
__global__ void __launch_bounds__(256, 1) mma_gemm(int J) {
    extern __shared__ __align__(1024) char smem[];
    GemmCore gc;
    int tid = threadIdx.x;
    gc.sbase = smem_u32(smem);
    gc.lane = tid & 31;
    int wid = tid >> 5;
    gc.wr = wid & 3; gc.wc = wid >> 2;
    gc.row0 = blockIdx.y * 128;
    gc.col0 = blockIdx.x * 128;
    if (WHICH == 0) { gc.Bhi = g_Ybhi; gc.Blo = g_Yblo; gc.jrowb = 2048; }
    else            { gc.Bhi = g_Bxhi; gc.Blo = g_Bxlo; gc.jrowb = 256;  }
    gc.run((WHICH == 0) ? g_SY : g_SXall, J, tid);
}

__global__ void __launch_bounds__(256, 1) mma_gemm_sm(int sA, int sB) {
    extern __shared__ __align__(1024) char smem[];
    int set = (blockIdx.z == 0) ? sA : sB;
    GemmCore gc;
    int tid = threadIdx.x;
    gc.sbase = smem_u32(smem);
    gc.lane = tid & 31;
    int wid = tid >> 5;
    gc.wr = wid & 3; gc.wc = wid >> 2;
    gc.row0 = blockIdx.y * 128;
    gc.col0 = blockIdx.x * 128;
    gc.Bhi = set ? g_Z1hi : g_Z0hi;
    gc.Blo = set ? g_Z1lo : g_Z0lo;
    gc.jrowb = 1024;
    gc.run(set ? g_SZS1 : g_SZS0, 1024, tid);
}

// ---------------- tensor-core gate/update heads (fragment-LDG weights, fused packs) ----------------
// MODE: 0 gate-layer0, 1 gate-layer1, 2 update-layer0, 3 update-layer1
template <int K2P, int MODE>
__device__ __forceinline__ void head_body(const float* __restrict__ src, int tt,
                                          char* smem, int bx) {
    constexpr int STRB = (K2P == 256) ? 512 : 384;
    constexpr int KST  = K2P / 16;
    constexpr bool GATE = (MODE == 0 || MODE == 1);
    int node, half;
    if (GATE) { node = bx >> 1; half = bx & 1; } else { node = bx; half = 0; }
    int tid = threadIdx.x, lane = tid & 31, w = tid >> 5;

    uint32_t sXhi = smem_u32(smem);
    uint32_t sXlo = sXhi + 16u * STRB;

    const uint32_t* WF;
    const float* bias;
    int og8 = (GATE ? half * 8 : 0) + w;
    if (MODE == 0)      { WF = g_WFg0 + ((size_t)node * 16 + og8) * (size_t)(KST * 128); bias = g_bg0 + node * 128 + half * 64; }
    else if (MODE == 1) { WF = g_WFg1 + ((size_t)node * 16 + og8) * (size_t)(KST * 128); bias = g_bg1 + node * 128 + half * 64; }
    else if (MODE == 2) { WF = g_WFu0 + ((size_t)node * 8  + og8) * (size_t)(KST * 128); bias = g_bu0 + node * 64; }
    else                { WF = g_WFu1 + ((size_t)node * 8  + og8) * (size_t)(KST * 128); bias = g_bu1 + node * 64; }
    const uint4* wp = (const uint4*)WF;

    const float* srd = (MODE == 0 || MODE == 2) ? s0RD(tt) : (const float*)0;
    const float* swr = (MODE == 1 || MODE == 3) ? s0WR(tt) : (const float*)0;

    // ---- batched X gather ----
    if (K2P == 256) {
        float4 xv[4];
#pragma unroll
        for (int it = 0; it < 4; it++) {
            int v = it * 256 + tid;
            int b = v >> 6, i4 = (v & 63) << 2;
            int seg = i4 >> 6, off = i4 & 63;
            const float* p;
            if (MODE == 1) {
                if      (seg == 0) p = swr      + node * 1024 + b * 64 + off;
                else if (seg == 1) p = g_state1 + node * 1024 + b * 64 + off;
                else if (seg == 2) p = g_SY     + (size_t)node * 2048 + b * 64 + off;
                else               p = g_SY     + (size_t)node * 2048 + 1024 + b * 64 + off;
            } else {
                if      (seg == 0) p = swr      + node * 1024 + b * 64 + off;
                else if (seg == 1) p = g_ZS1    + node * 1024 + b * 64 + off;
                else if (seg == 2) p = g_SY     + (size_t)node * 2048 + b * 64 + off;
                else               p = g_SZS1   + node * 1024 + b * 64 + off;
            }
            xv[it] = *(const float4*)p;
        }
#pragma unroll
        for (int it = 0; it < 4; it++) {
            int v = it * 256 + tid;
            int b = v >> 6, i4 = (v & 63) << 2;
            float4 x = xv[it];
            uint32_t hi0 = bsplit_hi(x.x, x.y), hi1 = bsplit_hi(x.z, x.w);
            uint32_t lo0 = bsplit_lo(x.x, x.y), lo1 = bsplit_lo(x.z, x.w);
            uint32_t boff = (uint32_t)(b * STRB) + swz16(i4 >> 3, b) + (uint32_t)((i4 & 7) * 2);
            asm volatile("st.shared.v2.b32 [%0], {%1,%2};" :: "r"(sXhi + boff), "r"(hi0), "r"(hi1));
            asm volatile("st.shared.v2.b32 [%0], {%1,%2};" :: "r"(sXlo + boff), "r"(lo0), "r"(lo1));
        }
    } else {
        float vals[9];
#pragma unroll
        for (int it = 0; it < 9; it++) {
            int idx = it * 256 + tid;
            int b = idx / 144, i = idx % 144;
            float v = 0.f;
            if (MODE == 0) {
                if (i == 0)       v = src[(b * TT + tt) * NN + node];
                else if (i < 65)  v = srd[node * 1024 + b * 64 + (i - 1)];
                else if (i == 65) v = g_SXall[(size_t)node * 192 + tt * 16 + b];
                else if (i < 130) v = g_SY[(size_t)node * 2048 + b * 64 + (i - 66)];
            } else {
                if (i == 0)       v = src[(b * TT + tt) * NN + node];
                else if (i < 65)  v = g_ZS0[node * 1024 + b * 64 + (i - 1)];
                else if (i == 65) v = g_SXall[(size_t)node * 192 + tt * 16 + b];
                else if (i < 130) v = g_SZS0[node * 1024 + b * 64 + (i - 66)];
            }
            vals[it] = v;
        }
#pragma unroll
        for (int it = 0; it < 9; it++) {
            int idx = it * 256 + tid;
            int b = idx / 144, i = idx % 144;
            float v = vals[it];
            __nv_bfloat16 h = __float2bfloat16(v);
            __nv_bfloat16 l = __float2bfloat16(v - __bfloat162float(h));
            uint32_t boff = (uint32_t)(b * STRB) + swz16(i >> 3, b) + (uint32_t)((i & 7) * 2);
            asm volatile("st.shared.b16 [%0], %1;" :: "r"(sXhi + boff), "h"(*(unsigned short*)&h));
            asm volatile("st.shared.b16 [%0], %1;" :: "r"(sXlo + boff), "h"(*(unsigned short*)&l));
        }
    }
    __syncthreads();

    // ---- compute: warp w -> 8 outputs; weights streamed via LDG.128 (double-buffered) ----
    float acc[4] = {0.f, 0.f, 0.f, 0.f};
    int l15 = lane & 15;
    int rowA = l15;
    int oL = w * 8;
    uint4 wv0 = wp[lane];
#pragma unroll
    for (int ks = 0; ks < KST; ks++) {
        uint4 wv = wv0;
        if (ks + 1 < KST) wv0 = wp[(ks + 1) * 32 + lane];
        int cA = ks * 2 + (lane >> 4);
        uint32_t offA = (uint32_t)(rowA * STRB) + swz16(cA, rowA);
        uint32_t ahi[4], alo[4];
        ldsm4(ahi, sXhi + offA);
        ldsm4(alo, sXlo + offA);
        mma16816(acc, ahi, wv.x, wv.y);
        mma16816(acc, alo, wv.x, wv.y);
        mma16816(acc, ahi, wv.z, wv.w);
    }

    int qr = lane >> 2;
    int o = oL + (lane & 3) * 2;
    float b0 = bias[o], b1 = bias[o + 1];
    int base0 = node * 1024 + qr * 64 + o;
    int base1 = base0 + 512;
    int j0 = qr * 64 + o;              // pack col (row b=qr)
    int j1 = (qr + 8) * 64 + o;        // pack col (row b=qr+8)

    if (GATE) {
        float* ZS = (MODE == 0) ? g_ZS0 : g_ZS1;
        float* R  = (MODE == 0) ? g_r0  : g_r1;
        const float* st = (MODE == 0) ? srd : g_state1;
        float s0 = 1.f / (1.f + expf(-(acc[0] + b0)));
        float s1 = 1.f / (1.f + expf(-(acc[1] + b1)));
        float s2 = 1.f / (1.f + expf(-(acc[2] + b0)));
        float s3 = 1.f / (1.f + expf(-(acc[3] + b1)));
        if (half == 0) {
            float z0 = s0 * st[base0],     z1 = s1 * st[base0 + 1];
            float z2 = s2 * st[base1],     z3 = s3 * st[base1 + 1];
            ZS[base0] = z0; ZS[base0 + 1] = z1;
            ZS[base1] = z2; ZS[base1 + 1] = z3;
            __nv_bfloat16* Zh = (MODE == 0) ? g_Z0hi : g_Z1hi;
            __nv_bfloat16* Zl = (MODE == 0) ? g_Z0lo : g_Z1lo;
            *(uint32_t*)&Zh[(size_t)node * 1024 + j0] = bsplit_hi(z0, z1);
            *(uint32_t*)&Zl[(size_t)node * 1024 + j0] = bsplit_lo(z0, z1);
            *(uint32_t*)&Zh[(size_t)node * 1024 + j1] = bsplit_hi(z2, z3);
            *(uint32_t*)&Zl[(size_t)node * 1024 + j1] = bsplit_lo(z2, z3);
        } else {
            R[base0] = s0; R[base0 + 1] = s1;
            R[base1] = s2; R[base1 + 1] = s3;
        }
    } else {
        const float* R   = (MODE == 2) ? g_r0 : g_r1;
        const float* stR = (MODE == 2) ? srd : g_state1;
        float* stW       = (MODE == 2) ? s0WR(tt) : g_state1;
        float h0 = tanhf(acc[0] + b0);
        float h1 = tanhf(acc[1] + b1);
        float h2 = tanhf(acc[2] + b0);
        float h3 = tanhf(acc[3] + b1);
        float r0v = R[base0],     r1v = R[base0 + 1];
        float r2v = R[base1],     r3v = R[base1 + 1];
        float n0 = r0v * stR[base0]     + (1.f - r0v) * h0;
        float n1 = r1v * stR[base0 + 1] + (1.f - r1v) * h1;
        float n2 = r2v * stR[base1]     + (1.f - r2v) * h2;
        float n3 = r3v * stR[base1 + 1] + (1.f - r3v) * h3;
        stW[base0] = n0; stW[base0 + 1] = n1;
        stW[base1] = n2; stW[base1 + 1] = n3;
        int jb = (MODE == 2) ? 0 : 1024;
        *(uint32_t*)&g_Ybhi[(size_t)node * 2048 + jb + j0] = bsplit_hi(n0, n1);
        *(uint32_t*)&g_Yblo[(size_t)node * 2048 + jb + j0] = bsplit_lo(n0, n1);
        *(uint32_t*)&g_Ybhi[(size_t)node * 2048 + jb + j1] = bsplit_hi(n2, n3);
        *(uint32_t*)&g_Yblo[(size_t)node * 2048 + jb + j1] = bsplit_lo(n2, n3);
    }
}

__global__ __launch_bounds__(256) void fused_gate(const float* __restrict__ src, int t1, int t0) {
    extern __shared__ __align__(128) char smem[];
    int role;
    if (gridDim.y == 2) role = (blockIdx.y == 0) ? 1 : 0;
    else                role = (t1 >= 0) ? 1 : 0;
    if (role) head_body<256, 1>(src, t1, smem, blockIdx.x);
    else      head_body<144, 0>(src, t0, smem, blockIdx.x);
}

__global__ __launch_bounds__(256) void fused_update(const float* __restrict__ src, int t1, int t0) {
    extern __shared__ __align__(128) char smem[];
    int role;
    if (gridDim.y == 2) role = (blockIdx.y == 0) ? 1 : 0;
    else                role = (t1 >= 0) ? 1 : 0;
    if (role) head_body<256, 3>(src, t1, smem, blockIdx.x);
    else      head_body<144, 2>(src, t0, smem, blockIdx.x);
}

// ---------------- output head ----------------
__global__ void out_kernel(const float* __restrict__ cw, const float* __restrict__ cb,
                           float* __restrict__ out) {
    int idx = blockIdx.x * 256 + threadIdx.x;
    if (idx >= NB * HR * NN) return;
    int n = idx & 2047;
    int h = (idx >> 11) % HR;
    int b = idx / (HR * NN);
    float a = cb[h];
#pragma unroll
    for (int c = 0; c < 64; c++)
        a = fmaf(g_state1[n * 1024 + b * 64 + c], cw[h * 64 + c], a);
    out[idx] = a;
}

// ---------------- launcher ----------------
extern "C" void kernel_launch(void* const* d_in, const int* in_sizes, int n_in,
                              void* d_out, int out_size) {
    const float* src = (const float*)d_in[0];
    const float* E   = (const float*)d_in[1];
    const float* Wg0 = (const float*)d_in[2];
    const float* bg0 = (const float*)d_in[3];
    const float* Wu0 = (const float*)d_in[4];
    const float* bu0 = (const float*)d_in[5];
    const float* Wg1 = (const float*)d_in[6];
    const float* bg1 = (const float*)d_in[7];
    const float* Wu1 = (const float*)d_in[8];
    const float* bu1 = (const float*)d_in[9];
    const float* cw  = (const float*)d_in[10];
    const float* cb  = (const float*)d_in[11];
    float* out = (float*)d_out;

    const int GEMM_SMEM = 2 * STAGE_BYTES;   // 128 KB
    const int HEAD_SMEM = 32 * 512;          // 16 KB (X only)
    cudaFuncSetAttribute(mma_gemm<0>,  cudaFuncAttributeMaxDynamicSharedMemorySize, GEMM_SMEM);
    cudaFuncSetAttribute(mma_gemm<2>,  cudaFuncAttributeMaxDynamicSharedMemorySize, GEMM_SMEM);
    cudaFuncSetAttribute(mma_gemm_sm,  cudaFuncAttributeMaxDynamicSharedMemorySize, GEMM_SMEM);
    cudaFuncSetAttribute(fused_gate,   cudaFuncAttributeMaxDynamicSharedMemorySize, HEAD_SMEM);
    cudaFuncSetAttribute(fused_update, cudaFuncAttributeMaxDynamicSharedMemorySize, HEAD_SMEM);

    // launches 1..4: #4 is a small THROWAWAY fused_gate for ncu profiling.
    build_S<<<NN, 256>>>(E);                                           // 1
    zero_all<<<(NN * 2048 + 255) / 256, 256>>>();                      // 2
    pack_x<<<(NN * 256 + 255) / 256, 256>>>(src);                      // 3
    fused_gate<<<dim3(1024, 2), 256, HEAD_SMEM>>>(src, 0, 1);          // 4 <- PROFILED (throwaway)

    mma_gemm<2><<<dim3(2, 16), 256, GEMM_SMEM>>>(192);                 // S@X all steps
    transpose_src<<<3000, 256>>>(Wg0, Wu0, Wg1, Wu1);
    expand_w<<<24576, 256>>>(E);
    fragmentize<<<98304, 128>>>();
    expand_bias<<<NN, 384>>>(E, bg0, bu0, bg1, bu1);

    // prologue: layer0 @ t=0
    fused_gate  <<<dim3(4096, 1), 256, HEAD_SMEM>>>(src, -1, 0);
    mma_gemm_sm <<<dim3(8, 16, 1), 256, GEMM_SMEM>>>(0, 0);
    fused_update<<<dim3(2048, 1), 256, HEAD_SMEM>>>(src, -1, 0);
    mma_gemm<0> <<<dim3(16, 16), 256, GEMM_SMEM>>>(2048);

    // steady state: layer1(t) || layer0(t+1)
    for (int t = 0; t + 1 < TT; t++) {
        fused_gate  <<<dim3(4096, 2), 256, HEAD_SMEM>>>(src, t, t + 1);
        mma_gemm_sm <<<dim3(8, 16, 2), 256, GEMM_SMEM>>>(1, 0);
        fused_update<<<dim3(2048, 2), 256, HEAD_SMEM>>>(src, t, t + 1);
        mma_gemm<0> <<<dim3(16, 16), 256, GEMM_SMEM>>>(2048);
    }

    // epilogue: layer1 @ t=TT-1
    fused_gate  <<<dim3(4096, 1), 256, HEAD_SMEM>>>(src, TT - 1, -1);
    mma_gemm_sm <<<dim3(8, 16, 1), 256, GEMM_SMEM>>>(1, 1);
    fused_update<<<dim3(2048, 1), 256, HEAD_SMEM>>>(src, TT - 1, -1);

    out_kernel<<<(NB * HR * NN + 255) / 256, 256>>>(cw, cb, out);
}

// round 13
// speedup vs baseline: 1.1618x; 1.0460x over previous
#include <cuda_runtime.h>
#include <cuda_bf16.h>
#include <math.h>
#include <stdint.h>

#define NB 16
#define TT 12
#define NN 2048
#define HD 64
#define HR 12

// ---------------- scratch ----------------
__device__ __nv_bfloat16 g_Shi[(size_t)NN * NN];
__device__ __nv_bfloat16 g_Slo[(size_t)NN * NN];
// MN-major packs: [m][j]
__device__ __nv_bfloat16 g_Ybhi[(size_t)NN * 2048];    // big: [m][0:1024)=state0', [1024:2048)=state1
__device__ __nv_bfloat16 g_Yblo[(size_t)NN * 2048];
__device__ __nv_bfloat16 g_Z0hi[(size_t)NN * 1024];    // z*state layer0
__device__ __nv_bfloat16 g_Z0lo[(size_t)NN * 1024];
__device__ __nv_bfloat16 g_Z1hi[(size_t)NN * 1024];    // z*state layer1
__device__ __nv_bfloat16 g_Z1lo[(size_t)NN * 1024];
__device__ __nv_bfloat16 g_Bxhi[(size_t)NN * 256];     // X pack [m][t*16+b]
__device__ __nv_bfloat16 g_Bxlo[(size_t)NN * 256];
// fragment-order weights: [n][og8][ks][lane][c], c = {bhi_j0, bhi_j1, blo_j0, blo_j1}
__device__ uint32_t g_WFg0[(size_t)NN * 16 * 9 * 128];
__device__ uint32_t g_WFu0[(size_t)NN * 8 * 9 * 128];
__device__ uint32_t g_WFg1[(size_t)NN * 16 * 16 * 128];
__device__ uint32_t g_WFu1[(size_t)NN * 8 * 16 * 128];
__device__ float g_Tsrc[768000];
__device__ float g_bg0[NN * 128];
__device__ float g_bu0[NN * 64];
__device__ float g_bg1[NN * 128];
__device__ float g_bu1[NN * 64];
__device__ float g_state0a[NN * NB * HD];
__device__ float g_state0b[NN * NB * HD];
__device__ float g_state1 [NN * NB * HD];
__device__ float g_SY [(size_t)NN * 2048];
__device__ float g_SXall[(size_t)NN * 192];
__device__ float g_SZS0[NN * NB * HD];
__device__ float g_SZS1[NN * NB * HD];
__device__ float g_ZS0[NN * NB * HD];
__device__ float g_ZS1[NN * NB * HD];
__device__ float g_r0 [NN * NB * HD];
__device__ float g_r1 [NN * NB * HD];

__device__ __forceinline__ float* s0RD(int t) { return (t & 1) ? g_state0b : g_state0a; }
__device__ __forceinline__ float* s0WR(int t) { return (t & 1) ? g_state0a : g_state0b; }

// ================= helpers =================
__device__ __forceinline__ uint32_t smem_u32(const void* p) {
    return (uint32_t)__cvta_generic_to_shared(p);
}
__device__ __forceinline__ void ldsm4(uint32_t* r, uint32_t a) {
    asm volatile("ldmatrix.sync.aligned.m8n8.x4.shared.b16 {%0,%1,%2,%3}, [%4];"
                 : "=r"(r[0]), "=r"(r[1]), "=r"(r[2]), "=r"(r[3]) : "r"(a));
}
__device__ __forceinline__ void ldsm4t(uint32_t* r, uint32_t a) {
    asm volatile("ldmatrix.sync.aligned.m8n8.x4.trans.shared.b16 {%0,%1,%2,%3}, [%4];"
                 : "=r"(r[0]), "=r"(r[1]), "=r"(r[2]), "=r"(r[3]) : "r"(a));
}
__device__ __forceinline__ void mma16816(float* c, const uint32_t* a, uint32_t b0, uint32_t b1) {
    asm volatile("mma.sync.aligned.m16n8k16.row.col.f32.bf16.bf16.f32 "
                 "{%0,%1,%2,%3}, {%4,%5,%6,%7}, {%8,%9}, {%0,%1,%2,%3};"
                 : "+f"(c[0]), "+f"(c[1]), "+f"(c[2]), "+f"(c[3])
                 : "r"(a[0]), "r"(a[1]), "r"(a[2]), "r"(a[3]), "r"(b0), "r"(b1));
}
__device__ __forceinline__ uint32_t swz16(int chunk, int row) {
    return (uint32_t)(((chunk & ~7) | ((chunk ^ row) & 7)) << 4);
}
__device__ __forceinline__ uint32_t bsplit_hi(float a, float b) {
    __nv_bfloat16 h0 = __float2bfloat16(a), h1 = __float2bfloat16(b);
    return (uint32_t)*(unsigned short*)&h0 | ((uint32_t)*(unsigned short*)&h1 << 16);
}
__device__ __forceinline__ uint32_t bsplit_lo(float a, float b) {
    __nv_bfloat16 h0 = __float2bfloat16(a), h1 = __float2bfloat16(b);
    __nv_bfloat16 l0 = __float2bfloat16(a - __bfloat162float(h0));
    __nv_bfloat16 l1 = __float2bfloat16(b - __bfloat162float(h1));
    return (uint32_t)*(unsigned short*)&l0 | ((uint32_t)*(unsigned short*)&l1 << 16);
}

// ---------------- S = softmax(relu(E E^T)) -> bf16 hi/lo ----------------
__global__ __launch_bounds__(256) void build_S(const float* __restrict__ E) {
    __shared__ float row[2048];
    __shared__ float red[8];
    int n = blockIdx.x, tid = threadIdx.x;
    float en[10];
#pragma unroll
    for (int d = 0; d < 10; d++) en[d] = E[n * 10 + d];
    float lmax = 0.f;
    for (int m = tid; m < 2048; m += 256) {
        float dot = 0.f;
#pragma unroll
        for (int d = 0; d < 10; d++) dot = fmaf(en[d], E[m * 10 + d], dot);
        dot = fmaxf(dot, 0.f);
        row[m] = dot;
        lmax = fmaxf(lmax, dot);
    }
#pragma unroll
    for (int o = 16; o; o >>= 1) lmax = fmaxf(lmax, __shfl_xor_sync(0xffffffffu, lmax, o));
    if ((tid & 31) == 0) red[tid >> 5] = lmax;
    __syncthreads();
    float mx = fmaxf(fmaxf(fmaxf(red[0], red[1]), fmaxf(red[2], red[3])),
                     fmaxf(fmaxf(red[4], red[5]), fmaxf(red[6], red[7])));
    __syncthreads();
    float lsum = 0.f;
    for (int m = tid; m < 2048; m += 256) {
        float e = expf(row[m] - mx);
        row[m] = e;
        lsum += e;
    }
#pragma unroll
    for (int o = 16; o; o >>= 1) lsum += __shfl_xor_sync(0xffffffffu, lsum, o);
    if ((tid & 31) == 0) red[tid >> 5] = lsum;
    __syncthreads();
    float inv = 1.f / (red[0] + red[1] + red[2] + red[3] + red[4] + red[5] + red[6] + red[7]);
    for (int m = tid; m < 2048; m += 256) {
        float v = row[m] * inv;
        __nv_bfloat16 h = __float2bfloat16(v);
        g_Shi[(size_t)n * 2048 + m] = h;
        g_Slo[(size_t)n * 2048 + m] = __float2bfloat16(v - __bfloat162float(h));
    }
}

// ---------------- weight source transpose ----------------
__global__ void transpose_src(const float* __restrict__ Wg0, const float* __restrict__ Wu0,
                              const float* __restrict__ Wg1, const float* __restrict__ Wu1) {
    int idx = blockIdx.x * 256 + threadIdx.x;
    if (idx >= 768000) return;
    const float* W; int off, OUT, K2, K2P;
    if (idx < 184320)      { W = Wg0; off = 0;      OUT = 128; K2 = 130; K2P = 144; }
    else if (idx < 276480) { W = Wu0; off = 184320; OUT = 64;  K2 = 130; K2P = 144; }
    else if (idx < 604160) { W = Wg1; off = 276480; OUT = 128; K2 = 256; K2P = 256; }
    else                   { W = Wu1; off = 604160; OUT = 64;  K2 = 256; K2P = 256; }
    int rem = idx - off;
    int d = rem / (OUT * K2P);
    int r2 = rem % (OUT * K2P);
    int o = r2 / K2P, kp = r2 % K2P;
    g_Tsrc[idx] = (kp < K2) ? W[(size_t)d * K2 * OUT + (size_t)kp * OUT + o] : 0.f;
}

// ---------------- fused expand + fragmentize: Tsrc -> g_WF* directly ----------------
// Block = (nc group of 32 nodes, weight/og8 slot). Per ks: load W chunk (10 x 128),
// compute 128 fp32 per node (same FMA order as before), emit fragment u32s.
__global__ __launch_bounds__(128) void expand_frag(const float* __restrict__ E) {
    __shared__ float Es[32][10];
    __shared__ float Wc[10][128];
    __shared__ float vbuf[32][128];
    int bx = blockIdx.x, tid = threadIdx.x;
    int nc = bx / 48, wi = bx % 48;
    int OUT, K2P, KST, G, og8; size_t toff; uint32_t* D;
    if (wi < 16)      { og8 = wi;      OUT = 128; K2P = 144; KST = 9;  G = 16; toff = 0;      D = g_WFg0; }
    else if (wi < 24) { og8 = wi - 16; OUT = 64;  K2P = 144; KST = 9;  G = 8;  toff = 184320; D = g_WFu0; }
    else if (wi < 40) { og8 = wi - 24; OUT = 128; K2P = 256; KST = 16; G = 16; toff = 276480; D = g_WFg1; }
    else              { og8 = wi - 40; OUT = 64;  K2P = 256; KST = 16; G = 8;  toff = 604160; D = g_WFu1; }
    for (int s = tid; s < 320; s += 128)
        Es[s / 10][s % 10] = E[(nc * 32 + s / 10) * 10 + s % 10];

    // fragment write mapping for this thread
    int lane = tid >> 2, c = tid & 3;
    int hlo = c >> 1, j = c & 1;
    int wo = lane >> 2;
    int ridx = wo * 16 + j * 8 + (lane & 3) * 2;

#pragma unroll 1
    for (int ks = 0; ks < KST; ks++) {
        __syncthreads();   // Es ready (first iter); vbuf readers done (later iters)
        for (int i = tid; i < 1280; i += 128) {
            int d = i >> 7, r = i & 127;
            int o_loc = r >> 4, k16 = r & 15;
            Wc[d][r] = g_Tsrc[toff + ((size_t)d * OUT + og8 * 8 + o_loc) * K2P + ks * 16 + k16];
        }
        __syncthreads();
        {
            int r = tid;
#pragma unroll 1
            for (int n = 0; n < 32; n++) {
                float a = 0.f;
#pragma unroll
                for (int d = 0; d < 10; d++) a = fmaf(Es[n][d], Wc[d][r], a);
                vbuf[n][r] = a;
            }
        }
        __syncthreads();
#pragma unroll 1
        for (int n = 0; n < 32; n++) {
            float v0 = vbuf[n][ridx], v1 = vbuf[n][ridx + 1];
            uint32_t u = hlo ? bsplit_lo(v0, v1) : bsplit_hi(v0, v1);
            D[(((size_t)(nc * 32 + n) * G + og8) * KST + ks) * 128 + tid] = u;
        }
    }
}

// ---------------- bias expansion ----------------
__global__ void expand_bias(const float* __restrict__ E,
                            const float* __restrict__ bg0, const float* __restrict__ bu0,
                            const float* __restrict__ bg1, const float* __restrict__ bu1) {
    int n = blockIdx.x, tid = threadIdx.x;  // 384 threads
    const float* B; float* D; int M, j;
    if (tid < 128)      { B = bg0; D = g_bg0; M = 128; j = tid; }
    else if (tid < 192) { B = bu0; D = g_bu0; M = 64;  j = tid - 128; }
    else if (tid < 320) { B = bg1; D = g_bg1; M = 128; j = tid - 192; }
    else                { B = bu1; D = g_bu1; M = 64;  j = tid - 320; }
    float a = 0.f;
#pragma unroll
    for (int d = 0; d < 10; d++) a = fmaf(E[n * 10 + d], B[d * M + j], a);
    D[n * M + j] = a;
}

__global__ void zero_all() {
    int idx = blockIdx.x * 256 + threadIdx.x;
    if (idx < NN * 2048) {
        g_SY[idx] = 0.f;
        g_Ybhi[idx] = __float2bfloat16(0.f);
        g_Yblo[idx] = __float2bfloat16(0.f);
    }
    if (idx < NN * NB * HD) {
        g_state0a[idx] = 0.f; g_state0b[idx] = 0.f; g_state1[idx] = 0.f;
    }
}

// ---------------- pack_x: [m][j], j = t*16+b (<192), zero-pad to 256 ----------------
__global__ void pack_x(const float* __restrict__ src) {
    int idx = blockIdx.x * 256 + threadIdx.x;
    if (idx >= NN * 256) return;
    int m = idx >> 8, j = idx & 255;
    float v = 0.f;
    if (j < 192) v = src[(((j & 15) * TT) + (j >> 4)) * NN + m];
    __nv_bfloat16 h = __float2bfloat16(v);
    g_Bxhi[idx] = h;
    g_Bxlo[idx] = __float2bfloat16(v - __bfloat162float(h));
}

// ---------------- big GEMM core: A K-major (S), B MN-major via ldsm.trans ----------------
#define CHUNK_B   128
#define TILE_BYTES  16384          // A: 128r x 128B; B: 64r x 256B
#define STAGE_BYTES (4 * TILE_BYTES)
#define NCH 32

struct GemmCore {
    uint32_t sbase;
    int lane, wr, wc, row0, col0, jrowb;
    const __nv_bfloat16 *Bhi, *Blo;

    __device__ __forceinline__ void load_chunk(int c, int tid) {
        int s = c & 1;
        uint32_t st = sbase + s * STAGE_BYTES;
#pragma unroll
        for (int op = 0; op < 2; op++) {  // A: Shi/Slo, 128 rows x 128B
            const __nv_bfloat16* gp0 = op ? g_Slo : g_Shi;
            const char* g = (const char*)gp0 + (size_t)row0 * 4096 + (size_t)c * CHUNK_B;
            uint32_t sm0 = st + op * TILE_BYTES;
#pragma unroll
            for (int it = 0; it < 4; it++) {
                int seg = it * 256 + tid;
                int r = seg >> 3, c16 = seg & 7;
                uint32_t off = (uint32_t)(r * 128 + c16 * 16);
                uint32_t sw = off ^ ((off >> 3) & 0x70);
                asm volatile("cp.async.cg.shared.global [%0], [%1], 16;"
                             :: "r"(sm0 + sw), "l"(g + (size_t)r * 4096 + c16 * 16));
            }
        }
#pragma unroll
        for (int op = 0; op < 2; op++) {  // B: [m][j] rows m=c*64.., 64 rows x 256B
            const __nv_bfloat16* gp0 = op ? Blo : Bhi;
            const char* g = (const char*)gp0 + ((size_t)(c * 64) * jrowb + col0) * 2;
            uint32_t sm0 = st + 2 * TILE_BYTES + op * TILE_BYTES;
#pragma unroll
            for (int it = 0; it < 4; it++) {
                int seg = it * 256 + tid;
                int r = seg >> 4, c16 = seg & 15;
                uint32_t sw = (uint32_t)(r * 256) + swz16(c16, r);
                asm volatile("cp.async.cg.shared.global [%0], [%1], 16;"
                             :: "r"(sm0 + sw), "l"(g + (size_t)r * jrowb * 2 + c16 * 16));
            }
        }
        asm volatile("cp.async.commit_group;" ::: "memory");
    }

    __device__ __forceinline__ void run(float* __restrict__ Cg, int J, int tid) {
        float acc[2][8][4];
#pragma unroll
        for (int i = 0; i < 2; i++)
#pragma unroll
            for (int j = 0; j < 8; j++)
#pragma unroll
                for (int k = 0; k < 4; k++) acc[i][j][k] = 0.f;

        int l15 = lane & 15, khalf = lane >> 4;
        int rA0 = wr * 32 + l15;
        uint32_t xA = (uint32_t)((rA0 & 7) * 16);
        int rll  = (lane & 7) + ((lane >> 4) << 3);   // B trans row-within-16
        int c16b = wc * 8 + ((lane >> 3) & 1);        // B trans col chunk base

        uint32_t ah[2][2][4], al[2][2][4];
        uint32_t bh[2][4], bl[2][4];
        uint32_t tAhi = 0, tAlo = 0, tBhi = 0, tBlo = 0;

        auto ldA = [&](int buf, int kk) {
            uint32_t kb = (uint32_t)(kk * 32 + khalf * 16);
            ldsm4(ah[buf][0], tAhi + (uint32_t)(rA0 * 128)        + (kb ^ xA));
            ldsm4(ah[buf][1], tAhi + (uint32_t)((rA0 + 16) * 128) + (kb ^ xA));
            ldsm4(al[buf][0], tAlo + (uint32_t)(rA0 * 128)        + (kb ^ xA));
            ldsm4(al[buf][1], tAlo + (uint32_t)((rA0 + 16) * 128) + (kb ^ xA));
        };
        auto ldB = [&](int buf, int kk, int g) {
            int rB = kk * 16 + rll;
            int c16 = c16b + g * 2;
            uint32_t off = (uint32_t)(rB * 256) + swz16(c16, rB);
            ldsm4t(bh[buf], tBhi + off);
            ldsm4t(bl[buf], tBlo + off);
        };

        load_chunk(0, tid);
        load_chunk(1, tid);

        for (int c = 0; c < NCH; c++) {
            int s = c & 1;
            if (c + 1 < NCH) asm volatile("cp.async.wait_group 1;" ::: "memory");
            else             asm volatile("cp.async.wait_group 0;" ::: "memory");
            __syncthreads();

            tAhi = sbase + s * STAGE_BYTES;
            tAlo = tAhi + TILE_BYTES;
            tBhi = tAhi + 2 * TILE_BYTES;
            tBlo = tAhi + 3 * TILE_BYTES;

            ldA(0, 0);
            ldB(0, 0, 0);
#pragma unroll
            for (int kk = 0; kk < 4; kk++) {
                int ab = kk & 1;
#pragma unroll
                for (int g = 0; g < 4; g++) {
                    int gb = g & 1;
                    if (g < 3) {
                        ldB(gb ^ 1, kk, g + 1);
                    } else if (kk < 3) {
                        ldA(ab ^ 1, kk + 1);
                        ldB(0, kk + 1, 0);
                    }
                    mma16816(acc[0][g * 2 + 0], ah[ab][0], bh[gb][0], bh[gb][2]);
                    mma16816(acc[0][g * 2 + 0], ah[ab][0], bl[gb][0], bl[gb][2]);
                    mma16816(acc[0][g * 2 + 0], al[ab][0], bh[gb][0], bh[gb][2]);
                    mma16816(acc[0][g * 2 + 1], ah[ab][0], bh[gb][1], bh[gb][3]);
                    mma16816(acc[0][g * 2 + 1], ah[ab][0], bl[gb][1], bl[gb][3]);
                    mma16816(acc[0][g * 2 + 1], al[ab][0], bh[gb][1], bh[gb][3]);
                    mma16816(acc[1][g * 2 + 0], ah[ab][1], bh[gb][0], bh[gb][2]);
                    mma16816(acc[1][g * 2 + 0], ah[ab][1], bl[gb][0], bl[gb][2]);
                    mma16816(acc[1][g * 2 + 0], al[ab][1], bh[gb][0], bh[gb][2]);
                    mma16816(acc[1][g * 2 + 1], ah[ab][1], bh[gb][1], bh[gb][3]);
                    mma16816(acc[1][g * 2 + 1], ah[ab][1], bl[gb][1], bl[gb][3]);
                    mma16816(acc[1][g * 2 + 1], al[ab][1], bh[gb][1], bh[gb][3]);
                }
            }
            __syncthreads();
            if (c + 2 < NCH) load_chunk(c + 2, tid);
        }

        int qr = lane >> 2, qc = lane & 3;
#pragma unroll
        for (int mt = 0; mt < 2; mt++) {
#pragma unroll
            for (int nt = 0; nt < 8; nt++) {
                int col = col0 + wc * 64 + nt * 8 + qc * 2;
                if (col < J) {
                    int row = row0 + wr * 32 + mt * 16 + qr;
                    *(float2*)&Cg[(size_t)row * J + col] =
                        make_float2(acc[mt][nt][0], acc[mt][nt][1]);
                    *(float2*)&Cg[(size_t)(row + 8) * J + col] =
                        make_float2(acc[mt][nt][2], acc[mt][nt][3]);
                }
            }
        }
    }
};

template <int WHICH>   // 0: Ybig->g_SY (J=2048); 2: Yx->g_SXall (J=192, jrow 256)
__global__ void __launch_bounds__(256, 1) mma_gemm(int J) {
    extern __shared__ __align__(1024) char smem[];
    GemmCore gc;
    int tid = threadIdx.x;
    gc.sbase = smem_u32(smem);
    gc.lane = tid & 31;
    int wid = tid >> 5;
    gc.wr = wid & 3; gc.wc = wid >> 2;
    gc.row0 = blockIdx.y * 128;
    gc.col0 = blockIdx.x * 128;
    if (WHICH == 0) { gc.Bhi = g_Ybhi; gc.Blo = g_Yblo; gc.jrowb = 2048; }
    else            { gc.Bhi = g_Bxhi; gc.Blo = g_Bxlo; gc.jrowb = 256;  }
    gc.run((WHICH == 0) ? g_SY : g_SXall, J, tid);
}

__global__ void __launch_bounds__(256, 1) mma_gemm_sm(int sA, int sB) {
    extern __shared__ __align__(1024) char smem[];
    int set = (blockIdx.z == 0) ? sA : sB;
    GemmCore gc;
    int tid = threadIdx.x;
    gc.sbase = smem_u32(smem);
    gc.lane = tid & 31;
    int wid = tid >> 5;
    gc.wr = wid & 3; gc.wc = wid >> 2;
    gc.row0 = blockIdx.y * 128;
    gc.col0 = blockIdx.x * 128;
    gc.Bhi = set ? g_Z1hi : g_Z0hi;
    gc.Blo = set ? g_Z1lo : g_Z0lo;
    gc.jrowb = 1024;
    gc.run(set ? g_SZS1 : g_SZS0, 1024, tid);
}

// ---------------- tensor-core gate/update heads (fragment-LDG weights, fused packs) ----------------
// MODE: 0 gate-layer0, 1 gate-layer1, 2 update-layer0, 3 update-layer1
template <int K2P, int MODE>
__device__ __forceinline__ void head_body(const float* __restrict__ src, int tt,
                                          char* smem, int bx) {
    constexpr int STRB = (K2P == 256) ? 512 : 384;
    constexpr int KST  = K2P / 16;
    constexpr bool GATE = (MODE == 0 || MODE == 1);
    int node, half;
    if (GATE) { node = bx >> 1; half = bx & 1; } else { node = bx; half = 0; }
    int tid = threadIdx.x, lane = tid & 31, w = tid >> 5;

    uint32_t sXhi = smem_u32(smem);
    uint32_t sXlo = sXhi + 16u * STRB;

    const uint32_t* WF;
    const float* bias;
    int og8 = (GATE ? half * 8 : 0) + w;
    if (MODE == 0)      { WF = g_WFg0 + ((size_t)node * 16 + og8) * (size_t)(KST * 128); bias = g_bg0 + node * 128 + half * 64; }
    else if (MODE == 1) { WF = g_WFg1 + ((size_t)node * 16 + og8) * (size_t)(KST * 128); bias = g_bg1 + node * 128 + half * 64; }
    else if (MODE == 2) { WF = g_WFu0 + ((size_t)node * 8  + og8) * (size_t)(KST * 128); bias = g_bu0 + node * 64; }
    else                { WF = g_WFu1 + ((size_t)node * 8  + og8) * (size_t)(KST * 128); bias = g_bu1 + node * 64; }
    const uint4* wp = (const uint4*)WF;

    const float* srd = (MODE == 0 || MODE == 2) ? s0RD(tt) : (const float*)0;
    const float* swr = (MODE == 1 || MODE == 3) ? s0WR(tt) : (const float*)0;

    // ---- batched X gather ----
    if (K2P == 256) {
        float4 xv[4];
#pragma unroll
        for (int it = 0; it < 4; it++) {
            int v = it * 256 + tid;
            int b = v >> 6, i4 = (v & 63) << 2;
            int seg = i4 >> 6, off = i4 & 63;
            const float* p;
            if (MODE == 1) {
                if      (seg == 0) p = swr      + node * 1024 + b * 64 + off;
                else if (seg == 1) p = g_state1 + node * 1024 + b * 64 + off;
                else if (seg == 2) p = g_SY     + (size_t)node * 2048 + b * 64 + off;
                else               p = g_SY     + (size_t)node * 2048 + 1024 + b * 64 + off;
            } else {
                if      (seg == 0) p = swr      + node * 1024 + b * 64 + off;
                else if (seg == 1) p = g_ZS1    + node * 1024 + b * 64 + off;
                else if (seg == 2) p = g_SY     + (size_t)node * 2048 + b * 64 + off;
                else               p = g_SZS1   + node * 1024 + b * 64 + off;
            }
            xv[it] = *(const float4*)p;
        }
#pragma unroll
        for (int it = 0; it < 4; it++) {
            int v = it * 256 + tid;
            int b = v >> 6, i4 = (v & 63) << 2;
            float4 x = xv[it];
            uint32_t hi0 = bsplit_hi(x.x, x.y), hi1 = bsplit_hi(x.z, x.w);
            uint32_t lo0 = bsplit_lo(x.x, x.y), lo1 = bsplit_lo(x.z, x.w);
            uint32_t boff = (uint32_t)(b * STRB) + swz16(i4 >> 3, b) + (uint32_t)((i4 & 7) * 2);
            asm volatile("st.shared.v2.b32 [%0], {%1,%2};" :: "r"(sXhi + boff), "r"(hi0), "r"(hi1));
            asm volatile("st.shared.v2.b32 [%0], {%1,%2};" :: "r"(sXlo + boff), "r"(lo0), "r"(lo1));
        }
    } else {
        float vals[9];
#pragma unroll
        for (int it = 0; it < 9; it++) {
            int idx = it * 256 + tid;
            int b = idx / 144, i = idx % 144;
            float v = 0.f;
            if (MODE == 0) {
                if (i == 0)       v = src[(b * TT + tt) * NN + node];
                else if (i < 65)  v = srd[node * 1024 + b * 64 + (i - 1)];
                else if (i == 65) v = g_SXall[(size_t)node * 192 + tt * 16 + b];
                else if (i < 130) v = g_SY[(size_t)node * 2048 + b * 64 + (i - 66)];
            } else {
                if (i == 0)       v = src[(b * TT + tt) * NN + node];
                else if (i < 65)  v = g_ZS0[node * 1024 + b * 64 + (i - 1)];
                else if (i == 65) v = g_SXall[(size_t)node * 192 + tt * 16 + b];
                else if (i < 130) v = g_SZS0[node * 1024 + b * 64 + (i - 66)];
            }
            vals[it] = v;
        }
#pragma unroll
        for (int it = 0; it < 9; it++) {
            int idx = it * 256 + tid;
            int b = idx / 144, i = idx % 144;
            float v = vals[it];
            __nv_bfloat16 h = __float2bfloat16(v);
            __nv_bfloat16 l = __float2bfloat16(v - __bfloat162float(h));
            uint32_t boff = (uint32_t)(b * STRB) + swz16(i >> 3, b) + (uint32_t)((i & 7) * 2);
            asm volatile("st.shared.b16 [%0], %1;" :: "r"(sXhi + boff), "h"(*(unsigned short*)&h));
            asm volatile("st.shared.b16 [%0], %1;" :: "r"(sXlo + boff), "h"(*(unsigned short*)&l));
        }
    }
    __syncthreads();

    // ---- compute: warp w -> 8 outputs; weights via LDG.128, depth-2 prefetch ----
    float acc[4] = {0.f, 0.f, 0.f, 0.f};
    int l15 = lane & 15;
    int rowA = l15;
    int oL = w * 8;
    uint4 wva = wp[lane];
    uint4 wvb = (KST > 1) ? wp[32 + lane] : wva;
#pragma unroll
    for (int ks = 0; ks < KST; ks++) {
        uint4 wv = (ks & 1) ? wvb : wva;
        if (ks + 2 < KST) {
            if (ks & 1) wvb = wp[(ks + 2) * 32 + lane];
            else        wva = wp[(ks + 2) * 32 + lane];
        }
        int cA = ks * 2 + (lane >> 4);
        uint32_t offA = (uint32_t)(rowA * STRB) + swz16(cA, rowA);
        uint32_t ahi[4], alo[4];
        ldsm4(ahi, sXhi + offA);
        ldsm4(alo, sXlo + offA);
        mma16816(acc, ahi, wv.x, wv.y);
        mma16816(acc, alo, wv.x, wv.y);
        mma16816(acc, ahi, wv.z, wv.w);
    }

    int qr = lane >> 2;
    int o = oL + (lane & 3) * 2;
    float b0 = bias[o], b1 = bias[o + 1];
    int base0 = node * 1024 + qr * 64 + o;
    int base1 = base0 + 512;
    int j0 = qr * 64 + o;              // pack col (row b=qr)
    int j1 = (qr + 8) * 64 + o;        // pack col (row b=qr+8)

    if (GATE) {
        float* ZS = (MODE == 0) ? g_ZS0 : g_ZS1;
        float* R  = (MODE == 0) ? g_r0  : g_r1;
        const float* st = (MODE == 0) ? srd : g_state1;
        float s0 = 1.f / (1.f + expf(-(acc[0] + b0)));
        float s1 = 1.f / (1.f + expf(-(acc[1] + b1)));
        float s2 = 1.f / (1.f + expf(-(acc[2] + b0)));
        float s3 = 1.f / (1.f + expf(-(acc[3] + b1)));
        if (half == 0) {
            float z0 = s0 * st[base0],     z1 = s1 * st[base0 + 1];
            float z2 = s2 * st[base1],     z3 = s3 * st[base1 + 1];
            ZS[base0] = z0; ZS[base0 + 1] = z1;
            ZS[base1] = z2; ZS[base1 + 1] = z3;
            __nv_bfloat16* Zh = (MODE == 0) ? g_Z0hi : g_Z1hi;
            __nv_bfloat16* Zl = (MODE == 0) ? g_Z0lo : g_Z1lo;
            *(uint32_t*)&Zh[(size_t)node * 1024 + j0] = bsplit_hi(z0, z1);
            *(uint32_t*)&Zl[(size_t)node * 1024 + j0] = bsplit_lo(z0, z1);
            *(uint32_t*)&Zh[(size_t)node * 1024 + j1] = bsplit_hi(z2, z3);
            *(uint32_t*)&Zl[(size_t)node * 1024 + j1] = bsplit_lo(z2, z3);
        } else {
            R[base0] = s0; R[base0 + 1] = s1;
            R[base1] = s2; R[base1 + 1] = s3;
        }
    } else {
        const float* R   = (MODE == 2) ? g_r0 : g_r1;
        const float* stR = (MODE == 2) ? srd : g_state1;
        float* stW       = (MODE == 2) ? s0WR(tt) : g_state1;
        float h0 = tanhf(acc[0] + b0);
        float h1 = tanhf(acc[1] + b1);
        float h2 = tanhf(acc[2] + b0);
        float h3 = tanhf(acc[3] + b1);
        float r0v = R[base0],     r1v = R[base0 + 1];
        float r2v = R[base1],     r3v = R[base1 + 1];
        float n0 = r0v * stR[base0]     + (1.f - r0v) * h0;
        float n1 = r1v * stR[base0 + 1] + (1.f - r1v) * h1;
        float n2 = r2v * stR[base1]     + (1.f - r2v) * h2;
        float n3 = r3v * stR[base1 + 1] + (1.f - r3v) * h3;
        stW[base0] = n0; stW[base0 + 1] = n1;
        stW[base1] = n2; stW[base1 + 1] = n3;
        int jb = (MODE == 2) ? 0 : 1024;
        *(uint32_t*)&g_Ybhi[(size_t)node * 2048 + jb + j0] = bsplit_hi(n0, n1);
        *(uint32_t*)&g_Yblo[(size_t)node * 2048 + jb + j0] = bsplit_lo(n0, n1);
        *(uint32_t*)&g_Ybhi[(size_t)node * 2048 + jb + j1] = bsplit_hi(n2, n3);
        *(uint32_t*)&g_Yblo[(size_t)node * 2048 + jb + j1] = bsplit_lo(n2, n3);
    }
}

__global__ __launch_bounds__(256) void fused_gate(const float* __restrict__ src, int t1, int t0) {
    extern __shared__ __align__(128) char smem[];
    int role;
    if (gridDim.y == 2) role = (blockIdx.y == 0) ? 1 : 0;
    else                role = (t1 >= 0) ? 1 : 0;
    if (role) head_body<256, 1>(src, t1, smem, blockIdx.x);
    else      head_body<144, 0>(src, t0, smem, blockIdx.x);
}

__global__ __launch_bounds__(256) void fused_update(const float* __restrict__ src, int t1, int t0) {
    extern __shared__ __align__(128) char smem[];
    int role;
    if (gridDim.y == 2) role = (blockIdx.y == 0) ? 1 : 0;
    else                role = (t1 >= 0) ? 1 : 0;
    if (role) head_body<256, 3>(src, t1, smem, blockIdx.x);
    else      head_body<144, 2>(src, t0, smem, blockIdx.x);
}

// ---------------- output head ----------------
__global__ void out_kernel(const float* __restrict__ cw, const float* __restrict__ cb,
                           float* __restrict__ out) {
    int idx = blockIdx.x * 256 + threadIdx.x;
    if (idx >= NB * HR * NN) return;
    int n = idx & 2047;
    int h = (idx >> 11) % HR;
    int b = idx / (HR * NN);
    float a = cb[h];
#pragma unroll
    for (int c = 0; c < 64; c++)
        a = fmaf(g_state1[n * 1024 + b * 64 + c], cw[h * 64 + c], a);
    out[idx] = a;
}

// ---------------- launcher ----------------
extern "C" void kernel_launch(void* const* d_in, const int* in_sizes, int n_in,
                              void* d_out, int out_size) {
    const float* src = (const float*)d_in[0];
    const float* E   = (const float*)d_in[1];
    const float* Wg0 = (const float*)d_in[2];
    const float* bg0 = (const float*)d_in[3];
    const float* Wu0 = (const float*)d_in[4];
    const float* bu0 = (const float*)d_in[5];
    const float* Wg1 = (const float*)d_in[6];
    const float* bg1 = (const float*)d_in[7];
    const float* Wu1 = (const float*)d_in[8];
    const float* bu1 = (const float*)d_in[9];
    const float* cw  = (const float*)d_in[10];
    const float* cb  = (const float*)d_in[11];
    float* out = (float*)d_out;

    const int GEMM_SMEM = 2 * STAGE_BYTES;   // 128 KB
    const int HEAD_SMEM = 32 * 512;          // 16 KB (X only)
    cudaFuncSetAttribute(mma_gemm<0>,  cudaFuncAttributeMaxDynamicSharedMemorySize, GEMM_SMEM);
    cudaFuncSetAttribute(mma_gemm<2>,  cudaFuncAttributeMaxDynamicSharedMemorySize, GEMM_SMEM);
    cudaFuncSetAttribute(mma_gemm_sm,  cudaFuncAttributeMaxDynamicSharedMemorySize, GEMM_SMEM);
    cudaFuncSetAttribute(fused_gate,   cudaFuncAttributeMaxDynamicSharedMemorySize, HEAD_SMEM);
    cudaFuncSetAttribute(fused_update, cudaFuncAttributeMaxDynamicSharedMemorySize, HEAD_SMEM);

    // launches 1..4: #4 is a small THROWAWAY fused_gate for ncu profiling.
    build_S<<<NN, 256>>>(E);                                           // 1
    zero_all<<<(NN * 2048 + 255) / 256, 256>>>();                      // 2
    pack_x<<<(NN * 256 + 255) / 256, 256>>>(src);                      // 3
    fused_gate<<<dim3(1024, 2), 256, HEAD_SMEM>>>(src, 0, 1);          // 4 <- PROFILED (throwaway)

    mma_gemm<2><<<dim3(2, 16), 256, GEMM_SMEM>>>(192);                 // S@X all steps
    transpose_src<<<3000, 256>>>(Wg0, Wu0, Wg1, Wu1);
    expand_frag<<<3072, 128>>>(E);
    expand_bias<<<NN, 384>>>(E, bg0, bu0, bg1, bu1);

    // prologue: layer0 @ t=0
    fused_gate  <<<dim3(4096, 1), 256, HEAD_SMEM>>>(src, -1, 0);
    mma_gemm_sm <<<dim3(8, 16, 1), 256, GEMM_SMEM>>>(0, 0);
    fused_update<<<dim3(2048, 1), 256, HEAD_SMEM>>>(src, -1, 0);
    mma_gemm<0> <<<dim3(16, 16), 256, GEMM_SMEM>>>(2048);

    // steady state: layer1(t) || layer0(t+1)
    for (int t = 0; t + 1 < TT; t++) {
        fused_gate  <<<dim3(4096, 2), 256, HEAD_SMEM>>>(src, t, t + 1);
        mma_gemm_sm <<<dim3(8, 16, 2), 256, GEMM_SMEM>>>(1, 0);
        fused_update<<<dim3(2048, 2), 256, HEAD_SMEM>>>(src, t, t + 1);
        mma_gemm<0> <<<dim3(16, 16), 256, GEMM_SMEM>>>(2048);
    }

    // epilogue: layer1 @ t=TT-1
    fused_gate  <<<dim3(4096, 1), 256, HEAD_SMEM>>>(src, TT - 1, -1);
    mma_gemm_sm <<<dim3(8, 16, 1), 256, GEMM_SMEM>>>(1, 1);
    fused_update<<<dim3(2048, 1), 256, HEAD_SMEM>>>(src, TT - 1, -1);

    out_kernel<<<(NB * HR * NN + 255) / 256, 256>>>(cw, cb, out);
}

// round 14
// speedup vs baseline: 1.1635x; 1.0015x over previous
#include <cuda_runtime.h>
#include <cuda_bf16.h>
#include <math.h>
#include <stdint.h>

#define NB 16
#define TT 12
#define NN 2048
#define HD 64
#define HR 12

// ---------------- scratch ----------------
__device__ __nv_bfloat16 g_Shi[(size_t)NN * NN];
__device__ __nv_bfloat16 g_Slo[(size_t)NN * NN];
// MN-major packs: [m][j]
__device__ __nv_bfloat16 g_Ybhi[(size_t)NN * 2048];    // big: [m][0:1024)=state0', [1024:2048)=state1
__device__ __nv_bfloat16 g_Yblo[(size_t)NN * 2048];
__device__ __nv_bfloat16 g_Z0hi[(size_t)NN * 1024];    // z*state layer0
__device__ __nv_bfloat16 g_Z0lo[(size_t)NN * 1024];
__device__ __nv_bfloat16 g_Z1hi[(size_t)NN * 1024];    // z*state layer1
__device__ __nv_bfloat16 g_Z1lo[(size_t)NN * 1024];
__device__ __nv_bfloat16 g_Bxhi[(size_t)NN * 256];     // X pack [m][t*16+b]
__device__ __nv_bfloat16 g_Bxlo[(size_t)NN * 256];
// fragment-order weights: [n][og8][ks][lane][c], c = {bhi_j0, bhi_j1, blo_j0, blo_j1}
__device__ uint32_t g_WFg0[(size_t)NN * 16 * 9 * 128];
__device__ uint32_t g_WFu0[(size_t)NN * 8 * 9 * 128];
__device__ uint32_t g_WFg1[(size_t)NN * 16 * 16 * 128];
__device__ uint32_t g_WFu1[(size_t)NN * 8 * 16 * 128];
__device__ float g_Tsrc[768000];
__device__ float g_bg0[NN * 128];
__device__ float g_bu0[NN * 64];
__device__ float g_bg1[NN * 128];
__device__ float g_bu1[NN * 64];
__device__ float g_state0a[NN * NB * HD];
__device__ float g_state0b[NN * NB * HD];
__device__ float g_state1 [NN * NB * HD];
__device__ float g_SY [(size_t)NN * 2048];
__device__ float g_SXall[(size_t)NN * 192];
__device__ float g_SZS0[NN * NB * HD];
__device__ float g_SZS1[NN * NB * HD];
__device__ float g_ZS0[NN * NB * HD];
__device__ float g_ZS1[NN * NB * HD];
__device__ float g_r0 [NN * NB * HD];
__device__ float g_r1 [NN * NB * HD];

__device__ __forceinline__ float* s0RD(int t) { return (t & 1) ? g_state0b : g_state0a; }
__device__ __forceinline__ float* s0WR(int t) { return (t & 1) ? g_state0a : g_state0b; }

// ================= helpers =================
__device__ __forceinline__ uint32_t smem_u32(const void* p) {
    return (uint32_t)__cvta_generic_to_shared(p);
}
__device__ __forceinline__ void ldsm4(uint32_t* r, uint32_t a) {
    asm volatile("ldmatrix.sync.aligned.m8n8.x4.shared.b16 {%0,%1,%2,%3}, [%4];"
                 : "=r"(r[0]), "=r"(r[1]), "=r"(r[2]), "=r"(r[3]) : "r"(a));
}
__device__ __forceinline__ void ldsm4t(uint32_t* r, uint32_t a) {
    asm volatile("ldmatrix.sync.aligned.m8n8.x4.trans.shared.b16 {%0,%1,%2,%3}, [%4];"
                 : "=r"(r[0]), "=r"(r[1]), "=r"(r[2]), "=r"(r[3]) : "r"(a));
}
__device__ __forceinline__ void mma16816(float* c, const uint32_t* a, uint32_t b0, uint32_t b1) {
    asm volatile("mma.sync.aligned.m16n8k16.row.col.f32.bf16.bf16.f32 "
                 "{%0,%1,%2,%3}, {%4,%5,%6,%7}, {%8,%9}, {%0,%1,%2,%3};"
                 : "+f"(c[0]), "+f"(c[1]), "+f"(c[2]), "+f"(c[3])
                 : "r"(a[0]), "r"(a[1]), "r"(a[2]), "r"(a[3]), "r"(b0), "r"(b1));
}
__device__ __forceinline__ uint32_t swz16(int chunk, int row) {
    return (uint32_t)(((chunk & ~7) | ((chunk ^ row) & 7)) << 4);
}
__device__ __forceinline__ uint32_t bsplit_hi(float a, float b) {
    __nv_bfloat16 h0 = __float2bfloat16(a), h1 = __float2bfloat16(b);
    return (uint32_t)*(unsigned short*)&h0 | ((uint32_t)*(unsigned short*)&h1 << 16);
}
__device__ __forceinline__ uint32_t bsplit_lo(float a, float b) {
    __nv_bfloat16 h0 = __float2bfloat16(a), h1 = __float2bfloat16(b);
    __nv_bfloat16 l0 = __float2bfloat16(a - __bfloat162float(h0));
    __nv_bfloat16 l1 = __float2bfloat16(b - __bfloat162float(h1));
    return (uint32_t)*(unsigned short*)&l0 | ((uint32_t)*(unsigned short*)&l1 << 16);
}

// ---------------- S = softmax(relu(E E^T)) -> bf16 hi/lo ----------------
__global__ __launch_bounds__(256) void build_S(const float* __restrict__ E) {
    __shared__ float row[2048];
    __shared__ float red[8];
    int n = blockIdx.x, tid = threadIdx.x;
    float en[10];
#pragma unroll
    for (int d = 0; d < 10; d++) en[d] = E[n * 10 + d];
    float lmax = 0.f;
    for (int m = tid; m < 2048; m += 256) {
        float dot = 0.f;
#pragma unroll
        for (int d = 0; d < 10; d++) dot = fmaf(en[d], E[m * 10 + d], dot);
        dot = fmaxf(dot, 0.f);
        row[m] = dot;
        lmax = fmaxf(lmax, dot);
    }
#pragma unroll
    for (int o = 16; o; o >>= 1) lmax = fmaxf(lmax, __shfl_xor_sync(0xffffffffu, lmax, o));
    if ((tid & 31) == 0) red[tid >> 5] = lmax;
    __syncthreads();
    float mx = fmaxf(fmaxf(fmaxf(red[0], red[1]), fmaxf(red[2], red[3])),
                     fmaxf(fmaxf(red[4], red[5]), fmaxf(red[6], red[7])));
    __syncthreads();
    float lsum = 0.f;
    for (int m = tid; m < 2048; m += 256) {
        float e = expf(row[m] - mx);
        row[m] = e;
        lsum += e;
    }
#pragma unroll
    for (int o = 16; o; o >>= 1) lsum += __shfl_xor_sync(0xffffffffu, lsum, o);
    if ((tid & 31) == 0) red[tid >> 5] = lsum;
    __syncthreads();
    float inv = 1.f / (red[0] + red[1] + red[2] + red[3] + red[4] + red[5] + red[6] + red[7]);
    for (int m = tid; m < 2048; m += 256) {
        float v = row[m] * inv;
        __nv_bfloat16 h = __float2bfloat16(v);
        g_Shi[(size_t)n * 2048 + m] = h;
        g_Slo[(size_t)n * 2048 + m] = __float2bfloat16(v - __bfloat162float(h));
    }
}

// ---------------- weight source transpose ----------------
__global__ void transpose_src(const float* __restrict__ Wg0, const float* __restrict__ Wu0,
                              const float* __restrict__ Wg1, const float* __restrict__ Wu1) {
    int idx = blockIdx.x * 256 + threadIdx.x;
    if (idx >= 768000) return;
    const float* W; int off, OUT, K2, K2P;
    if (idx < 184320)      { W = Wg0; off = 0;      OUT = 128; K2 = 130; K2P = 144; }
    else if (idx < 276480) { W = Wu0; off = 184320; OUT = 64;  K2 = 130; K2P = 144; }
    else if (idx < 604160) { W = Wg1; off = 276480; OUT = 128; K2 = 256; K2P = 256; }
    else                   { W = Wu1; off = 604160; OUT = 64;  K2 = 256; K2P = 256; }
    int rem = idx - off;
    int d = rem / (OUT * K2P);
    int r2 = rem % (OUT * K2P);
    int o = r2 / K2P, kp = r2 % K2P;
    g_Tsrc[idx] = (kp < K2) ? W[(size_t)d * K2 * OUT + (size_t)kp * OUT + o] : 0.f;
}

// ---------------- fused expand + fragmentize: Tsrc -> g_WF* directly ----------------
__global__ __launch_bounds__(128) void expand_frag(const float* __restrict__ E) {
    __shared__ float Es[32][10];
    __shared__ float Wc[10][128];
    __shared__ float vbuf[32][128];
    int bx = blockIdx.x, tid = threadIdx.x;
    int nc = bx / 48, wi = bx % 48;
    int OUT, K2P, KST, G, og8; size_t toff; uint32_t* D;
    if (wi < 16)      { og8 = wi;      OUT = 128; K2P = 144; KST = 9;  G = 16; toff = 0;      D = g_WFg0; }
    else if (wi < 24) { og8 = wi - 16; OUT = 64;  K2P = 144; KST = 9;  G = 8;  toff = 184320; D = g_WFu0; }
    else if (wi < 40) { og8 = wi - 24; OUT = 128; K2P = 256; KST = 16; G = 16; toff = 276480; D = g_WFg1; }
    else              { og8 = wi - 40; OUT = 64;  K2P = 256; KST = 16; G = 8;  toff = 604160; D = g_WFu1; }
    for (int s = tid; s < 320; s += 128)
        Es[s / 10][s % 10] = E[(nc * 32 + s / 10) * 10 + s % 10];

    int lane = tid >> 2, c = tid & 3;
    int hlo = c >> 1, j = c & 1;
    int wo = lane >> 2;
    int ridx = wo * 16 + j * 8 + (lane & 3) * 2;

#pragma unroll 1
    for (int ks = 0; ks < KST; ks++) {
        __syncthreads();
        for (int i = tid; i < 1280; i += 128) {
            int d = i >> 7, r = i & 127;
            int o_loc = r >> 4, k16 = r & 15;
            Wc[d][r] = g_Tsrc[toff + ((size_t)d * OUT + og8 * 8 + o_loc) * K2P + ks * 16 + k16];
        }
        __syncthreads();
        {
            int r = tid;
#pragma unroll 1
            for (int n = 0; n < 32; n++) {
                float a = 0.f;
#pragma unroll
                for (int d = 0; d < 10; d++) a = fmaf(Es[n][d], Wc[d][r], a);
                vbuf[n][r] = a;
            }
        }
        __syncthreads();
#pragma unroll 1
        for (int n = 0; n < 32; n++) {
            float v0 = vbuf[n][ridx], v1 = vbuf[n][ridx + 1];
            uint32_t u = hlo ? bsplit_lo(v0, v1) : bsplit_hi(v0, v1);
            D[(((size_t)(nc * 32 + n) * G + og8) * KST + ks) * 128 + tid] = u;
        }
    }
}

// ---------------- bias expansion ----------------
__global__ void expand_bias(const float* __restrict__ E,
                            const float* __restrict__ bg0, const float* __restrict__ bu0,
                            const float* __restrict__ bg1, const float* __restrict__ bu1) {
    int n = blockIdx.x, tid = threadIdx.x;  // 384 threads
    const float* B; float* D; int M, j;
    if (tid < 128)      { B = bg0; D = g_bg0; M = 128; j = tid; }
    else if (tid < 192) { B = bu0; D = g_bu0; M = 64;  j = tid - 128; }
    else if (tid < 320) { B = bg1; D = g_bg1; M = 128; j = tid - 192; }
    else                { B = bu1; D = g_bu1; M = 64;  j = tid - 320; }
    float a = 0.f;
#pragma unroll
    for (int d = 0; d < 10; d++) a = fmaf(E[n * 10 + d], B[d * M + j], a);
    D[n * M + j] = a;
}

__global__ void zero_all() {
    int idx = blockIdx.x * 256 + threadIdx.x;
    if (idx < NN * 2048) {
        g_SY[idx] = 0.f;
        g_Ybhi[idx] = __float2bfloat16(0.f);
        g_Yblo[idx] = __float2bfloat16(0.f);
    }
    if (idx < NN * NB * HD) {
        g_state0a[idx] = 0.f; g_state0b[idx] = 0.f; g_state1[idx] = 0.f;
    }
}

// ---------------- pack_x ----------------
__global__ void pack_x(const float* __restrict__ src) {
    int idx = blockIdx.x * 256 + threadIdx.x;
    if (idx >= NN * 256) return;
    int m = idx >> 8, j = idx & 255;
    float v = 0.f;
    if (j < 192) v = src[(((j & 15) * TT) + (j >> 4)) * NN + m];
    __nv_bfloat16 h = __float2bfloat16(v);
    g_Bxhi[idx] = h;
    g_Bxlo[idx] = __float2bfloat16(v - __bfloat162float(h));
}

// ---------------- big GEMM core: A K-major (S), B MN-major via ldsm.trans ----------------
#define CHUNK_B   128
#define TILE_BYTES  16384
#define STAGE_BYTES (4 * TILE_BYTES)
#define NCH 32

struct GemmCore {
    uint32_t sbase;
    int lane, wr, wc, row0, col0, jrowb;
    const __nv_bfloat16 *Bhi, *Blo;

    __device__ __forceinline__ void load_chunk(int c, int tid) {
        int s = c & 1;
        uint32_t st = sbase + s * STAGE_BYTES;
#pragma unroll
        for (int op = 0; op < 2; op++) {
            const __nv_bfloat16* gp0 = op ? g_Slo : g_Shi;
            const char* g = (const char*)gp0 + (size_t)row0 * 4096 + (size_t)c * CHUNK_B;
            uint32_t sm0 = st + op * TILE_BYTES;
#pragma unroll
            for (int it = 0; it < 4; it++) {
                int seg = it * 256 + tid;
                int r = seg >> 3, c16 = seg & 7;
                uint32_t off = (uint32_t)(r * 128 + c16 * 16);
                uint32_t sw = off ^ ((off >> 3) & 0x70);
                asm volatile("cp.async.cg.shared.global [%0], [%1], 16;"
                             :: "r"(sm0 + sw), "l"(g + (size_t)r * 4096 + c16 * 16));
            }
        }
#pragma unroll
        for (int op = 0; op < 2; op++) {
            const __nv_bfloat16* gp0 = op ? Blo : Bhi;
            const char* g = (const char*)gp0 + ((size_t)(c * 64) * jrowb + col0) * 2;
            uint32_t sm0 = st + 2 * TILE_BYTES + op * TILE_BYTES;
#pragma unroll
            for (int it = 0; it < 4; it++) {
                int seg = it * 256 + tid;
                int r = seg >> 4, c16 = seg & 15;
                uint32_t sw = (uint32_t)(r * 256) + swz16(c16, r);
                asm volatile("cp.async.cg.shared.global [%0], [%1], 16;"
                             :: "r"(sm0 + sw), "l"(g + (size_t)r * jrowb * 2 + c16 * 16));
            }
        }
        asm volatile("cp.async.commit_group;" ::: "memory");
    }

    __device__ __forceinline__ void run(float* __restrict__ Cg, int J, int tid) {
        float acc[2][8][4];
#pragma unroll
        for (int i = 0; i < 2; i++)
#pragma unroll
            for (int j = 0; j < 8; j++)
#pragma unroll
                for (int k = 0; k < 4; k++) acc[i][j][k] = 0.f;

        int l15 = lane & 15, khalf = lane >> 4;
        int rA0 = wr * 32 + l15;
        uint32_t xA = (uint32_t)((rA0 & 7) * 16);
        int rll  = (lane & 7) + ((lane >> 4) << 3);
        int c16b = wc * 8 + ((lane >> 3) & 1);

        uint32_t ah[2][2][4], al[2][2][4];
        uint32_t bh[2][4], bl[2][4];
        uint32_t tAhi = 0, tAlo = 0, tBhi = 0, tBlo = 0;

        auto ldA = [&](int buf, int kk) {
            uint32_t kb = (uint32_t)(kk * 32 + khalf * 16);
            ldsm4(ah[buf][0], tAhi + (uint32_t)(rA0 * 128)        + (kb ^ xA));
            ldsm4(ah[buf][1], tAhi + (uint32_t)((rA0 + 16) * 128) + (kb ^ xA));
            ldsm4(al[buf][0], tAlo + (uint32_t)(rA0 * 128)        + (kb ^ xA));
            ldsm4(al[buf][1], tAlo + (uint32_t)((rA0 + 16) * 128) + (kb ^ xA));
        };
        auto ldB = [&](int buf, int kk, int g) {
            int rB = kk * 16 + rll;
            int c16 = c16b + g * 2;
            uint32_t off = (uint32_t)(rB * 256) + swz16(c16, rB);
            ldsm4t(bh[buf], tBhi + off);
            ldsm4t(bl[buf], tBlo + off);
        };

        load_chunk(0, tid);
        load_chunk(1, tid);

        for (int c = 0; c < NCH; c++) {
            int s = c & 1;
            if (c + 1 < NCH) asm volatile("cp.async.wait_group 1;" ::: "memory");
            else             asm volatile("cp.async.wait_group 0;" ::: "memory");
            __syncthreads();

            tAhi = sbase + s * STAGE_BYTES;
            tAlo = tAhi + TILE_BYTES;
            tBhi = tAhi + 2 * TILE_BYTES;
            tBlo = tAhi + 3 * TILE_BYTES;

            ldA(0, 0);
            ldB(0, 0, 0);
#pragma unroll
            for (int kk = 0; kk < 4; kk++) {
                int ab = kk & 1;
#pragma unroll
                for (int g = 0; g < 4; g++) {
                    int gb = g & 1;
                    if (g < 3) {
                        ldB(gb ^ 1, kk, g + 1);
                    } else if (kk < 3) {
                        ldA(ab ^ 1, kk + 1);
                        ldB(0, kk + 1, 0);
                    }
                    mma16816(acc[0][g * 2 + 0], ah[ab][0], bh[gb][0], bh[gb][2]);
                    mma16816(acc[0][g * 2 + 0], ah[ab][0], bl[gb][0], bl[gb][2]);
                    mma16816(acc[0][g * 2 + 0], al[ab][0], bh[gb][0], bh[gb][2]);
                    mma16816(acc[0][g * 2 + 1], ah[ab][0], bh[gb][1], bh[gb][3]);
                    mma16816(acc[0][g * 2 + 1], ah[ab][0], bl[gb][1], bl[gb][3]);
                    mma16816(acc[0][g * 2 + 1], al[ab][0], bh[gb][1], bh[gb][3]);
                    mma16816(acc[1][g * 2 + 0], ah[ab][1], bh[gb][0], bh[gb][2]);
                    mma16816(acc[1][g * 2 + 0], ah[ab][1], bl[gb][0], bl[gb][2]);
                    mma16816(acc[1][g * 2 + 0], al[ab][1], bh[gb][0], bh[gb][2]);
                    mma16816(acc[1][g * 2 + 1], ah[ab][1], bh[gb][1], bh[gb][3]);
                    mma16816(acc[1][g * 2 + 1], ah[ab][1], bl[gb][1], bl[gb][3]);
                    mma16816(acc[1][g * 2 + 1], al[ab][1], bh[gb][1], bh[gb][3]);
                }
            }
            __syncthreads();
            if (c + 2 < NCH) load_chunk(c + 2, tid);
        }

        int qr = lane >> 2, qc = lane & 3;
#pragma unroll
        for (int mt = 0; mt < 2; mt++) {
#pragma unroll
            for (int nt = 0; nt < 8; nt++) {
                int col = col0 + wc * 64 + nt * 8 + qc * 2;
                if (col < J) {
                    int row = row0 + wr * 32 + mt * 16 + qr;
                    *(float2*)&Cg[(size_t)row * J + col] =
                        make_float2(acc[mt][nt][0], acc[mt][nt][1]);
                    *(float2*)&Cg[(size_t)(row + 8) * J + col] =
                        make_float2(acc[mt][nt][2], acc[mt][nt][3]);
                }
            }
        }
    }
};

template <int WHICH>
__global__ void __launch_bounds__(256, 1) mma_gemm(int J) {
    extern __shared__ __align__(1024) char smem[];
    GemmCore gc;
    int tid = threadIdx.x;
    gc.sbase = smem_u32(smem);
    gc.lane = tid & 31;
    int wid = tid >> 5;
    gc.wr = wid & 3; gc.wc = wid >> 2;
    gc.row0 = blockIdx.y * 128;
    gc.col0 = blockIdx.x * 128;
    if (WHICH == 0) { gc.Bhi = g_Ybhi; gc.Blo = g_Yblo; gc.jrowb = 2048; }
    else            { gc.Bhi = g_Bxhi; gc.Blo = g_Bxlo; gc.jrowb = 256;  }
    gc.run((WHICH == 0) ? g_SY : g_SXall, J, tid);
}

__global__ void __launch_bounds__(256, 1) mma_gemm_sm(int sA, int sB) {
    extern __shared__ __align__(1024) char smem[];
    int set = (blockIdx.z == 0) ? sA : sB;
    GemmCore gc;
    int tid = threadIdx.x;
    gc.sbase = smem_u32(smem);
    gc.lane = tid & 31;
    int wid = tid >> 5;
    gc.wr = wid & 3; gc.wc = wid >> 2;
    gc.row0 = blockIdx.y * 128;
    gc.col0 = blockIdx.x * 128;
    gc.Bhi = set ? g_Z1hi : g_Z0hi;
    gc.Blo = set ? g_Z1lo : g_Z0lo;
    gc.jrowb = 1024;
    gc.run(set ? g_SZS1 : g_SZS0, 1024, tid);
}

// ---------------- tensor-core gate/update heads ----------------
// GATE: one block per node; warp w owns og8=w (z-side) and og8=w+8 (r-side), dual weight streams.
// UPDATE: one block per node, warp w owns og8=w.
// MODE: 0 gate-layer0, 1 gate-layer1, 2 update-layer0, 3 update-layer1
template <int K2P, int MODE>
__device__ __forceinline__ void head_body(const float* __restrict__ src, int tt,
                                          char* smem, int node) {
    constexpr int STRB = (K2P == 256) ? 512 : 384;
    constexpr int KST  = K2P / 16;
    constexpr bool GATE = (MODE == 0 || MODE == 1);
    int tid = threadIdx.x, lane = tid & 31, w = tid >> 5;

    uint32_t sXhi = smem_u32(smem);
    uint32_t sXlo = sXhi + 16u * STRB;

    const uint32_t* WFbase;
    const float* bias;
    if (MODE == 0)      { WFbase = g_WFg0 + (size_t)node * 16 * (size_t)(KST * 128); bias = g_bg0 + node * 128; }
    else if (MODE == 1) { WFbase = g_WFg1 + (size_t)node * 16 * (size_t)(KST * 128); bias = g_bg1 + node * 128; }
    else if (MODE == 2) { WFbase = g_WFu0 + (size_t)node * 8  * (size_t)(KST * 128); bias = g_bu0 + node * 64; }
    else                { WFbase = g_WFu1 + (size_t)node * 8  * (size_t)(KST * 128); bias = g_bu1 + node * 64; }
    const uint4* wpa = (const uint4*)(WFbase + (size_t)w * (KST * 128));
    const uint4* wpb = GATE ? (const uint4*)(WFbase + (size_t)(w + 8) * (KST * 128)) : wpa;

    // early weight prefetch (independent of gather)
    uint4 wa0 = wpa[lane];
    uint4 wa1 = wpa[32 + lane];
    uint4 wb0, wb1;
    if (GATE) { wb0 = wpb[lane]; wb1 = wpb[32 + lane]; }

    const float* srd = (MODE == 0 || MODE == 2) ? s0RD(tt) : (const float*)0;
    const float* swr = (MODE == 1 || MODE == 3) ? s0WR(tt) : (const float*)0;

    // ---- batched X gather ----
    if (K2P == 256) {
        float4 xv[4];
#pragma unroll
        for (int it = 0; it < 4; it++) {
            int v = it * 256 + tid;
            int b = v >> 6, i4 = (v & 63) << 2;
            int seg = i4 >> 6, off = i4 & 63;
            const float* p;
            if (MODE == 1) {
                if      (seg == 0) p = swr      + node * 1024 + b * 64 + off;
                else if (seg == 1) p = g_state1 + node * 1024 + b * 64 + off;
                else if (seg == 2) p = g_SY     + (size_t)node * 2048 + b * 64 + off;
                else               p = g_SY     + (size_t)node * 2048 + 1024 + b * 64 + off;
            } else {
                if      (seg == 0) p = swr      + node * 1024 + b * 64 + off;
                else if (seg == 1) p = g_ZS1    + node * 1024 + b * 64 + off;
                else if (seg == 2) p = g_SY     + (size_t)node * 2048 + b * 64 + off;
                else               p = g_SZS1   + node * 1024 + b * 64 + off;
            }
            xv[it] = *(const float4*)p;
        }
#pragma unroll
        for (int it = 0; it < 4; it++) {
            int v = it * 256 + tid;
            int b = v >> 6, i4 = (v & 63) << 2;
            float4 x = xv[it];
            uint32_t hi0 = bsplit_hi(x.x, x.y), hi1 = bsplit_hi(x.z, x.w);
            uint32_t lo0 = bsplit_lo(x.x, x.y), lo1 = bsplit_lo(x.z, x.w);
            uint32_t boff = (uint32_t)(b * STRB) + swz16(i4 >> 3, b) + (uint32_t)((i4 & 7) * 2);
            asm volatile("st.shared.v2.b32 [%0], {%1,%2};" :: "r"(sXhi + boff), "r"(hi0), "r"(hi1));
            asm volatile("st.shared.v2.b32 [%0], {%1,%2};" :: "r"(sXlo + boff), "r"(lo0), "r"(lo1));
        }
    } else {
        float vals[9];
#pragma unroll
        for (int it = 0; it < 9; it++) {
            int idx = it * 256 + tid;
            int b = idx / 144, i = idx % 144;
            float v = 0.f;
            if (MODE == 0) {
                if (i == 0)       v = src[(b * TT + tt) * NN + node];
                else if (i < 65)  v = srd[node * 1024 + b * 64 + (i - 1)];
                else if (i == 65) v = g_SXall[(size_t)node * 192 + tt * 16 + b];
                else if (i < 130) v = g_SY[(size_t)node * 2048 + b * 64 + (i - 66)];
            } else {
                if (i == 0)       v = src[(b * TT + tt) * NN + node];
                else if (i < 65)  v = g_ZS0[node * 1024 + b * 64 + (i - 1)];
                else if (i == 65) v = g_SXall[(size_t)node * 192 + tt * 16 + b];
                else if (i < 130) v = g_SZS0[node * 1024 + b * 64 + (i - 66)];
            }
            vals[it] = v;
        }
#pragma unroll
        for (int it = 0; it < 9; it++) {
            int idx = it * 256 + tid;
            int b = idx / 144, i = idx % 144;
            float v = vals[it];
            __nv_bfloat16 h = __float2bfloat16(v);
            __nv_bfloat16 l = __float2bfloat16(v - __bfloat162float(h));
            uint32_t boff = (uint32_t)(b * STRB) + swz16(i >> 3, b) + (uint32_t)((i & 7) * 2);
            asm volatile("st.shared.b16 [%0], %1;" :: "r"(sXhi + boff), "h"(*(unsigned short*)&h));
            asm volatile("st.shared.b16 [%0], %1;" :: "r"(sXlo + boff), "h"(*(unsigned short*)&l));
        }
    }
    __syncthreads();

    // ---- compute ----
    float accA[4] = {0.f, 0.f, 0.f, 0.f};
    float accB[4] = {0.f, 0.f, 0.f, 0.f};
    int l15 = lane & 15;
    int rowA = l15;
#pragma unroll
    for (int ks = 0; ks < KST; ks++) {
        uint4 wvA = (ks & 1) ? wa1 : wa0;
        uint4 wvB;
        if (GATE) wvB = (ks & 1) ? wb1 : wb0;
        if (ks + 2 < KST) {
            if (ks & 1) { wa1 = wpa[(ks + 2) * 32 + lane]; if (GATE) wb1 = wpb[(ks + 2) * 32 + lane]; }
            else        { wa0 = wpa[(ks + 2) * 32 + lane]; if (GATE) wb0 = wpb[(ks + 2) * 32 + lane]; }
        }
        int cA = ks * 2 + (lane >> 4);
        uint32_t offA = (uint32_t)(rowA * STRB) + swz16(cA, rowA);
        uint32_t ahi[4], alo[4];
        ldsm4(ahi, sXhi + offA);
        ldsm4(alo, sXlo + offA);
        mma16816(accA, ahi, wvA.x, wvA.y);
        mma16816(accA, alo, wvA.x, wvA.y);
        mma16816(accA, ahi, wvA.z, wvA.w);
        if (GATE) {
            mma16816(accB, ahi, wvB.x, wvB.y);
            mma16816(accB, alo, wvB.x, wvB.y);
            mma16816(accB, ahi, wvB.z, wvB.w);
        }
    }

    int qr = lane >> 2;
    int o = w * 8 + (lane & 3) * 2;
    int base0 = node * 1024 + qr * 64 + o;
    int base1 = base0 + 512;
    int j0 = qr * 64 + o;
    int j1 = (qr + 8) * 64 + o;

    if (GATE) {
        float* ZS = (MODE == 0) ? g_ZS0 : g_ZS1;
        float* R  = (MODE == 0) ? g_r0  : g_r1;
        const float* st = (MODE == 0) ? srd : g_state1;
        float bz0 = bias[o], bz1 = bias[o + 1];
        float br0 = bias[64 + o], br1 = bias[64 + o + 1];
        float s0 = 1.f / (1.f + expf(-(accA[0] + bz0)));
        float s1 = 1.f / (1.f + expf(-(accA[1] + bz1)));
        float s2 = 1.f / (1.f + expf(-(accA[2] + bz0)));
        float s3 = 1.f / (1.f + expf(-(accA[3] + bz1)));
        float z0 = s0 * st[base0],     z1 = s1 * st[base0 + 1];
        float z2 = s2 * st[base1],     z3 = s3 * st[base1 + 1];
        ZS[base0] = z0; ZS[base0 + 1] = z1;
        ZS[base1] = z2; ZS[base1 + 1] = z3;
        __nv_bfloat16* Zh = (MODE == 0) ? g_Z0hi : g_Z1hi;
        __nv_bfloat16* Zl = (MODE == 0) ? g_Z0lo : g_Z1lo;
        *(uint32_t*)&Zh[(size_t)node * 1024 + j0] = bsplit_hi(z0, z1);
        *(uint32_t*)&Zl[(size_t)node * 1024 + j0] = bsplit_lo(z0, z1);
        *(uint32_t*)&Zh[(size_t)node * 1024 + j1] = bsplit_hi(z2, z3);
        *(uint32_t*)&Zl[(size_t)node * 1024 + j1] = bsplit_lo(z2, z3);
        float r0v = 1.f / (1.f + expf(-(accB[0] + br0)));
        float r1v = 1.f / (1.f + expf(-(accB[1] + br1)));
        float r2v = 1.f / (1.f + expf(-(accB[2] + br0)));
        float r3v = 1.f / (1.f + expf(-(accB[3] + br1)));
        R[base0] = r0v; R[base0 + 1] = r1v;
        R[base1] = r2v; R[base1 + 1] = r3v;
    } else {
        const float* R   = (MODE == 2) ? g_r0 : g_r1;
        const float* stR = (MODE == 2) ? srd : g_state1;
        float* stW       = (MODE == 2) ? s0WR(tt) : g_state1;
        float b0 = bias[o], b1 = bias[o + 1];
        float h0 = tanhf(accA[0] + b0);
        float h1 = tanhf(accA[1] + b1);
        float h2 = tanhf(accA[2] + b0);
        float h3 = tanhf(accA[3] + b1);
        float r0v = R[base0],     r1v = R[base0 + 1];
        float r2v = R[base1],     r3v = R[base1 + 1];
        float n0 = r0v * stR[base0]     + (1.f - r0v) * h0;
        float n1 = r1v * stR[base0 + 1] + (1.f - r1v) * h1;
        float n2 = r2v * stR[base1]     + (1.f - r2v) * h2;
        float n3 = r3v * stR[base1 + 1] + (1.f - r3v) * h3;
        stW[base0] = n0; stW[base0 + 1] = n1;
        stW[base1] = n2; stW[base1 + 1] = n3;
        int jb = (MODE == 2) ? 0 : 1024;
        *(uint32_t*)&g_Ybhi[(size_t)node * 2048 + jb + j0] = bsplit_hi(n0, n1);
        *(uint32_t*)&g_Yblo[(size_t)node * 2048 + jb + j0] = bsplit_lo(n0, n1);
        *(uint32_t*)&g_Ybhi[(size_t)node * 2048 + jb + j1] = bsplit_hi(n2, n3);
        *(uint32_t*)&g_Yblo[(size_t)node * 2048 + jb + j1] = bsplit_lo(n2, n3);
    }
}

__global__ __launch_bounds__(256) void fused_gate(const float* __restrict__ src, int t1, int t0) {
    extern __shared__ __align__(128) char smem[];
    int role;
    if (gridDim.y == 2) role = (blockIdx.y == 0) ? 1 : 0;
    else                role = (t1 >= 0) ? 1 : 0;
    if (role) head_body<256, 1>(src, t1, smem, blockIdx.x);
    else      head_body<144, 0>(src, t0, smem, blockIdx.x);
}

__global__ __launch_bounds__(256) void fused_update(const float* __restrict__ src, int t1, int t0) {
    extern __shared__ __align__(128) char smem[];
    int role;
    if (gridDim.y == 2) role = (blockIdx.y == 0) ? 1 : 0;
    else                role = (t1 >= 0) ? 1 : 0;
    if (role) head_body<256, 3>(src, t1, smem, blockIdx.x);
    else      head_body<144, 2>(src, t0, smem, blockIdx.x);
}

// ---------------- output head ----------------
__global__ void out_kernel(const float* __restrict__ cw, const float* __restrict__ cb,
                           float* __restrict__ out) {
    int idx = blockIdx.x * 256 + threadIdx.x;
    if (idx >= NB * HR * NN) return;
    int n = idx & 2047;
    int h = (idx >> 11) % HR;
    int b = idx / (HR * NN);
    float a = cb[h];
#pragma unroll
    for (int c = 0; c < 64; c++)
        a = fmaf(g_state1[n * 1024 + b * 64 + c], cw[h * 64 + c], a);
    out[idx] = a;
}

// ---------------- launcher ----------------
extern "C" void kernel_launch(void* const* d_in, const int* in_sizes, int n_in,
                              void* d_out, int out_size) {
    const float* src = (const float*)d_in[0];
    const float* E   = (const float*)d_in[1];
    const float* Wg0 = (const float*)d_in[2];
    const float* bg0 = (const float*)d_in[3];
    const float* Wu0 = (const float*)d_in[4];
    const float* bu0 = (const float*)d_in[5];
    const float* Wg1 = (const float*)d_in[6];
    const float* bg1 = (const float*)d_in[7];
    const float* Wu1 = (const float*)d_in[8];
    const float* bu1 = (const float*)d_in[9];
    const float* cw  = (const float*)d_in[10];
    const float* cb  = (const float*)d_in[11];
    float* out = (float*)d_out;

    const int GEMM_SMEM = 2 * STAGE_BYTES;   // 128 KB
    const int HEAD_SMEM = 32 * 512;          // 16 KB (X only)
    cudaFuncSetAttribute(mma_gemm<0>,  cudaFuncAttributeMaxDynamicSharedMemorySize, GEMM_SMEM);
    cudaFuncSetAttribute(mma_gemm<2>,  cudaFuncAttributeMaxDynamicSharedMemorySize, GEMM_SMEM);
    cudaFuncSetAttribute(mma_gemm_sm,  cudaFuncAttributeMaxDynamicSharedMemorySize, GEMM_SMEM);
    cudaFuncSetAttribute(fused_gate,   cudaFuncAttributeMaxDynamicSharedMemorySize, HEAD_SMEM);
    cudaFuncSetAttribute(fused_update, cudaFuncAttributeMaxDynamicSharedMemorySize, HEAD_SMEM);

    // launches 1..4: #4 is a small THROWAWAY fused_gate for ncu profiling.
    build_S<<<NN, 256>>>(E);                                           // 1
    zero_all<<<(NN * 2048 + 255) / 256, 256>>>();                      // 2
    pack_x<<<(NN * 256 + 255) / 256, 256>>>(src);                      // 3
    fused_gate<<<dim3(1024, 2), 256, HEAD_SMEM>>>(src, 0, 1);          // 4 <- PROFILED (throwaway)

    mma_gemm<2><<<dim3(2, 16), 256, GEMM_SMEM>>>(192);                 // S@X all steps
    transpose_src<<<3000, 256>>>(Wg0, Wu0, Wg1, Wu1);
    expand_frag<<<3072, 128>>>(E);
    expand_bias<<<NN, 384>>>(E, bg0, bu0, bg1, bu1);

    // prologue: layer0 @ t=0
    fused_gate  <<<dim3(2048, 1), 256, HEAD_SMEM>>>(src, -1, 0);
    mma_gemm_sm <<<dim3(8, 16, 1), 256, GEMM_SMEM>>>(0, 0);
    fused_update<<<dim3(2048, 1), 256, HEAD_SMEM>>>(src, -1, 0);
    mma_gemm<0> <<<dim3(16, 16), 256, GEMM_SMEM>>>(2048);

    // steady state: layer1(t) || layer0(t+1)
    for (int t = 0; t + 1 < TT; t++) {
        fused_gate  <<<dim3(2048, 2), 256, HEAD_SMEM>>>(src, t, t + 1);
        mma_gemm_sm <<<dim3(8, 16, 2), 256, GEMM_SMEM>>>(1, 0);
        fused_update<<<dim3(2048, 2), 256, HEAD_SMEM>>>(src, t, t + 1);
        mma_gemm<0> <<<dim3(16, 16), 256, GEMM_SMEM>>>(2048);
    }

    // epilogue: layer1 @ t=TT-1
    fused_gate  <<<dim3(2048, 1), 256, HEAD_SMEM>>>(src, TT - 1, -1);
    mma_gemm_sm <<<dim3(8, 16, 1), 256, GEMM_SMEM>>>(1, 1);
    fused_update<<<dim3(2048, 1), 256, HEAD_SMEM>>>(src, TT - 1, -1);

    out_kernel<<<(NB * HR * NN + 255) / 256, 256>>>(cw, cb, out);
}

// round 15
// speedup vs baseline: 1.1699x; 1.0055x over previous
#include <cuda_runtime.h>
#include <cuda_bf16.h>
#include <math.h>
#include <stdint.h>

#define NB 16
#define TT 12
#define NN 2048
#define HD 64
#define HR 12

// ---------------- scratch ----------------
__device__ __nv_bfloat16 g_Shi[(size_t)NN * NN];
__device__ __nv_bfloat16 g_Slo[(size_t)NN * NN];
// MN-major packs: [m][j]
__device__ __nv_bfloat16 g_Ybhi[(size_t)NN * 2048];
__device__ __nv_bfloat16 g_Yblo[(size_t)NN * 2048];
__device__ __nv_bfloat16 g_Z0hi[(size_t)NN * 1024];
__device__ __nv_bfloat16 g_Z0lo[(size_t)NN * 1024];
__device__ __nv_bfloat16 g_Z1hi[(size_t)NN * 1024];
__device__ __nv_bfloat16 g_Z1lo[(size_t)NN * 1024];
__device__ __nv_bfloat16 g_Bxhi[(size_t)NN * 256];
__device__ __nv_bfloat16 g_Bxlo[(size_t)NN * 256];
// fragment-order weights
__device__ uint32_t g_WFg0[(size_t)NN * 16 * 9 * 128];
__device__ uint32_t g_WFu0[(size_t)NN * 8 * 9 * 128];
__device__ uint32_t g_WFg1[(size_t)NN * 16 * 16 * 128];
__device__ uint32_t g_WFu1[(size_t)NN * 8 * 16 * 128];
__device__ float g_Tsrc[768000];
__device__ float g_bg0[NN * 128];
__device__ float g_bu0[NN * 64];
__device__ float g_bg1[NN * 128];
__device__ float g_bu1[NN * 64];
__device__ float g_state0a[NN * NB * HD];
__device__ float g_state0b[NN * NB * HD];
__device__ float g_state1 [NN * NB * HD];
__device__ float g_SY [(size_t)NN * 2048];
__device__ float g_SXall[(size_t)NN * 192];
__device__ float g_SZS0[NN * NB * HD];
__device__ float g_SZS1[NN * NB * HD];
__device__ float g_ZS0[NN * NB * HD];
__device__ float g_ZS1[NN * NB * HD];
__device__ float g_r0 [NN * NB * HD];
__device__ float g_r1 [NN * NB * HD];

__device__ __forceinline__ float* s0RD(int t) { return (t & 1) ? g_state0b : g_state0a; }
__device__ __forceinline__ float* s0WR(int t) { return (t & 1) ? g_state0a : g_state0b; }

// ================= helpers =================
__device__ __forceinline__ uint32_t smem_u32(const void* p) {
    return (uint32_t)__cvta_generic_to_shared(p);
}
__device__ __forceinline__ void ldsm4(uint32_t* r, uint32_t a) {
    asm volatile("ldmatrix.sync.aligned.m8n8.x4.shared.b16 {%0,%1,%2,%3}, [%4];"
                 : "=r"(r[0]), "=r"(r[1]), "=r"(r[2]), "=r"(r[3]) : "r"(a));
}
__device__ __forceinline__ void ldsm4t(uint32_t* r, uint32_t a) {
    asm volatile("ldmatrix.sync.aligned.m8n8.x4.trans.shared.b16 {%0,%1,%2,%3}, [%4];"
                 : "=r"(r[0]), "=r"(r[1]), "=r"(r[2]), "=r"(r[3]) : "r"(a));
}
__device__ __forceinline__ void mma16816(float* c, const uint32_t* a, uint32_t b0, uint32_t b1) {
    asm volatile("mma.sync.aligned.m16n8k16.row.col.f32.bf16.bf16.f32 "
                 "{%0,%1,%2,%3}, {%4,%5,%6,%7}, {%8,%9}, {%0,%1,%2,%3};"
                 : "+f"(c[0]), "+f"(c[1]), "+f"(c[2]), "+f"(c[3])
                 : "r"(a[0]), "r"(a[1]), "r"(a[2]), "r"(a[3]), "r"(b0), "r"(b1));
}
__device__ __forceinline__ uint32_t swz16(int chunk, int row) {
    return (uint32_t)(((chunk & ~7) | ((chunk ^ row) & 7)) << 4);
}
__device__ __forceinline__ uint32_t bsplit_hi(float a, float b) {
    __nv_bfloat16 h0 = __float2bfloat16(a), h1 = __float2bfloat16(b);
    return (uint32_t)*(unsigned short*)&h0 | ((uint32_t)*(unsigned short*)&h1 << 16);
}
__device__ __forceinline__ uint32_t bsplit_lo(float a, float b) {
    __nv_bfloat16 h0 = __float2bfloat16(a), h1 = __float2bfloat16(b);
    __nv_bfloat16 l0 = __float2bfloat16(a - __bfloat162float(h0));
    __nv_bfloat16 l1 = __float2bfloat16(b - __bfloat162float(h1));
    return (uint32_t)*(unsigned short*)&l0 | ((uint32_t)*(unsigned short*)&l1 << 16);
}

// ---------------- S = softmax(relu(E E^T)) -> bf16 hi/lo ----------------
__global__ __launch_bounds__(256) void build_S(const float* __restrict__ E) {
    __shared__ float row[2048];
    __shared__ float red[8];
    int n = blockIdx.x, tid = threadIdx.x;
    float en[10];
#pragma unroll
    for (int d = 0; d < 10; d++) en[d] = E[n * 10 + d];
    float lmax = 0.f;
    for (int m = tid; m < 2048; m += 256) {
        float dot = 0.f;
#pragma unroll
        for (int d = 0; d < 10; d++) dot = fmaf(en[d], E[m * 10 + d], dot);
        dot = fmaxf(dot, 0.f);
        row[m] = dot;
        lmax = fmaxf(lmax, dot);
    }
#pragma unroll
    for (int o = 16; o; o >>= 1) lmax = fmaxf(lmax, __shfl_xor_sync(0xffffffffu, lmax, o));
    if ((tid & 31) == 0) red[tid >> 5] = lmax;
    __syncthreads();
    float mx = fmaxf(fmaxf(fmaxf(red[0], red[1]), fmaxf(red[2], red[3])),
                     fmaxf(fmaxf(red[4], red[5]), fmaxf(red[6], red[7])));
    __syncthreads();
    float lsum = 0.f;
    for (int m = tid; m < 2048; m += 256) {
        float e = expf(row[m] - mx);
        row[m] = e;
        lsum += e;
    }
#pragma unroll
    for (int o = 16; o; o >>= 1) lsum += __shfl_xor_sync(0xffffffffu, lsum, o);
    if ((tid & 31) == 0) red[tid >> 5] = lsum;
    __syncthreads();
    float inv = 1.f / (red[0] + red[1] + red[2] + red[3] + red[4] + red[5] + red[6] + red[7]);
    for (int m = tid; m < 2048; m += 256) {
        float v = row[m] * inv;
        __nv_bfloat16 h = __float2bfloat16(v);
        g_Shi[(size_t)n * 2048 + m] = h;
        g_Slo[(size_t)n * 2048 + m] = __float2bfloat16(v - __bfloat162float(h));
    }
}

// ---------------- weight source transpose ----------------
__global__ void transpose_src(const float* __restrict__ Wg0, const float* __restrict__ Wu0,
                              const float* __restrict__ Wg1, const float* __restrict__ Wu1) {
    int idx = blockIdx.x * 256 + threadIdx.x;
    if (idx >= 768000) return;
    const float* W; int off, OUT, K2, K2P;
    if (idx < 184320)      { W = Wg0; off = 0;      OUT = 128; K2 = 130; K2P = 144; }
    else if (idx < 276480) { W = Wu0; off = 184320; OUT = 64;  K2 = 130; K2P = 144; }
    else if (idx < 604160) { W = Wg1; off = 276480; OUT = 128; K2 = 256; K2P = 256; }
    else                   { W = Wu1; off = 604160; OUT = 64;  K2 = 256; K2P = 256; }
    int rem = idx - off;
    int d = rem / (OUT * K2P);
    int r2 = rem % (OUT * K2P);
    int o = r2 / K2P, kp = r2 % K2P;
    g_Tsrc[idx] = (kp < K2) ? W[(size_t)d * K2 * OUT + (size_t)kp * OUT + o] : 0.f;
}

// ---------------- fused expand + fragmentize ----------------
__global__ __launch_bounds__(128) void expand_frag(const float* __restrict__ E) {
    __shared__ float Es[32][10];
    __shared__ float Wc[10][128];
    __shared__ float vbuf[32][128];
    int bx = blockIdx.x, tid = threadIdx.x;
    int nc = bx / 48, wi = bx % 48;
    int OUT, K2P, KST, G, og8; size_t toff; uint32_t* D;
    if (wi < 16)      { og8 = wi;      OUT = 128; K2P = 144; KST = 9;  G = 16; toff = 0;      D = g_WFg0; }
    else if (wi < 24) { og8 = wi - 16; OUT = 64;  K2P = 144; KST = 9;  G = 8;  toff = 184320; D = g_WFu0; }
    else if (wi < 40) { og8 = wi - 24; OUT = 128; K2P = 256; KST = 16; G = 16; toff = 276480; D = g_WFg1; }
    else              { og8 = wi - 40; OUT = 64;  K2P = 256; KST = 16; G = 8;  toff = 604160; D = g_WFu1; }
    for (int s = tid; s < 320; s += 128)
        Es[s / 10][s % 10] = E[(nc * 32 + s / 10) * 10 + s % 10];

    int lane = tid >> 2, c = tid & 3;
    int hlo = c >> 1, j = c & 1;
    int wo = lane >> 2;
    int ridx = wo * 16 + j * 8 + (lane & 3) * 2;

#pragma unroll 1
    for (int ks = 0; ks < KST; ks++) {
        __syncthreads();
        for (int i = tid; i < 1280; i += 128) {
            int d = i >> 7, r = i & 127;
            int o_loc = r >> 4, k16 = r & 15;
            Wc[d][r] = g_Tsrc[toff + ((size_t)d * OUT + og8 * 8 + o_loc) * K2P + ks * 16 + k16];
        }
        __syncthreads();
        {
            int r = tid;
#pragma unroll 1
            for (int n = 0; n < 32; n++) {
                float a = 0.f;
#pragma unroll
                for (int d = 0; d < 10; d++) a = fmaf(Es[n][d], Wc[d][r], a);
                vbuf[n][r] = a;
            }
        }
        __syncthreads();
#pragma unroll 1
        for (int n = 0; n < 32; n++) {
            float v0 = vbuf[n][ridx], v1 = vbuf[n][ridx + 1];
            uint32_t u = hlo ? bsplit_lo(v0, v1) : bsplit_hi(v0, v1);
            D[(((size_t)(nc * 32 + n) * G + og8) * KST + ks) * 128 + tid] = u;
        }
    }
}

// ---------------- bias expansion ----------------
__global__ void expand_bias(const float* __restrict__ E,
                            const float* __restrict__ bg0, const float* __restrict__ bu0,
                            const float* __restrict__ bg1, const float* __restrict__ bu1) {
    int n = blockIdx.x, tid = threadIdx.x;  // 384 threads
    const float* B; float* D; int M, j;
    if (tid < 128)      { B = bg0; D = g_bg0; M = 128; j = tid; }
    else if (tid < 192) { B = bu0; D = g_bu0; M = 64;  j = tid - 128; }
    else if (tid < 320) { B = bg1; D = g_bg1; M = 128; j = tid - 192; }
    else                { B = bu1; D = g_bu1; M = 64;  j = tid - 320; }
    float a = 0.f;
#pragma unroll
    for (int d = 0; d < 10; d++) a = fmaf(E[n * 10 + d], B[d * M + j], a);
    D[n * M + j] = a;
}

__global__ void zero_all() {
    int idx = blockIdx.x * 256 + threadIdx.x;
    if (idx < NN * 2048) {
        g_SY[idx] = 0.f;
        g_Ybhi[idx] = __float2bfloat16(0.f);
        g_Yblo[idx] = __float2bfloat16(0.f);
    }
    if (idx < NN * NB * HD) {
        g_state0a[idx] = 0.f; g_state0b[idx] = 0.f; g_state1[idx] = 0.f;
    }
}

// ---------------- pack_x ----------------
__global__ void pack_x(const float* __restrict__ src) {
    int idx = blockIdx.x * 256 + threadIdx.x;
    if (idx >= NN * 256) return;
    int m = idx >> 8, j = idx & 255;
    float v = 0.f;
    if (j < 192) v = src[(((j & 15) * TT) + (j >> 4)) * NN + m];
    __nv_bfloat16 h = __float2bfloat16(v);
    g_Bxhi[idx] = h;
    g_Bxlo[idx] = __float2bfloat16(v - __bfloat162float(h));
}

// ---------------- big GEMM core ----------------
#define CHUNK_B   128
#define TILE_BYTES  16384
#define STAGE_BYTES (4 * TILE_BYTES)
#define NCH 32

struct GemmCore {
    uint32_t sbase;
    int lane, wr, wc, row0, col0, jrowb;
    const __nv_bfloat16 *Bhi, *Blo;

    __device__ __forceinline__ void load_chunk(int c, int tid) {
        int s = c & 1;
        uint32_t st = sbase + s * STAGE_BYTES;
#pragma unroll
        for (int op = 0; op < 2; op++) {
            const __nv_bfloat16* gp0 = op ? g_Slo : g_Shi;
            const char* g = (const char*)gp0 + (size_t)row0 * 4096 + (size_t)c * CHUNK_B;
            uint32_t sm0 = st + op * TILE_BYTES;
#pragma unroll
            for (int it = 0; it < 4; it++) {
                int seg = it * 256 + tid;
                int r = seg >> 3, c16 = seg & 7;
                uint32_t off = (uint32_t)(r * 128 + c16 * 16);
                uint32_t sw = off ^ ((off >> 3) & 0x70);
                asm volatile("cp.async.cg.shared.global [%0], [%1], 16;"
                             :: "r"(sm0 + sw), "l"(g + (size_t)r * 4096 + c16 * 16));
            }
        }
#pragma unroll
        for (int op = 0; op < 2; op++) {
            const __nv_bfloat16* gp0 = op ? Blo : Bhi;
            const char* g = (const char*)gp0 + ((size_t)(c * 64) * jrowb + col0) * 2;
            uint32_t sm0 = st + 2 * TILE_BYTES + op * TILE_BYTES;
#pragma unroll
            for (int it = 0; it < 4; it++) {
                int seg = it * 256 + tid;
                int r = seg >> 4, c16 = seg & 15;
                uint32_t sw = (uint32_t)(r * 256) + swz16(c16, r);
                asm volatile("cp.async.cg.shared.global [%0], [%1], 16;"
                             :: "r"(sm0 + sw), "l"(g + (size_t)r * jrowb * 2 + c16 * 16));
            }
        }
        asm volatile("cp.async.commit_group;" ::: "memory");
    }

    __device__ __forceinline__ void run(float* __restrict__ Cg, int J, int tid) {
        float acc[2][8][4];
#pragma unroll
        for (int i = 0; i < 2; i++)
#pragma unroll
            for (int j = 0; j < 8; j++)
#pragma unroll
                for (int k = 0; k < 4; k++) acc[i][j][k] = 0.f;

        int l15 = lane & 15, khalf = lane >> 4;
        int rA0 = wr * 32 + l15;
        uint32_t xA = (uint32_t)((rA0 & 7) * 16);
        int rll  = (lane & 7) + ((lane >> 4) << 3);
        int c16b = wc * 8 + ((lane >> 3) & 1);

        uint32_t ah[2][2][4], al[2][2][4];
        uint32_t bh[2][4], bl[2][4];
        uint32_t tAhi = 0, tAlo = 0, tBhi = 0, tBlo = 0;

        auto ldA = [&](int buf, int kk) {
            uint32_t kb = (uint32_t)(kk * 32 + khalf * 16);
            ldsm4(ah[buf][0], tAhi + (uint32_t)(rA0 * 128)        + (kb ^ xA));
            ldsm4(ah[buf][1], tAhi + (uint32_t)((rA0 + 16) * 128) + (kb ^ xA));
            ldsm4(al[buf][0], tAlo + (uint32_t)(rA0 * 128)        + (kb ^ xA));
            ldsm4(al[buf][1], tAlo + (uint32_t)((rA0 + 16) * 128) + (kb ^ xA));
        };
        auto ldB = [&](int buf, int kk, int g) {
            int rB = kk * 16 + rll;
            int c16 = c16b + g * 2;
            uint32_t off = (uint32_t)(rB * 256) + swz16(c16, rB);
            ldsm4t(bh[buf], tBhi + off);
            ldsm4t(bl[buf], tBlo + off);
        };

        load_chunk(0, tid);
        load_chunk(1, tid);

        for (int c = 0; c < NCH; c++) {
            int s = c & 1;
            if (c + 1 < NCH) asm volatile("cp.async.wait_group 1;" ::: "memory");
            else             asm volatile("cp.async.wait_group 0;" ::: "memory");
            __syncthreads();

            tAhi = sbase + s * STAGE_BYTES;
            tAlo = tAhi + TILE_BYTES;
            tBhi = tAhi + 2 * TILE_BYTES;
            tBlo = tAhi + 3 * TILE_BYTES;

            ldA(0, 0);
            ldB(0, 0, 0);
#pragma unroll
            for (int kk = 0; kk < 4; kk++) {
                int ab = kk & 1;
#pragma unroll
                for (int g = 0; g < 4; g++) {
                    int gb = g & 1;
                    if (g < 3) {
                        ldB(gb ^ 1, kk, g + 1);
                    } else if (kk < 3) {
                        ldA(ab ^ 1, kk + 1);
                        ldB(0, kk + 1, 0);
                    }
                    mma16816(acc[0][g * 2 + 0], ah[ab][0], bh[gb][0], bh[gb][2]);
                    mma16816(acc[0][g * 2 + 0], ah[ab][0], bl[gb][0], bl[gb][2]);
                    mma16816(acc[0][g * 2 + 0], al[ab][0], bh[gb][0], bh[gb][2]);
                    mma16816(acc[0][g * 2 + 1], ah[ab][0], bh[gb][1], bh[gb][3]);
                    mma16816(acc[0][g * 2 + 1], ah[ab][0], bl[gb][1], bl[gb][3]);
                    mma16816(acc[0][g * 2 + 1], al[ab][0], bh[gb][1], bh[gb][3]);
                    mma16816(acc[1][g * 2 + 0], ah[ab][1], bh[gb][0], bh[gb][2]);
                    mma16816(acc[1][g * 2 + 0], ah[ab][1], bl[gb][0], bl[gb][2]);
                    mma16816(acc[1][g * 2 + 0], al[ab][1], bh[gb][0], bh[gb][2]);
                    mma16816(acc[1][g * 2 + 1], ah[ab][1], bh[gb][1], bh[gb][3]);
                    mma16816(acc[1][g * 2 + 1], ah[ab][1], bl[gb][1], bl[gb][3]);
                    mma16816(acc[1][g * 2 + 1], al[ab][1], bh[gb][1], bh[gb][3]);
                }
            }
            __syncthreads();
            if (c + 2 < NCH) load_chunk(c + 2, tid);
        }

        int qr = lane >> 2, qc = lane & 3;
#pragma unroll
        for (int mt = 0; mt < 2; mt++) {
#pragma unroll
            for (int nt = 0; nt < 8; nt++) {
                int col = col0 + wc * 64 + nt * 8 + qc * 2;
                if (col < J) {
                    int row = row0 + wr * 32 + mt * 16 + qr;
                    *(float2*)&Cg[(size_t)row * J + col] =
                        make_float2(acc[mt][nt][0], acc[mt][nt][1]);
                    *(float2*)&Cg[(size_t)(row + 8) * J + col] =
                        make_float2(acc[mt][nt][2], acc[mt][nt][3]);
                }
            }
        }
    }
};

template <int WHICH>
__global__ void __launch_bounds__(256, 1) mma_gemm(int J) {
    extern __shared__ __align__(1024) char smem[];
    GemmCore gc;
    int tid = threadIdx.x;
    gc.sbase = smem_u32(smem);
    gc.lane = tid & 31;
    int wid = tid >> 5;
    gc.wr = wid & 3; gc.wc = wid >> 2;
    gc.row0 = blockIdx.y * 128;
    gc.col0 = blockIdx.x * 128;
    if (WHICH == 0) { gc.Bhi = g_Ybhi; gc.Blo = g_Yblo; gc.jrowb = 2048; }
    else            { gc.Bhi = g_Bxhi; gc.Blo = g_Bxlo; gc.jrowb = 256;  }
    gc.run((WHICH == 0) ? g_SY : g_SXall, J, tid);
}

__global__ void __launch_bounds__(256, 1) mma_gemm_sm(int sA, int sB) {
    extern __shared__ __align__(1024) char smem[];
    int set = (blockIdx.z == 0) ? sA : sB;
    GemmCore gc;
    int tid = threadIdx.x;
    gc.sbase = smem_u32(smem);
    gc.lane = tid & 31;
    int wid = tid >> 5;
    gc.wr = wid & 3; gc.wc = wid >> 2;
    gc.row0 = blockIdx.y * 128;
    gc.col0 = blockIdx.x * 128;
    gc.Bhi = set ? g_Z1hi : g_Z0hi;
    gc.Blo = set ? g_Z1lo : g_Z0lo;
    gc.jrowb = 1024;
    gc.run(set ? g_SZS1 : g_SZS0, 1024, tid);
}

// ---------------- GATE head (256 thr, 8 warps, dual streams per warp) ----------------
// MODE: 0 gate-layer0, 1 gate-layer1
template <int K2P, int MODE>
__device__ __forceinline__ void gate_body(const float* __restrict__ src, int tt,
                                          char* smem, int node) {
    constexpr int STRB = (K2P == 256) ? 512 : 384;
    constexpr int KST  = K2P / 16;
    int tid = threadIdx.x, lane = tid & 31, w = tid >> 5;

    uint32_t sXhi = smem_u32(smem);
    uint32_t sXlo = sXhi + 16u * STRB;

    const uint32_t* WFbase;
    const float* bias;
    if (MODE == 0) { WFbase = g_WFg0 + (size_t)node * 16 * (size_t)(KST * 128); bias = g_bg0 + node * 128; }
    else           { WFbase = g_WFg1 + (size_t)node * 16 * (size_t)(KST * 128); bias = g_bg1 + node * 128; }
    const uint4* wpa = (const uint4*)(WFbase + (size_t)w * (KST * 128));
    const uint4* wpb = (const uint4*)(WFbase + (size_t)(w + 8) * (KST * 128));

    uint4 wa0 = wpa[lane];
    uint4 wa1 = wpa[32 + lane];
    uint4 wb0 = wpb[lane];
    uint4 wb1 = wpb[32 + lane];

    const float* srd = (MODE == 0) ? s0RD(tt) : (const float*)0;
    const float* swr = (MODE == 1) ? s0WR(tt) : (const float*)0;

    if (K2P == 256) {
        float4 xv[4];
#pragma unroll
        for (int it = 0; it < 4; it++) {
            int v = it * 256 + tid;
            int b = v >> 6, i4 = (v & 63) << 2;
            int seg = i4 >> 6, off = i4 & 63;
            const float* p;
            if      (seg == 0) p = swr      + node * 1024 + b * 64 + off;
            else if (seg == 1) p = g_state1 + node * 1024 + b * 64 + off;
            else if (seg == 2) p = g_SY     + (size_t)node * 2048 + b * 64 + off;
            else               p = g_SY     + (size_t)node * 2048 + 1024 + b * 64 + off;
            xv[it] = *(const float4*)p;
        }
#pragma unroll
        for (int it = 0; it < 4; it++) {
            int v = it * 256 + tid;
            int b = v >> 6, i4 = (v & 63) << 2;
            float4 x = xv[it];
            uint32_t hi0 = bsplit_hi(x.x, x.y), hi1 = bsplit_hi(x.z, x.w);
            uint32_t lo0 = bsplit_lo(x.x, x.y), lo1 = bsplit_lo(x.z, x.w);
            uint32_t boff = (uint32_t)(b * STRB) + swz16(i4 >> 3, b) + (uint32_t)((i4 & 7) * 2);
            asm volatile("st.shared.v2.b32 [%0], {%1,%2};" :: "r"(sXhi + boff), "r"(hi0), "r"(hi1));
            asm volatile("st.shared.v2.b32 [%0], {%1,%2};" :: "r"(sXlo + boff), "r"(lo0), "r"(lo1));
        }
    } else {
        float vals[9];
#pragma unroll
        for (int it = 0; it < 9; it++) {
            int idx = it * 256 + tid;
            int b = idx / 144, i = idx % 144;
            float v = 0.f;
            if (i == 0)       v = src[(b * TT + tt) * NN + node];
            else if (i < 65)  v = srd[node * 1024 + b * 64 + (i - 1)];
            else if (i == 65) v = g_SXall[(size_t)node * 192 + tt * 16 + b];
            else if (i < 130) v = g_SY[(size_t)node * 2048 + b * 64 + (i - 66)];
            vals[it] = v;
        }
#pragma unroll
        for (int it = 0; it < 9; it++) {
            int idx = it * 256 + tid;
            int b = idx / 144, i = idx % 144;
            float v = vals[it];
            __nv_bfloat16 h = __float2bfloat16(v);
            __nv_bfloat16 l = __float2bfloat16(v - __bfloat162float(h));
            uint32_t boff = (uint32_t)(b * STRB) + swz16(i >> 3, b) + (uint32_t)((i & 7) * 2);
            asm volatile("st.shared.b16 [%0], %1;" :: "r"(sXhi + boff), "h"(*(unsigned short*)&h));
            asm volatile("st.shared.b16 [%0], %1;" :: "r"(sXlo + boff), "h"(*(unsigned short*)&l));
        }
    }
    __syncthreads();

    float accA[4] = {0.f, 0.f, 0.f, 0.f};
    float accB[4] = {0.f, 0.f, 0.f, 0.f};
    int l15 = lane & 15;
#pragma unroll
    for (int ks = 0; ks < KST; ks++) {
        uint4 wvA = (ks & 1) ? wa1 : wa0;
        uint4 wvB = (ks & 1) ? wb1 : wb0;
        if (ks + 2 < KST) {
            if (ks & 1) { wa1 = wpa[(ks + 2) * 32 + lane]; wb1 = wpb[(ks + 2) * 32 + lane]; }
            else        { wa0 = wpa[(ks + 2) * 32 + lane]; wb0 = wpb[(ks + 2) * 32 + lane]; }
        }
        int cA = ks * 2 + (lane >> 4);
        uint32_t offA = (uint32_t)(l15 * STRB) + swz16(cA, l15);
        uint32_t ahi[4], alo[4];
        ldsm4(ahi, sXhi + offA);
        ldsm4(alo, sXlo + offA);
        mma16816(accA, ahi, wvA.x, wvA.y);
        mma16816(accA, alo, wvA.x, wvA.y);
        mma16816(accA, ahi, wvA.z, wvA.w);
        mma16816(accB, ahi, wvB.x, wvB.y);
        mma16816(accB, alo, wvB.x, wvB.y);
        mma16816(accB, ahi, wvB.z, wvB.w);
    }

    int qr = lane >> 2;
    int o = w * 8 + (lane & 3) * 2;
    int base0 = node * 1024 + qr * 64 + o;
    int base1 = base0 + 512;
    int j0 = qr * 64 + o;
    int j1 = (qr + 8) * 64 + o;

    float* ZS = (MODE == 0) ? g_ZS0 : g_ZS1;
    float* R  = (MODE == 0) ? g_r0  : g_r1;
    const float* st = (MODE == 0) ? srd : g_state1;
    float bz0 = bias[o], bz1 = bias[o + 1];
    float br0 = bias[64 + o], br1 = bias[64 + o + 1];
    float s0 = 1.f / (1.f + expf(-(accA[0] + bz0)));
    float s1 = 1.f / (1.f + expf(-(accA[1] + bz1)));
    float s2 = 1.f / (1.f + expf(-(accA[2] + bz0)));
    float s3 = 1.f / (1.f + expf(-(accA[3] + bz1)));
    float z0 = s0 * st[base0],     z1 = s1 * st[base0 + 1];
    float z2 = s2 * st[base1],     z3 = s3 * st[base1 + 1];
    ZS[base0] = z0; ZS[base0 + 1] = z1;
    ZS[base1] = z2; ZS[base1 + 1] = z3;
    __nv_bfloat16* Zh = (MODE == 0) ? g_Z0hi : g_Z1hi;
    __nv_bfloat16* Zl = (MODE == 0) ? g_Z0lo : g_Z1lo;
    *(uint32_t*)&Zh[(size_t)node * 1024 + j0] = bsplit_hi(z0, z1);
    *(uint32_t*)&Zl[(size_t)node * 1024 + j0] = bsplit_lo(z0, z1);
    *(uint32_t*)&Zh[(size_t)node * 1024 + j1] = bsplit_hi(z2, z3);
    *(uint32_t*)&Zl[(size_t)node * 1024 + j1] = bsplit_lo(z2, z3);
    float r0v = 1.f / (1.f + expf(-(accB[0] + br0)));
    float r1v = 1.f / (1.f + expf(-(accB[1] + br1)));
    float r2v = 1.f / (1.f + expf(-(accB[2] + br0)));
    float r3v = 1.f / (1.f + expf(-(accB[3] + br1)));
    R[base0] = r0v; R[base0 + 1] = r1v;
    R[base1] = r2v; R[base1 + 1] = r3v;
}

// ---------------- UPDATE head (128 thr, 4 warps, dual og8 streams per warp) ----------------
// MODE: 2 update-layer0, 3 update-layer1
template <int K2P, int MODE>
__device__ __forceinline__ void update_body(const float* __restrict__ src, int tt,
                                            char* smem, int node) {
    constexpr int STRB = (K2P == 256) ? 512 : 384;
    constexpr int KST  = K2P / 16;
    int tid = threadIdx.x, lane = tid & 31, w = tid >> 5;   // 4 warps

    uint32_t sXhi = smem_u32(smem);
    uint32_t sXlo = sXhi + 16u * STRB;

    const uint32_t* WFbase;
    const float* bias;
    if (MODE == 2) { WFbase = g_WFu0 + (size_t)node * 8 * (size_t)(KST * 128); bias = g_bu0 + node * 64; }
    else           { WFbase = g_WFu1 + (size_t)node * 8 * (size_t)(KST * 128); bias = g_bu1 + node * 64; }
    const uint4* wpa = (const uint4*)(WFbase + (size_t)w * (KST * 128));
    const uint4* wpb = (const uint4*)(WFbase + (size_t)(w + 4) * (KST * 128));

    uint4 wa0 = wpa[lane];
    uint4 wa1 = wpa[32 + lane];
    uint4 wb0 = wpb[lane];
    uint4 wb1 = wpb[32 + lane];

    const float* srd = (MODE == 2) ? s0RD(tt) : (const float*)0;
    const float* swr = s0WR(tt);

    if (K2P == 256) {
        float4 xv[8];
#pragma unroll
        for (int it = 0; it < 8; it++) {
            int v = it * 128 + tid;
            int b = v >> 6, i4 = (v & 63) << 2;
            int seg = i4 >> 6, off = i4 & 63;
            const float* p;
            if      (seg == 0) p = swr      + node * 1024 + b * 64 + off;
            else if (seg == 1) p = g_ZS1    + node * 1024 + b * 64 + off;
            else if (seg == 2) p = g_SY     + (size_t)node * 2048 + b * 64 + off;
            else               p = g_SZS1   + node * 1024 + b * 64 + off;
            xv[it] = *(const float4*)p;
        }
#pragma unroll
        for (int it = 0; it < 8; it++) {
            int v = it * 128 + tid;
            int b = v >> 6, i4 = (v & 63) << 2;
            float4 x = xv[it];
            uint32_t hi0 = bsplit_hi(x.x, x.y), hi1 = bsplit_hi(x.z, x.w);
            uint32_t lo0 = bsplit_lo(x.x, x.y), lo1 = bsplit_lo(x.z, x.w);
            uint32_t boff = (uint32_t)(b * STRB) + swz16(i4 >> 3, b) + (uint32_t)((i4 & 7) * 2);
            asm volatile("st.shared.v2.b32 [%0], {%1,%2};" :: "r"(sXhi + boff), "r"(hi0), "r"(hi1));
            asm volatile("st.shared.v2.b32 [%0], {%1,%2};" :: "r"(sXlo + boff), "r"(lo0), "r"(lo1));
        }
    } else {
        float vals[18];
#pragma unroll
        for (int it = 0; it < 18; it++) {
            int idx = it * 128 + tid;
            int b = idx / 144, i = idx % 144;
            float v = 0.f;
            if (i == 0)       v = src[(b * TT + tt) * NN + node];
            else if (i < 65)  v = g_ZS0[node * 1024 + b * 64 + (i - 1)];
            else if (i == 65) v = g_SXall[(size_t)node * 192 + tt * 16 + b];
            else if (i < 130) v = g_SZS0[node * 1024 + b * 64 + (i - 66)];
            vals[it] = v;
        }
#pragma unroll
        for (int it = 0; it < 18; it++) {
            int idx = it * 128 + tid;
            int b = idx / 144, i = idx % 144;
            float v = vals[it];
            __nv_bfloat16 h = __float2bfloat16(v);
            __nv_bfloat16 l = __float2bfloat16(v - __bfloat162float(h));
            uint32_t boff = (uint32_t)(b * STRB) + swz16(i >> 3, b) + (uint32_t)((i & 7) * 2);
            asm volatile("st.shared.b16 [%0], %1;" :: "r"(sXhi + boff), "h"(*(unsigned short*)&h));
            asm volatile("st.shared.b16 [%0], %1;" :: "r"(sXlo + boff), "h"(*(unsigned short*)&l));
        }
    }
    __syncthreads();

    float accA[4] = {0.f, 0.f, 0.f, 0.f};
    float accB[4] = {0.f, 0.f, 0.f, 0.f};
    int l15 = lane & 15;
#pragma unroll
    for (int ks = 0; ks < KST; ks++) {
        uint4 wvA = (ks & 1) ? wa1 : wa0;
        uint4 wvB = (ks & 1) ? wb1 : wb0;
        if (ks + 2 < KST) {
            if (ks & 1) { wa1 = wpa[(ks + 2) * 32 + lane]; wb1 = wpb[(ks + 2) * 32 + lane]; }
            else        { wa0 = wpa[(ks + 2) * 32 + lane]; wb0 = wpb[(ks + 2) * 32 + lane]; }
        }
        int cA = ks * 2 + (lane >> 4);
        uint32_t offA = (uint32_t)(l15 * STRB) + swz16(cA, l15);
        uint32_t ahi[4], alo[4];
        ldsm4(ahi, sXhi + offA);
        ldsm4(alo, sXlo + offA);
        mma16816(accA, ahi, wvA.x, wvA.y);
        mma16816(accA, alo, wvA.x, wvA.y);
        mma16816(accA, ahi, wvA.z, wvA.w);
        mma16816(accB, ahi, wvB.x, wvB.y);
        mma16816(accB, alo, wvB.x, wvB.y);
        mma16816(accB, ahi, wvB.z, wvB.w);
    }

    const float* R   = (MODE == 2) ? g_r0 : g_r1;
    const float* stR = (MODE == 2) ? srd : g_state1;
    float* stW       = (MODE == 2) ? s0WR(tt) : g_state1;
    int jb = (MODE == 2) ? 0 : 1024;
    int qr = lane >> 2;

#pragma unroll
    for (int half = 0; half < 2; half++) {
        float* acc = half ? accB : accA;
        int o = (half ? (w + 4) : w) * 8 + (lane & 3) * 2;
        float b0 = bias[o], b1 = bias[o + 1];
        int base0 = node * 1024 + qr * 64 + o;
        int base1 = base0 + 512;
        int j0 = qr * 64 + o;
        int j1 = (qr + 8) * 64 + o;
        float h0 = tanhf(acc[0] + b0);
        float h1 = tanhf(acc[1] + b1);
        float h2 = tanhf(acc[2] + b0);
        float h3 = tanhf(acc[3] + b1);
        float r0v = R[base0],     r1v = R[base0 + 1];
        float r2v = R[base1],     r3v = R[base1 + 1];
        float n0 = r0v * stR[base0]     + (1.f - r0v) * h0;
        float n1 = r1v * stR[base0 + 1] + (1.f - r1v) * h1;
        float n2 = r2v * stR[base1]     + (1.f - r2v) * h2;
        float n3 = r3v * stR[base1 + 1] + (1.f - r3v) * h3;
        stW[base0] = n0; stW[base0 + 1] = n1;
        stW[base1] = n2; stW[base1 + 1] = n3;
        *(uint32_t*)&g_Ybhi[(size_t)node * 2048 + jb + j0] = bsplit_hi(n0, n1);
        *(uint32_t*)&g_Yblo[(size_t)node * 2048 + jb + j0] = bsplit_lo(n0, n1);
        *(uint32_t*)&g_Ybhi[(size_t)node * 2048 + jb + j1] = bsplit_hi(n2, n3);
        *(uint32_t*)&g_Yblo[(size_t)node * 2048 + jb + j1] = bsplit_lo(n2, n3);
    }
}

__global__ __launch_bounds__(256) void fused_gate(const float* __restrict__ src, int t1, int t0) {
    extern __shared__ __align__(128) char smem[];
    int role;
    if (gridDim.y == 2) role = (blockIdx.y == 0) ? 1 : 0;
    else                role = (t1 >= 0) ? 1 : 0;
    if (role) gate_body<256, 1>(src, t1, smem, blockIdx.x);
    else      gate_body<144, 0>(src, t0, smem, blockIdx.x);
}

__global__ __launch_bounds__(128) void fused_update(const float* __restrict__ src, int t1, int t0) {
    extern __shared__ __align__(128) char smem[];
    int role;
    if (gridDim.y == 2) role = (blockIdx.y == 0) ? 1 : 0;
    else                role = (t1 >= 0) ? 1 : 0;
    if (role) update_body<256, 3>(src, t1, smem, blockIdx.x);
    else      update_body<144, 2>(src, t0, smem, blockIdx.x);
}

// ---------------- output head ----------------
__global__ void out_kernel(const float* __restrict__ cw, const float* __restrict__ cb,
                           float* __restrict__ out) {
    int idx = blockIdx.x * 256 + threadIdx.x;
    if (idx >= NB * HR * NN) return;
    int n = idx & 2047;
    int h = (idx >> 11) % HR;
    int b = idx / (HR * NN);
    float a = cb[h];
#pragma unroll
    for (int c = 0; c < 64; c++)
        a = fmaf(g_state1[n * 1024 + b * 64 + c], cw[h * 64 + c], a);
    out[idx] = a;
}

// ---------------- launcher ----------------
extern "C" void kernel_launch(void* const* d_in, const int* in_sizes, int n_in,
                              void* d_out, int out_size) {
    const float* src = (const float*)d_in[0];
    const float* E   = (const float*)d_in[1];
    const float* Wg0 = (const float*)d_in[2];
    const float* bg0 = (const float*)d_in[3];
    const float* Wu0 = (const float*)d_in[4];
    const float* bu0 = (const float*)d_in[5];
    const float* Wg1 = (const float*)d_in[6];
    const float* bg1 = (const float*)d_in[7];
    const float* Wu1 = (const float*)d_in[8];
    const float* bu1 = (const float*)d_in[9];
    const float* cw  = (const float*)d_in[10];
    const float* cb  = (const float*)d_in[11];
    float* out = (float*)d_out;

    const int GEMM_SMEM = 2 * STAGE_BYTES;   // 128 KB
    const int HEAD_SMEM = 32 * 512;          // 16 KB (X only)
    cudaFuncSetAttribute(mma_gemm<0>,  cudaFuncAttributeMaxDynamicSharedMemorySize, GEMM_SMEM);
    cudaFuncSetAttribute(mma_gemm<2>,  cudaFuncAttributeMaxDynamicSharedMemorySize, GEMM_SMEM);
    cudaFuncSetAttribute(mma_gemm_sm,  cudaFuncAttributeMaxDynamicSharedMemorySize, GEMM_SMEM);
    cudaFuncSetAttribute(fused_gate,   cudaFuncAttributeMaxDynamicSharedMemorySize, HEAD_SMEM);
    cudaFuncSetAttribute(fused_update, cudaFuncAttributeMaxDynamicSharedMemorySize, HEAD_SMEM);

    // launches 1..4: #4 is a small THROWAWAY fused_gate for ncu profiling.
    build_S<<<NN, 256>>>(E);                                           // 1
    zero_all<<<(NN * 2048 + 255) / 256, 256>>>();                      // 2
    pack_x<<<(NN * 256 + 255) / 256, 256>>>(src);                      // 3
    fused_gate<<<dim3(256, 2), 256, HEAD_SMEM>>>(src, 0, 1);           // 4 <- PROFILED (throwaway)

    mma_gemm<2><<<dim3(2, 16), 256, GEMM_SMEM>>>(192);                 // S@X all steps
    transpose_src<<<3000, 256>>>(Wg0, Wu0, Wg1, Wu1);
    expand_frag<<<3072, 128>>>(E);
    expand_bias<<<NN, 384>>>(E, bg0, bu0, bg1, bu1);

    // prologue: layer0 @ t=0
    fused_gate  <<<dim3(2048, 1), 256, HEAD_SMEM>>>(src, -1, 0);
    mma_gemm_sm <<<dim3(8, 16, 1), 256, GEMM_SMEM>>>(0, 0);
    fused_update<<<dim3(2048, 1), 128, HEAD_SMEM>>>(src, -1, 0);
    mma_gemm<0> <<<dim3(16, 16), 256, GEMM_SMEM>>>(2048);

    // steady state: layer1(t) || layer0(t+1)
    for (int t = 0; t + 1 < TT; t++) {
        fused_gate  <<<dim3(2048, 2), 256, HEAD_SMEM>>>(src, t, t + 1);
        mma_gemm_sm <<<dim3(8, 16, 2), 256, GEMM_SMEM>>>(1, 0);
        fused_update<<<dim3(2048, 2), 128, HEAD_SMEM>>>(src, t, t + 1);
        mma_gemm<0> <<<dim3(16, 16), 256, GEMM_SMEM>>>(2048);
    }

    // epilogue: layer1 @ t=TT-1
    fused_gate  <<<dim3(2048, 1), 256, HEAD_SMEM>>>(src, TT - 1, -1);
    mma_gemm_sm <<<dim3(8, 16, 1), 256, GEMM_SMEM>>>(1, 1);
    fused_update<<<dim3(2048, 1), 128, HEAD_SMEM>>>(src, TT - 1, -1);

    out_kernel<<<(NB * HR * NN + 255) / 256, 256>>>(cw, cb, out);
}